// round 7
// baseline (speedup 1.0000x reference)
#include <cuda_runtime.h>
#include <cuda_bf16.h>
#include <cstdint>
#include <math.h>

// Problem constants
#define B_  2
#define S_  2048
#define F_  1024
#define H_  16
#define D_  64
#define M_  (B_ * S_)          // 4096 rows
#define BH_ (B_ * H_)          // 32
#define OUT_ELEMS (M_ * F_)    // 4194304
#define ATTN_ELEMS ((size_t)BH_ * S_ * S_)  // 134217728

// ---------------- device scratch (no allocations allowed) ----------------
__device__ float g_xn[OUT_ELEMS];
__device__ float g_tmp[OUT_ELEMS];
__device__ float g_rs[BH_ * S_];
__device__ float g_attn_fallback[ATTN_ELEMS];

__device__ __nv_bfloat16 g_xn_hi[OUT_ELEMS];
__device__ __nv_bfloat16 g_xn_lo[OUT_ELEMS];
__device__ __nv_bfloat16 g_qh[OUT_ELEMS];
__device__ __nv_bfloat16 g_ql[OUT_ELEMS];
__device__ __nv_bfloat16 g_kh[OUT_ELEMS];
__device__ __nv_bfloat16 g_kl[OUT_ELEMS];
__device__ __nv_bfloat16 g_vh[OUT_ELEMS];
__device__ __nv_bfloat16 g_vl[OUT_ELEMS];
__device__ __nv_bfloat16 g_ctx_hi[OUT_ELEMS];
__device__ __nv_bfloat16 g_ctx_lo[OUT_ELEMS];
__device__ __nv_bfloat16 g_WqT_hi[F_ * F_];
__device__ __nv_bfloat16 g_WqT_lo[F_ * F_];
__device__ __nv_bfloat16 g_WkT_hi[F_ * F_];
__device__ __nv_bfloat16 g_WkT_lo[F_ * F_];
__device__ __nv_bfloat16 g_WvT_hi[F_ * F_];
__device__ __nv_bfloat16 g_WvT_lo[F_ * F_];
__device__ __nv_bfloat16 g_WoT_hi[F_ * F_];
__device__ __nv_bfloat16 g_WoT_lo[F_ * F_];

// ---------------- helpers ----------------
__device__ __forceinline__ uint32_t smem_u32(const void* p) {
    uint32_t a;
    asm("{ .reg .u64 t; cvta.to.shared.u64 t, %1; cvt.u32.u64 %0, t; }"
        : "=r"(a) : "l"(p));
    return a;
}
__device__ __forceinline__ void ldsm4(uint32_t* r, uint32_t addr) {
    asm volatile("ldmatrix.sync.aligned.m8n8.x4.shared.b16 {%0,%1,%2,%3}, [%4];"
                 : "=r"(r[0]), "=r"(r[1]), "=r"(r[2]), "=r"(r[3]) : "r"(addr));
}
__device__ __forceinline__ void mma_bf16(float* c, const uint32_t* a,
                                         uint32_t b0, uint32_t b1) {
    asm volatile("mma.sync.aligned.m16n8k16.row.col.f32.bf16.bf16.f32 "
                 "{%0,%1,%2,%3}, {%4,%5,%6,%7}, {%8,%9}, {%0,%1,%2,%3};"
                 : "+f"(c[0]), "+f"(c[1]), "+f"(c[2]), "+f"(c[3])
                 : "r"(a[0]), "r"(a[1]), "r"(a[2]), "r"(a[3]), "r"(b0), "r"(b1));
}
__device__ __forceinline__ void split_f32(float a, __nv_bfloat16& hi, __nv_bfloat16& lo) {
    hi = __float2bfloat16(a);
    lo = __float2bfloat16(a - __bfloat162float(hi));
}
// exp(s*0.125) via FMA-pipe exp2 (no MUFU). s is the raw dot product.
#define EXP_C1 0.18033688011112042f   // 0.125 * log2(e)
__device__ __forceinline__ float fexp_dot(float dot) {
    float y = dot * EXP_C1;
    y = fminf(fmaxf(y, -126.f), 126.f);
    float t = y + 12582912.f;
    int e = (__float_as_int(t) - 0x4B400000) << 23;
    float f = y - (t - 12582912.f);
    float p = 0.00133335581f;
    p = fmaf(p, f, 0.00961812910f);
    p = fmaf(p, f, 0.0555041086f);
    p = fmaf(p, f, 0.240226507f);
    p = fmaf(p, f, 0.693147182f);
    p = fmaf(p, f, 1.0f);
    return __int_as_float(__float_as_int(p) + e);
}
__device__ __forceinline__ uint32_t pack_hi(float a, float b, float& ra, float& rb) {
    __nv_bfloat162 h = __floats2bfloat162_rn(a, b);
    ra = a - __bfloat162float(h.x);
    rb = b - __bfloat162float(h.y);
    return *(uint32_t*)&h;
}
__device__ __forceinline__ uint32_t pack2(float a, float b) {
    __nv_bfloat162 h = __floats2bfloat162_rn(a, b);
    return *(uint32_t*)&h;
}

// ---------------- LayerNorm (optional bf16 hi/lo split outputs) ----------
__global__ void ln_kernel(const float* __restrict__ x,
                          const float* __restrict__ gamma,
                          const float* __restrict__ beta,
                          float* __restrict__ out,
                          __nv_bfloat16* __restrict__ hi,
                          __nv_bfloat16* __restrict__ lo) {
    __shared__ float sred[8];
    int row = blockIdx.x;
    int t = threadIdx.x;
    const float4* xr = (const float4*)(x + (size_t)row * F_);
    float4 v = xr[t];

    float s = v.x + v.y + v.z + v.w;
    #pragma unroll
    for (int o = 16; o; o >>= 1) s += __shfl_xor_sync(0xffffffffu, s, o);
    if ((t & 31) == 0) sred[t >> 5] = s;
    __syncthreads();
    float tot = 0.f;
    #pragma unroll
    for (int i = 0; i < 8; i++) tot += sred[i];
    float mean = tot * (1.0f / F_);
    __syncthreads();

    float dx = v.x - mean, dy = v.y - mean, dz = v.z - mean, dw = v.w - mean;
    float ss = dx*dx + dy*dy + dz*dz + dw*dw;
    #pragma unroll
    for (int o = 16; o; o >>= 1) ss += __shfl_xor_sync(0xffffffffu, ss, o);
    if ((t & 31) == 0) sred[t >> 5] = ss;
    __syncthreads();
    float tot2 = 0.f;
    #pragma unroll
    for (int i = 0; i < 8; i++) tot2 += sred[i];
    float rstd = rsqrtf(tot2 * (1.0f / F_) + 1e-6f);

    float4 g4 = ((const float4*)gamma)[t];
    float4 b4 = ((const float4*)beta)[t];
    float4 o4;
    o4.x = dx * rstd * g4.x + b4.x;
    o4.y = dy * rstd * g4.y + b4.y;
    o4.z = dz * rstd * g4.z + b4.z;
    o4.w = dw * rstd * g4.w + b4.w;
    ((float4*)(out + (size_t)row * F_))[t] = o4;
    if (hi) {
        __nv_bfloat16 h0, l0, h1, l1, h2, l2, h3, l3;
        split_f32(o4.x, h0, l0); split_f32(o4.y, h1, l1);
        split_f32(o4.z, h2, l2); split_f32(o4.w, h3, l3);
        size_t base = (size_t)row * F_ + 4 * t;
        *(__nv_bfloat162*)&hi[base]     = __nv_bfloat162(h0, h1);
        *(__nv_bfloat162*)&hi[base + 2] = __nv_bfloat162(h2, h3);
        *(__nv_bfloat162*)&lo[base]     = __nv_bfloat162(l0, l1);
        *(__nv_bfloat162*)&lo[base + 2] = __nv_bfloat162(l2, l3);
    }
}

// ---------------- transpose + split: W[k][n] -> T[n][k] bf16 hi/lo -------
__global__ void transpose_split_kernel(const float* __restrict__ W,
                                       __nv_bfloat16* __restrict__ hiT,
                                       __nv_bfloat16* __restrict__ loT) {
    __shared__ float t[32][33];
    int bx = blockIdx.x * 32;  // n
    int by = blockIdx.y * 32;  // k
    int tx = threadIdx.x, ty = threadIdx.y;
    #pragma unroll
    for (int i = 0; i < 4; i++)
        t[ty + 8 * i][tx] = W[(size_t)(by + ty + 8 * i) * F_ + bx + tx];
    __syncthreads();
    #pragma unroll
    for (int i = 0; i < 4; i++) {
        float v = t[tx][ty + 8 * i];
        __nv_bfloat16 h, l;
        split_f32(v, h, l);
        size_t o = (size_t)(bx + ty + 8 * i) * F_ + by + tx;
        hiT[o] = h;
        loT[o] = l;
    }
}

// ---------------- mma.sync GEMM (fp32 out and/or bf16-split out) ---------
#define GBK 32
#define KPAD 40

__global__ __launch_bounds__(256, 2)
void gemm_mma(const __nv_bfloat16* __restrict__ Ahi,
              const __nv_bfloat16* __restrict__ Alo,
              const __nv_bfloat16* __restrict__ BhiT,
              const __nv_bfloat16* __restrict__ BloT,
              const float* __restrict__ bias,
              const float* __restrict__ pos,   // null or [S_, D_]
              const float* __restrict__ res,   // null or [M_, F_]
              float* __restrict__ C,           // nullable fp32 out
              __nv_bfloat16* __restrict__ Chi, // nullable bf16-split out
              __nv_bfloat16* __restrict__ Clo) {
    __shared__ __nv_bfloat16 sAhi[128][KPAD];
    __shared__ __nv_bfloat16 sAlo[128][KPAD];
    __shared__ __nv_bfloat16 sBhi[128][KPAD];
    __shared__ __nv_bfloat16 sBlo[128][KPAD];

    int tid = threadIdx.x;
    int warp = tid >> 5, lane = tid & 31;
    int m0 = blockIdx.y * 128;
    int n0 = blockIdx.x * 128;
    int mw = (warp >> 1) * 32;
    int nw = (warp & 1) * 64;

    float acc[2][8][4];
    #pragma unroll
    for (int i = 0; i < 2; i++)
        #pragma unroll
        for (int j = 0; j < 8; j++)
            #pragma unroll
            for (int c = 0; c < 4; c++) acc[i][j][c] = 0.f;

    int a_row = (lane & 15);
    int a_col = (lane & 16) >> 1;
    int b_row = (lane & 7) + ((lane & 16) >> 1);
    int b_col = (lane & 8);

    for (int kc = 0; kc < F_; kc += GBK) {
        #pragma unroll
        for (int i = 0; i < 2; i++) {
            int f = tid + 256 * i;
            int r = f >> 2, g = f & 3;
            size_t asrc = (size_t)(m0 + r) * F_ + kc + g * 8;
            size_t bsrc = (size_t)(n0 + r) * F_ + kc + g * 8;
            *(uint4*)&sAhi[r][g * 8] = *(const uint4*)(Ahi + asrc);
            *(uint4*)&sAlo[r][g * 8] = *(const uint4*)(Alo + asrc);
            *(uint4*)&sBhi[r][g * 8] = *(const uint4*)(BhiT + bsrc);
            *(uint4*)&sBlo[r][g * 8] = *(const uint4*)(BloT + bsrc);
        }
        __syncthreads();

        #pragma unroll
        for (int ks = 0; ks < 2; ks++) {
            int k0 = ks * 16;
            uint32_t ah[2][4], al[2][4];
            #pragma unroll
            for (int mi = 0; mi < 2; mi++) {
                ldsm4(ah[mi], smem_u32(&sAhi[mw + 16 * mi + a_row][k0 + a_col]));
                ldsm4(al[mi], smem_u32(&sAlo[mw + 16 * mi + a_row][k0 + a_col]));
            }
            #pragma unroll
            for (int ni = 0; ni < 4; ni++) {
                uint32_t bh[4], bl[4];
                ldsm4(bh, smem_u32(&sBhi[nw + 16 * ni + b_row][k0 + b_col]));
                ldsm4(bl, smem_u32(&sBlo[nw + 16 * ni + b_row][k0 + b_col]));
                #pragma unroll
                for (int mi = 0; mi < 2; mi++) {
                    mma_bf16(acc[mi][2 * ni + 0], ah[mi], bh[0], bh[1]);
                    mma_bf16(acc[mi][2 * ni + 0], al[mi], bh[0], bh[1]);
                    mma_bf16(acc[mi][2 * ni + 0], ah[mi], bl[0], bl[1]);
                    mma_bf16(acc[mi][2 * ni + 1], ah[mi], bh[2], bh[3]);
                    mma_bf16(acc[mi][2 * ni + 1], al[mi], bh[2], bh[3]);
                    mma_bf16(acc[mi][2 * ni + 1], ah[mi], bl[2], bl[3]);
                }
            }
        }
        __syncthreads();
    }

    int gid = lane >> 2, tig = lane & 3;
    #pragma unroll
    for (int mi = 0; mi < 2; mi++) {
        #pragma unroll
        for (int nj = 0; nj < 8; nj++) {
            int row = m0 + mw + 16 * mi + gid;
            int col = n0 + nw + 8 * nj + 2 * tig;
            #pragma unroll
            for (int half = 0; half < 2; half++) {
                int r = row + half * 8;
                int s = r & (S_ - 1);
                float v0 = acc[mi][nj][half * 2 + 0] + bias[col];
                float v1 = acc[mi][nj][half * 2 + 1] + bias[col + 1];
                if (pos) {
                    v0 += pos[(size_t)s * D_ + (col & (D_ - 1))];
                    v1 += pos[(size_t)s * D_ + ((col + 1) & (D_ - 1))];
                }
                if (res) {
                    v0 += res[(size_t)r * F_ + col];
                    v1 += res[(size_t)r * F_ + col + 1];
                }
                if (C)
                    *(float2*)&C[(size_t)r * F_ + col] = make_float2(v0, v1);
                if (Chi) {
                    __nv_bfloat16 h0, l0, h1, l1;
                    split_f32(v0, h0, l0); split_f32(v1, h1, l1);
                    *(__nv_bfloat162*)&Chi[(size_t)r * F_ + col] = __nv_bfloat162(h0, h1);
                    *(__nv_bfloat162*)&Clo[(size_t)r * F_ + col] = __nv_bfloat162(l0, l1);
                }
            }
        }
    }
}

// ---------------- Flash pass 1: rowsums + ctx (NO attn writes) -----------
// Block: 128 q-rows, key tiles of 64. 8 warps, each warp 16 q-rows x 64 keys.
#define FKP 72
#define FLASH_SMEM_BYTES ((2*128*FKP + 4*64*FKP) * 2)

__global__ __launch_bounds__(256, 2)
void flash_mma(const __nv_bfloat16* __restrict__ qh_g, const __nv_bfloat16* __restrict__ ql_g,
               const __nv_bfloat16* __restrict__ kh_g, const __nv_bfloat16* __restrict__ kl_g,
               const __nv_bfloat16* __restrict__ vh_g, const __nv_bfloat16* __restrict__ vl_g,
               __nv_bfloat16* __restrict__ ctxh, __nv_bfloat16* __restrict__ ctxl,
               float* __restrict__ rs_g) {
    extern __shared__ __nv_bfloat16 fsm[];
    __nv_bfloat16* sQh = fsm;                     // [128][FKP]
    __nv_bfloat16* sQl = fsm + 128 * FKP;
    __nv_bfloat16* sKh = fsm + 2 * 128 * FKP;     // [64][FKP]
    __nv_bfloat16* sKl = sKh + 64 * FKP;
    __nv_bfloat16* sVh = sKh + 2 * 64 * FKP;      // [64 d][FKP keys] (transposed)
    __nv_bfloat16* sVl = sVh + 64 * FKP;

    int tid = threadIdx.x;
    int warp = tid >> 5, lane = tid & 31;
    int gid = lane >> 2, tig = lane & 3;
    int bh = blockIdx.y;
    int b = bh >> 4, h = bh & 15;
    int q0 = blockIdx.x * 128;

    #pragma unroll
    for (int i = 0; i < 4; i++) {
        int f = tid + 256 * i;
        int r = f >> 3, g = f & 7;
        size_t src = (size_t)(b * S_ + q0 + r) * F_ + h * D_ + g * 8;
        *(uint4*)&sQh[r * FKP + g * 8] = *(const uint4*)(qh_g + src);
        *(uint4*)&sQl[r * FKP + g * 8] = *(const uint4*)(ql_g + src);
    }
    __syncthreads();

    int a_row = lane & 15, a_col = (lane & 16) >> 1;
    int b_row = (lane & 7) + ((lane & 16) >> 1), b_col = lane & 8;
    uint32_t qfh[4][4], qfl[4][4];
    #pragma unroll
    for (int ks = 0; ks < 4; ks++) {
        ldsm4(qfh[ks], smem_u32(&sQh[(16 * warp + a_row) * FKP + 16 * ks + a_col]));
        ldsm4(qfl[ks], smem_u32(&sQl[(16 * warp + a_row) * FKP + 16 * ks + a_col]));
    }

    float O[8][4];
    #pragma unroll
    for (int i = 0; i < 8; i++)
        #pragma unroll
        for (int c = 0; c < 4; c++) O[i][c] = 0.f;
    float ls0 = 0.f, ls1 = 0.f;

    int r0 = q0 + 16 * warp + gid;
    int r1 = r0 + 8;

    for (int jb = 0; jb < q0 + 128; jb += 64) {
        __syncthreads();
        #pragma unroll
        for (int i = 0; i < 2; i++) {
            int f = tid + 256 * i;
            int r = f >> 3, g = f & 7;
            size_t src = (size_t)(b * S_ + jb + r) * F_ + h * D_ + g * 8;
            *(uint4*)&sKh[r * FKP + g * 8] = *(const uint4*)(kh_g + src);
            *(uint4*)&sKl[r * FKP + g * 8] = *(const uint4*)(kl_g + src);
        }
        #pragma unroll
        for (int i = 0; i < 8; i++) {
            int idx = tid + 256 * i;
            int key = idx >> 5, dp = idx & 31;
            size_t src = (size_t)(b * S_ + jb + key) * F_ + h * D_ + 2 * dp;
            __nv_bfloat162 vh2 = *(const __nv_bfloat162*)(vh_g + src);
            __nv_bfloat162 vl2 = *(const __nv_bfloat162*)(vl_g + src);
            sVh[(2 * dp + 0) * FKP + key] = vh2.x;
            sVh[(2 * dp + 1) * FKP + key] = vh2.y;
            sVl[(2 * dp + 0) * FKP + key] = vl2.x;
            sVl[(2 * dp + 1) * FKP + key] = vl2.y;
        }
        __syncthreads();

        float Sv[8][4];
        #pragma unroll
        for (int i = 0; i < 8; i++)
            Sv[i][0] = Sv[i][1] = Sv[i][2] = Sv[i][3] = 0.f;
        #pragma unroll
        for (int ks = 0; ks < 4; ks++) {
            #pragma unroll
            for (int ni = 0; ni < 4; ni++) {
                uint32_t kbh[4], kbl[4];
                ldsm4(kbh, smem_u32(&sKh[(16 * ni + b_row) * FKP + 16 * ks + b_col]));
                ldsm4(kbl, smem_u32(&sKl[(16 * ni + b_row) * FKP + 16 * ks + b_col]));
                mma_bf16(Sv[2 * ni + 0], qfh[ks], kbh[0], kbh[1]);
                mma_bf16(Sv[2 * ni + 0], qfl[ks], kbh[0], kbh[1]);
                mma_bf16(Sv[2 * ni + 0], qfh[ks], kbl[0], kbl[1]);
                mma_bf16(Sv[2 * ni + 1], qfh[ks], kbh[2], kbh[3]);
                mma_bf16(Sv[2 * ni + 1], qfl[ks], kbh[2], kbh[3]);
                mma_bf16(Sv[2 * ni + 1], qfh[ks], kbl[2], kbl[3]);
            }
        }

        bool needmask = (jb + 63 > q0 + 16 * warp);
        #pragma unroll
        for (int nt = 0; nt < 8; nt++) {
            int c0 = jb + 8 * nt + 2 * tig;
            float e0 = fexp_dot(Sv[nt][0]);
            float e1 = fexp_dot(Sv[nt][1]);
            float e2 = fexp_dot(Sv[nt][2]);
            float e3 = fexp_dot(Sv[nt][3]);
            if (needmask) {
                if (c0 + 0 > r0) e0 = 0.f;
                if (c0 + 1 > r0) e1 = 0.f;
                if (c0 + 0 > r1) e2 = 0.f;
                if (c0 + 1 > r1) e3 = 0.f;
            }
            Sv[nt][0] = e0; Sv[nt][1] = e1; Sv[nt][2] = e2; Sv[nt][3] = e3;
            ls0 += e0 + e1;
            ls1 += e2 + e3;
        }

        #pragma unroll
        for (int kt = 0; kt < 4; kt++) {
            uint32_t pah[4], pal[4];
            float lo0, lo1, lo2, lo3;
            pah[0] = pack_hi(Sv[2 * kt][0], Sv[2 * kt][1], lo0, lo1);
            pal[0] = pack2(lo0, lo1);
            pah[1] = pack_hi(Sv[2 * kt][2], Sv[2 * kt][3], lo0, lo1);
            pal[1] = pack2(lo0, lo1);
            pah[2] = pack_hi(Sv[2 * kt + 1][0], Sv[2 * kt + 1][1], lo2, lo3);
            pal[2] = pack2(lo2, lo3);
            pah[3] = pack_hi(Sv[2 * kt + 1][2], Sv[2 * kt + 1][3], lo2, lo3);
            pal[3] = pack2(lo2, lo3);
            #pragma unroll
            for (int ni = 0; ni < 4; ni++) {
                uint32_t vbh[4], vbl[4];
                ldsm4(vbh, smem_u32(&sVh[(16 * ni + b_row) * FKP + 16 * kt + b_col]));
                ldsm4(vbl, smem_u32(&sVl[(16 * ni + b_row) * FKP + 16 * kt + b_col]));
                mma_bf16(O[2 * ni + 0], pah, vbh[0], vbh[1]);
                mma_bf16(O[2 * ni + 0], pal, vbh[0], vbh[1]);
                mma_bf16(O[2 * ni + 0], pah, vbl[0], vbl[1]);
                mma_bf16(O[2 * ni + 1], pah, vbh[2], vbh[3]);
                mma_bf16(O[2 * ni + 1], pal, vbh[2], vbh[3]);
                mma_bf16(O[2 * ni + 1], pah, vbl[2], vbl[3]);
            }
        }
    }

    ls0 += __shfl_xor_sync(0xffffffffu, ls0, 1);
    ls0 += __shfl_xor_sync(0xffffffffu, ls0, 2);
    ls1 += __shfl_xor_sync(0xffffffffu, ls1, 1);
    ls1 += __shfl_xor_sync(0xffffffffu, ls1, 2);
    float rs0 = 1.0f / ls0, rs1 = 1.0f / ls1;
    if (tig == 0) {
        rs_g[bh * S_ + r0] = rs0;
        rs_g[bh * S_ + r1] = rs1;
    }

    #pragma unroll
    for (int nt = 0; nt < 8; nt++) {
        int col = h * D_ + 8 * nt + 2 * tig;
        float o0 = O[nt][0] * rs0, o1 = O[nt][1] * rs0;
        float o2 = O[nt][2] * rs1, o3 = O[nt][3] * rs1;
        __nv_bfloat16 h0, l0, h1, l1;
        split_f32(o0, h0, l0); split_f32(o1, h1, l1);
        *(__nv_bfloat162*)&ctxh[(size_t)(b * S_ + r0) * F_ + col] = __nv_bfloat162(h0, h1);
        *(__nv_bfloat162*)&ctxl[(size_t)(b * S_ + r0) * F_ + col] = __nv_bfloat162(l0, l1);
        split_f32(o2, h0, l0); split_f32(o3, h1, l1);
        *(__nv_bfloat162*)&ctxh[(size_t)(b * S_ + r1) * F_ + col] = __nv_bfloat162(h0, h1);
        *(__nv_bfloat162*)&ctxl[(size_t)(b * S_ + r1) * F_ + col] = __nv_bfloat162(l0, l1);
    }
}

// ---------------- Pass 2: recompute QK, write normalized attn once -------
// Same fragment layout as flash_mma (bitwise-identical logits), multiplies
// by 1/rowsum, streams the full row including zero tiles past the diagonal.
#define AW_SMEM_BYTES ((2*128*FKP + 2*64*FKP) * 2)

__global__ __launch_bounds__(256, 2)
void attn_write_mma(const __nv_bfloat16* __restrict__ qh_g, const __nv_bfloat16* __restrict__ ql_g,
                    const __nv_bfloat16* __restrict__ kh_g, const __nv_bfloat16* __restrict__ kl_g,
                    const float* __restrict__ rs_g,
                    float* __restrict__ attn) {
    extern __shared__ __nv_bfloat16 asm_[];
    __nv_bfloat16* sQh = asm_;
    __nv_bfloat16* sQl = asm_ + 128 * FKP;
    __nv_bfloat16* sKh = asm_ + 2 * 128 * FKP;
    __nv_bfloat16* sKl = sKh + 64 * FKP;

    int tid = threadIdx.x;
    int warp = tid >> 5, lane = tid & 31;
    int gid = lane >> 2, tig = lane & 3;
    int bh = blockIdx.y;
    int b = bh >> 4, h = bh & 15;
    int q0 = blockIdx.x * 128;

    #pragma unroll
    for (int i = 0; i < 4; i++) {
        int f = tid + 256 * i;
        int r = f >> 3, g = f & 7;
        size_t src = (size_t)(b * S_ + q0 + r) * F_ + h * D_ + g * 8;
        *(uint4*)&sQh[r * FKP + g * 8] = *(const uint4*)(qh_g + src);
        *(uint4*)&sQl[r * FKP + g * 8] = *(const uint4*)(ql_g + src);
    }
    __syncthreads();

    int a_row = lane & 15, a_col = (lane & 16) >> 1;
    int b_row = (lane & 7) + ((lane & 16) >> 1), b_col = lane & 8;
    uint32_t qfh[4][4], qfl[4][4];
    #pragma unroll
    for (int ks = 0; ks < 4; ks++) {
        ldsm4(qfh[ks], smem_u32(&sQh[(16 * warp + a_row) * FKP + 16 * ks + a_col]));
        ldsm4(qfl[ks], smem_u32(&sQl[(16 * warp + a_row) * FKP + 16 * ks + a_col]));
    }

    int r0 = q0 + 16 * warp + gid;
    int r1 = r0 + 8;
    float rs0 = __ldg(&rs_g[bh * S_ + r0]);
    float rs1 = __ldg(&rs_g[bh * S_ + r1]);
    size_t arow0 = (size_t)(bh * S_ + r0) * S_;
    size_t arow1 = (size_t)(bh * S_ + r1) * S_;

    for (int jb = 0; jb < S_; jb += 64) {
        if (jb < q0 + 128) {
            // causal region: recompute logits, normalize, write
            __syncthreads();
            #pragma unroll
            for (int i = 0; i < 2; i++) {
                int f = tid + 256 * i;
                int r = f >> 3, g = f & 7;
                size_t src = (size_t)(b * S_ + jb + r) * F_ + h * D_ + g * 8;
                *(uint4*)&sKh[r * FKP + g * 8] = *(const uint4*)(kh_g + src);
                *(uint4*)&sKl[r * FKP + g * 8] = *(const uint4*)(kl_g + src);
            }
            __syncthreads();

            float Sv[8][4];
            #pragma unroll
            for (int i = 0; i < 8; i++)
                Sv[i][0] = Sv[i][1] = Sv[i][2] = Sv[i][3] = 0.f;
            #pragma unroll
            for (int ks = 0; ks < 4; ks++) {
                #pragma unroll
                for (int ni = 0; ni < 4; ni++) {
                    uint32_t kbh[4], kbl[4];
                    ldsm4(kbh, smem_u32(&sKh[(16 * ni + b_row) * FKP + 16 * ks + b_col]));
                    ldsm4(kbl, smem_u32(&sKl[(16 * ni + b_row) * FKP + 16 * ks + b_col]));
                    mma_bf16(Sv[2 * ni + 0], qfh[ks], kbh[0], kbh[1]);
                    mma_bf16(Sv[2 * ni + 0], qfl[ks], kbh[0], kbh[1]);
                    mma_bf16(Sv[2 * ni + 0], qfh[ks], kbl[0], kbl[1]);
                    mma_bf16(Sv[2 * ni + 1], qfh[ks], kbh[2], kbh[3]);
                    mma_bf16(Sv[2 * ni + 1], qfl[ks], kbh[2], kbh[3]);
                    mma_bf16(Sv[2 * ni + 1], qfh[ks], kbl[2], kbl[3]);
                }
            }

            bool needmask = (jb + 63 > q0 + 16 * warp);
            #pragma unroll
            for (int nt = 0; nt < 8; nt++) {
                int c0 = jb + 8 * nt + 2 * tig;
                float e0 = fexp_dot(Sv[nt][0]) * rs0;
                float e1 = fexp_dot(Sv[nt][1]) * rs0;
                float e2 = fexp_dot(Sv[nt][2]) * rs1;
                float e3 = fexp_dot(Sv[nt][3]) * rs1;
                if (needmask) {
                    if (c0 + 0 > r0) e0 = 0.f;
                    if (c0 + 1 > r0) e1 = 0.f;
                    if (c0 + 0 > r1) e2 = 0.f;
                    if (c0 + 1 > r1) e3 = 0.f;
                }
                __stcs((float2*)&attn[arow0 + c0], make_float2(e0, e1));
                __stcs((float2*)&attn[arow1 + c0], make_float2(e2, e3));
            }
        } else {
            // fully-masked region: stream zeros
            #pragma unroll
            for (int nt = 0; nt < 8; nt++) {
                int c0 = jb + 8 * nt + 2 * tig;
                __stcs((float2*)&attn[arow0 + c0], make_float2(0.f, 0.f));
                __stcs((float2*)&attn[arow1 + c0], make_float2(0.f, 0.f));
            }
        }
    }
}

// ---------------- launch ----------------
extern "C" void kernel_launch(void* const* d_in, const int* in_sizes, int n_in,
                              void* d_out, int out_size) {
    const float* x      = (const float*)d_in[0];
    const float* Wq     = (const float*)d_in[1];
    const float* bq     = (const float*)d_in[2];
    const float* Wk     = (const float*)d_in[3];
    const float* bk     = (const float*)d_in[4];
    const float* Wv     = (const float*)d_in[5];
    const float* bv     = (const float*)d_in[6];
    const float* Wo     = (const float*)d_in[7];
    const float* bo     = (const float*)d_in[8];
    const float* gamma1 = (const float*)d_in[9];
    const float* beta1  = (const float*)d_in[10];
    const float* gamma2 = (const float*)d_in[11];
    const float* beta2  = (const float*)d_in[12];
    const float* pos    = (const float*)d_in[13];

    float* out = (float*)d_out;

    float *xn, *tmp, *rs, *attn_fb;
    cudaGetSymbolAddress((void**)&xn, g_xn);
    cudaGetSymbolAddress((void**)&tmp, g_tmp);
    cudaGetSymbolAddress((void**)&rs, g_rs);
    cudaGetSymbolAddress((void**)&attn_fb, g_attn_fallback);

    __nv_bfloat16 *xnh, *xnl, *qh, *ql, *kh, *kl, *vh, *vl, *ctxh, *ctxl;
    __nv_bfloat16 *wqh, *wql, *wkh, *wkl, *wvh, *wvl, *woh, *wol;
    cudaGetSymbolAddress((void**)&xnh, g_xn_hi);
    cudaGetSymbolAddress((void**)&xnl, g_xn_lo);
    cudaGetSymbolAddress((void**)&qh, g_qh);
    cudaGetSymbolAddress((void**)&ql, g_ql);
    cudaGetSymbolAddress((void**)&kh, g_kh);
    cudaGetSymbolAddress((void**)&kl, g_kl);
    cudaGetSymbolAddress((void**)&vh, g_vh);
    cudaGetSymbolAddress((void**)&vl, g_vl);
    cudaGetSymbolAddress((void**)&ctxh, g_ctx_hi);
    cudaGetSymbolAddress((void**)&ctxl, g_ctx_lo);
    cudaGetSymbolAddress((void**)&wqh, g_WqT_hi);
    cudaGetSymbolAddress((void**)&wql, g_WqT_lo);
    cudaGetSymbolAddress((void**)&wkh, g_WkT_hi);
    cudaGetSymbolAddress((void**)&wkl, g_WkT_lo);
    cudaGetSymbolAddress((void**)&wvh, g_WvT_hi);
    cudaGetSymbolAddress((void**)&wvl, g_WvT_lo);
    cudaGetSymbolAddress((void**)&woh, g_WoT_hi);
    cudaGetSymbolAddress((void**)&wol, g_WoT_lo);

    float* attn = (out_size > OUT_ELEMS) ? (out + OUT_ELEMS) : attn_fb;

    cudaFuncSetAttribute(flash_mma,
                         cudaFuncAttributeMaxDynamicSharedMemorySize,
                         FLASH_SMEM_BYTES);
    cudaFuncSetAttribute(attn_write_mma,
                         cudaFuncAttributeMaxDynamicSharedMemorySize,
                         AW_SMEM_BYTES);

    // 1) LN1 (with bf16 split outputs) + weight transpose-splits
    ln_kernel<<<M_, 256>>>(x, gamma1, beta1, xn, xnh, xnl);
    dim3 tb(32, 8), tg(F_ / 32, F_ / 32);
    transpose_split_kernel<<<tg, tb>>>(Wq, wqh, wql);
    transpose_split_kernel<<<tg, tb>>>(Wk, wkh, wkl);
    transpose_split_kernel<<<tg, tb>>>(Wv, wvh, wvl);
    transpose_split_kernel<<<tg, tb>>>(Wo, woh, wol);

    // 2) Q/K/V projections -> bf16 hi/lo outputs directly
    dim3 ggrid(F_ / 128, M_ / 128);
    gemm_mma<<<ggrid, 256>>>(xnh, xnl, wqh, wql, bq, nullptr, nullptr, nullptr, qh, ql);
    gemm_mma<<<ggrid, 256>>>(xnh, xnl, wkh, wkl, bk, pos,     nullptr, nullptr, kh, kl);
    gemm_mma<<<ggrid, 256>>>(xnh, xnl, wvh, wvl, bv, nullptr, nullptr, nullptr, vh, vl);

    // 3) flash pass 1: rowsums + ctx (no attn traffic)
    dim3 fgrid(S_ / 128, BH_);
    flash_mma<<<fgrid, 256, FLASH_SMEM_BYTES>>>(qh, ql, kh, kl, vh, vl,
                                                ctxh, ctxl, rs);

    // 4) pass 2: write normalized attn exactly once (incl. zero triangle)
    attn_write_mma<<<fgrid, 256, AW_SMEM_BYTES>>>(qh, ql, kh, kl, rs, attn);

    // 5) output projection + residual -> fp32 tmp
    gemm_mma<<<ggrid, 256>>>(ctxh, ctxl, woh, wol, bo, nullptr, xn, tmp, nullptr, nullptr);

    // 6) LN2
    ln_kernel<<<M_, 256>>>(tmp, gamma2, beta2, out, nullptr, nullptr);
}

// round 8
// speedup vs baseline: 1.4687x; 1.4687x over previous
#include <cuda_runtime.h>
#include <cuda_fp16.h>
#include <cstdint>
#include <math.h>

// Problem constants
#define B_  2
#define S_  2048
#define F_  1024
#define H_  16
#define D_  64
#define M_  (B_ * S_)          // 4096 rows
#define BH_ (B_ * H_)          // 32
#define OUT_ELEMS (M_ * F_)    // 4194304
#define ATTN_ELEMS ((size_t)BH_ * S_ * S_)  // 134217728

// ---------------- device scratch (no allocations allowed) ----------------
__device__ float g_xn[OUT_ELEMS];
__device__ float g_tmp[OUT_ELEMS];
__device__ float g_rs[BH_ * S_];
__device__ float g_attn_fallback[ATTN_ELEMS];

__device__ __half g_xn_hi[OUT_ELEMS];
__device__ __half g_xn_lo[OUT_ELEMS];
__device__ __half g_qh[OUT_ELEMS];
__device__ __half g_ql[OUT_ELEMS];
__device__ __half g_kh[OUT_ELEMS];     // single fp16 (B operand of QK)
__device__ __half g_vh[OUT_ELEMS];     // single fp16 (B operand of PV)
__device__ __half g_ctx_hi[OUT_ELEMS];
__device__ __half g_ctx_lo[OUT_ELEMS];
__device__ __half g_WqT[F_ * F_];
__device__ __half g_WkT[F_ * F_];
__device__ __half g_WvT[F_ * F_];
__device__ __half g_WoT[F_ * F_];

// ---------------- helpers ----------------
__device__ __forceinline__ uint32_t smem_u32(const void* p) {
    uint32_t a;
    asm("{ .reg .u64 t; cvta.to.shared.u64 t, %1; cvt.u32.u64 %0, t; }"
        : "=r"(a) : "l"(p));
    return a;
}
__device__ __forceinline__ void ldsm4(uint32_t* r, uint32_t addr) {
    asm volatile("ldmatrix.sync.aligned.m8n8.x4.shared.b16 {%0,%1,%2,%3}, [%4];"
                 : "=r"(r[0]), "=r"(r[1]), "=r"(r[2]), "=r"(r[3]) : "r"(addr));
}
__device__ __forceinline__ void mma_f16(float* c, const uint32_t* a,
                                        uint32_t b0, uint32_t b1) {
    asm volatile("mma.sync.aligned.m16n8k16.row.col.f32.f16.f16.f32 "
                 "{%0,%1,%2,%3}, {%4,%5,%6,%7}, {%8,%9}, {%0,%1,%2,%3};"
                 : "+f"(c[0]), "+f"(c[1]), "+f"(c[2]), "+f"(c[3])
                 : "r"(a[0]), "r"(a[1]), "r"(a[2]), "r"(a[3]), "r"(b0), "r"(b1));
}
__device__ __forceinline__ void split_f32h(float a, __half& hi, __half& lo) {
    hi = __float2half_rn(a);
    lo = __float2half_rn(a - __half2float(hi));
}
// exp(s*0.125) via FMA-pipe exp2 (no MUFU).
#define EXP_C1 0.18033688011112042f   // 0.125 * log2(e)
__device__ __forceinline__ float fexp_dot(float dot) {
    float y = dot * EXP_C1;
    y = fminf(fmaxf(y, -126.f), 126.f);
    float t = y + 12582912.f;
    int e = (__float_as_int(t) - 0x4B400000) << 23;
    float f = y - (t - 12582912.f);
    float p = 0.00133335581f;
    p = fmaf(p, f, 0.00961812910f);
    p = fmaf(p, f, 0.0555041086f);
    p = fmaf(p, f, 0.240226507f);
    p = fmaf(p, f, 0.693147182f);
    p = fmaf(p, f, 1.0f);
    return __int_as_float(__float_as_int(p) + e);
}
__device__ __forceinline__ uint32_t packh_hi(float a, float b, float& ra, float& rb) {
    __half2 h = __floats2half2_rn(a, b);
    ra = a - __low2float(h);
    rb = b - __high2float(h);
    return *(uint32_t*)&h;
}
__device__ __forceinline__ uint32_t packh(float a, float b) {
    __half2 h = __floats2half2_rn(a, b);
    return *(uint32_t*)&h;
}

// ---------------- LayerNorm (optional fp16 hi/lo split outputs) ----------
__global__ void ln_kernel(const float* __restrict__ x,
                          const float* __restrict__ gamma,
                          const float* __restrict__ beta,
                          float* __restrict__ out,
                          __half* __restrict__ hi,
                          __half* __restrict__ lo) {
    __shared__ float sred[8];
    int row = blockIdx.x;
    int t = threadIdx.x;
    const float4* xr = (const float4*)(x + (size_t)row * F_);
    float4 v = xr[t];

    float s = v.x + v.y + v.z + v.w;
    #pragma unroll
    for (int o = 16; o; o >>= 1) s += __shfl_xor_sync(0xffffffffu, s, o);
    if ((t & 31) == 0) sred[t >> 5] = s;
    __syncthreads();
    float tot = 0.f;
    #pragma unroll
    for (int i = 0; i < 8; i++) tot += sred[i];
    float mean = tot * (1.0f / F_);
    __syncthreads();

    float dx = v.x - mean, dy = v.y - mean, dz = v.z - mean, dw = v.w - mean;
    float ss = dx*dx + dy*dy + dz*dz + dw*dw;
    #pragma unroll
    for (int o = 16; o; o >>= 1) ss += __shfl_xor_sync(0xffffffffu, ss, o);
    if ((t & 31) == 0) sred[t >> 5] = ss;
    __syncthreads();
    float tot2 = 0.f;
    #pragma unroll
    for (int i = 0; i < 8; i++) tot2 += sred[i];
    float rstd = rsqrtf(tot2 * (1.0f / F_) + 1e-6f);

    float4 g4 = ((const float4*)gamma)[t];
    float4 b4 = ((const float4*)beta)[t];
    float4 o4;
    o4.x = dx * rstd * g4.x + b4.x;
    o4.y = dy * rstd * g4.y + b4.y;
    o4.z = dz * rstd * g4.z + b4.z;
    o4.w = dw * rstd * g4.w + b4.w;
    ((float4*)(out + (size_t)row * F_))[t] = o4;
    if (hi) {
        __half h0, l0, h1, l1, h2, l2, h3, l3;
        split_f32h(o4.x, h0, l0); split_f32h(o4.y, h1, l1);
        split_f32h(o4.z, h2, l2); split_f32h(o4.w, h3, l3);
        size_t base = (size_t)row * F_ + 4 * t;
        *(__half2*)&hi[base]     = __half2(h0, h1);
        *(__half2*)&hi[base + 2] = __half2(h2, h3);
        *(__half2*)&lo[base]     = __half2(l0, l1);
        *(__half2*)&lo[base + 2] = __half2(l2, l3);
    }
}

// ---------------- transpose: W[k][n] -> T[n][k] single fp16 --------------
__global__ void transpose_h_kernel(const float* __restrict__ W,
                                   __half* __restrict__ T) {
    __shared__ float t[32][33];
    int bx = blockIdx.x * 32;  // n
    int by = blockIdx.y * 32;  // k
    int tx = threadIdx.x, ty = threadIdx.y;
    #pragma unroll
    for (int i = 0; i < 4; i++)
        t[ty + 8 * i][tx] = W[(size_t)(by + ty + 8 * i) * F_ + bx + tx];
    __syncthreads();
    #pragma unroll
    for (int i = 0; i < 4; i++) {
        float v = t[tx][ty + 8 * i];
        T[(size_t)(bx + ty + 8 * i) * F_ + by + tx] = __float2half_rn(v);
    }
}

// ---------------- mma.sync GEMM: C = (Ah+Al) @ Bt (2-product) ------------
// outputs: fp32 C, or split Chi/Clo, or single-fp16 Cs (each nullable)
#define GBK 32
#define KPAD 40

__global__ __launch_bounds__(256, 2)
void gemm_mma(const __half* __restrict__ Ahi,
              const __half* __restrict__ Alo,
              const __half* __restrict__ Bt,
              const float* __restrict__ bias,
              const float* __restrict__ pos,   // null or [S_, D_]
              const float* __restrict__ res,   // null or [M_, F_]
              float* __restrict__ C,
              __half* __restrict__ Chi,
              __half* __restrict__ Clo,
              __half* __restrict__ Cs) {
    __shared__ __half sAh[128][KPAD];
    __shared__ __half sAl[128][KPAD];
    __shared__ __half sB[128][KPAD];

    int tid = threadIdx.x;
    int warp = tid >> 5, lane = tid & 31;
    int m0 = blockIdx.y * 128;
    int n0 = blockIdx.x * 128;
    int mw = (warp >> 1) * 32;
    int nw = (warp & 1) * 64;

    float acc[2][8][4];
    #pragma unroll
    for (int i = 0; i < 2; i++)
        #pragma unroll
        for (int j = 0; j < 8; j++)
            #pragma unroll
            for (int c = 0; c < 4; c++) acc[i][j][c] = 0.f;

    int a_row = (lane & 15);
    int a_col = (lane & 16) >> 1;
    int b_row = (lane & 7) + ((lane & 16) >> 1);
    int b_col = (lane & 8);

    for (int kc = 0; kc < F_; kc += GBK) {
        #pragma unroll
        for (int i = 0; i < 2; i++) {
            int f = tid + 256 * i;
            int r = f >> 2, g = f & 3;
            size_t asrc = (size_t)(m0 + r) * F_ + kc + g * 8;
            size_t bsrc = (size_t)(n0 + r) * F_ + kc + g * 8;
            *(uint4*)&sAh[r][g * 8] = *(const uint4*)(Ahi + asrc);
            *(uint4*)&sAl[r][g * 8] = *(const uint4*)(Alo + asrc);
            *(uint4*)&sB[r][g * 8]  = *(const uint4*)(Bt + bsrc);
        }
        __syncthreads();

        #pragma unroll
        for (int ks = 0; ks < 2; ks++) {
            int k0 = ks * 16;
            uint32_t ah[2][4], al[2][4];
            #pragma unroll
            for (int mi = 0; mi < 2; mi++) {
                ldsm4(ah[mi], smem_u32(&sAh[mw + 16 * mi + a_row][k0 + a_col]));
                ldsm4(al[mi], smem_u32(&sAl[mw + 16 * mi + a_row][k0 + a_col]));
            }
            #pragma unroll
            for (int ni = 0; ni < 4; ni++) {
                uint32_t bb[4];
                ldsm4(bb, smem_u32(&sB[nw + 16 * ni + b_row][k0 + b_col]));
                #pragma unroll
                for (int mi = 0; mi < 2; mi++) {
                    mma_f16(acc[mi][2 * ni + 0], ah[mi], bb[0], bb[1]);
                    mma_f16(acc[mi][2 * ni + 0], al[mi], bb[0], bb[1]);
                    mma_f16(acc[mi][2 * ni + 1], ah[mi], bb[2], bb[3]);
                    mma_f16(acc[mi][2 * ni + 1], al[mi], bb[2], bb[3]);
                }
            }
        }
        __syncthreads();
    }

    int gid = lane >> 2, tig = lane & 3;
    #pragma unroll
    for (int mi = 0; mi < 2; mi++) {
        #pragma unroll
        for (int nj = 0; nj < 8; nj++) {
            int row = m0 + mw + 16 * mi + gid;
            int col = n0 + nw + 8 * nj + 2 * tig;
            #pragma unroll
            for (int half_ = 0; half_ < 2; half_++) {
                int r = row + half_ * 8;
                int s = r & (S_ - 1);
                float v0 = acc[mi][nj][half_ * 2 + 0] + bias[col];
                float v1 = acc[mi][nj][half_ * 2 + 1] + bias[col + 1];
                if (pos) {
                    v0 += pos[(size_t)s * D_ + (col & (D_ - 1))];
                    v1 += pos[(size_t)s * D_ + ((col + 1) & (D_ - 1))];
                }
                if (res) {
                    v0 += res[(size_t)r * F_ + col];
                    v1 += res[(size_t)r * F_ + col + 1];
                }
                if (C)
                    *(float2*)&C[(size_t)r * F_ + col] = make_float2(v0, v1);
                if (Chi) {
                    __half h0, l0, h1, l1;
                    split_f32h(v0, h0, l0); split_f32h(v1, h1, l1);
                    *(__half2*)&Chi[(size_t)r * F_ + col] = __half2(h0, h1);
                    *(__half2*)&Clo[(size_t)r * F_ + col] = __half2(l0, l1);
                }
                if (Cs)
                    *(__half2*)&Cs[(size_t)r * F_ + col] = __floats2half2_rn(v0, v1);
            }
        }
    }
}

// ---------------- Flash pass 1: rowsums + ctx (NO attn writes) -----------
#define FKP 72
#define FLASH_SMEM_BYTES ((2*128*FKP + 2*64*FKP) * 2)

__global__ __launch_bounds__(256, 2)
void flash_mma(const __half* __restrict__ qh_g, const __half* __restrict__ ql_g,
               const __half* __restrict__ kh_g,
               const __half* __restrict__ vh_g,
               __half* __restrict__ ctxh, __half* __restrict__ ctxl,
               float* __restrict__ rs_g) {
    extern __shared__ __half fsm[];
    __half* sQh = fsm;                    // [128][FKP]
    __half* sQl = fsm + 128 * FKP;
    __half* sKh = fsm + 2 * 128 * FKP;    // [64][FKP]
    __half* sVh = sKh + 64 * FKP;         // [64 d][FKP keys] (transposed)

    int tid = threadIdx.x;
    int warp = tid >> 5, lane = tid & 31;
    int gid = lane >> 2, tig = lane & 3;
    int bh = blockIdx.y;
    int b = bh >> 4, h = bh & 15;
    int q0 = blockIdx.x * 128;

    #pragma unroll
    for (int i = 0; i < 4; i++) {
        int f = tid + 256 * i;
        int r = f >> 3, g = f & 7;
        size_t src = (size_t)(b * S_ + q0 + r) * F_ + h * D_ + g * 8;
        *(uint4*)&sQh[r * FKP + g * 8] = *(const uint4*)(qh_g + src);
        *(uint4*)&sQl[r * FKP + g * 8] = *(const uint4*)(ql_g + src);
    }
    __syncthreads();

    int a_row = lane & 15, a_col = (lane & 16) >> 1;
    int b_row = (lane & 7) + ((lane & 16) >> 1), b_col = lane & 8;
    uint32_t qfh[4][4], qfl[4][4];
    #pragma unroll
    for (int ks = 0; ks < 4; ks++) {
        ldsm4(qfh[ks], smem_u32(&sQh[(16 * warp + a_row) * FKP + 16 * ks + a_col]));
        ldsm4(qfl[ks], smem_u32(&sQl[(16 * warp + a_row) * FKP + 16 * ks + a_col]));
    }

    float O[8][4];
    #pragma unroll
    for (int i = 0; i < 8; i++)
        #pragma unroll
        for (int c = 0; c < 4; c++) O[i][c] = 0.f;
    float ls0 = 0.f, ls1 = 0.f;

    int r0 = q0 + 16 * warp + gid;
    int r1 = r0 + 8;

    for (int jb = 0; jb < q0 + 128; jb += 64) {
        __syncthreads();
        #pragma unroll
        for (int i = 0; i < 2; i++) {
            int f = tid + 256 * i;
            int r = f >> 3, g = f & 7;
            size_t src = (size_t)(b * S_ + jb + r) * F_ + h * D_ + g * 8;
            *(uint4*)&sKh[r * FKP + g * 8] = *(const uint4*)(kh_g + src);
        }
        #pragma unroll
        for (int i = 0; i < 8; i++) {
            int idx = tid + 256 * i;
            int key = idx >> 5, dp = idx & 31;
            size_t src = (size_t)(b * S_ + jb + key) * F_ + h * D_ + 2 * dp;
            __half2 v2 = *(const __half2*)(vh_g + src);
            sVh[(2 * dp + 0) * FKP + key] = __low2half(v2);
            sVh[(2 * dp + 1) * FKP + key] = __high2half(v2);
        }
        __syncthreads();

        float Sv[8][4];
        #pragma unroll
        for (int i = 0; i < 8; i++)
            Sv[i][0] = Sv[i][1] = Sv[i][2] = Sv[i][3] = 0.f;
        #pragma unroll
        for (int ks = 0; ks < 4; ks++) {
            #pragma unroll
            for (int ni = 0; ni < 4; ni++) {
                uint32_t kb[4];
                ldsm4(kb, smem_u32(&sKh[(16 * ni + b_row) * FKP + 16 * ks + b_col]));
                mma_f16(Sv[2 * ni + 0], qfh[ks], kb[0], kb[1]);
                mma_f16(Sv[2 * ni + 0], qfl[ks], kb[0], kb[1]);
                mma_f16(Sv[2 * ni + 1], qfh[ks], kb[2], kb[3]);
                mma_f16(Sv[2 * ni + 1], qfl[ks], kb[2], kb[3]);
            }
        }

        bool needmask = (jb + 63 > q0 + 16 * warp);
        #pragma unroll
        for (int nt = 0; nt < 8; nt++) {
            int c0 = jb + 8 * nt + 2 * tig;
            float e0 = fexp_dot(Sv[nt][0]);
            float e1 = fexp_dot(Sv[nt][1]);
            float e2 = fexp_dot(Sv[nt][2]);
            float e3 = fexp_dot(Sv[nt][3]);
            if (needmask) {
                if (c0 + 0 > r0) e0 = 0.f;
                if (c0 + 1 > r0) e1 = 0.f;
                if (c0 + 0 > r1) e2 = 0.f;
                if (c0 + 1 > r1) e3 = 0.f;
            }
            Sv[nt][0] = e0; Sv[nt][1] = e1; Sv[nt][2] = e2; Sv[nt][3] = e3;
            ls0 += e0 + e1;
            ls1 += e2 + e3;
        }

        #pragma unroll
        for (int kt = 0; kt < 4; kt++) {
            uint32_t pah[4], pal[4];
            float lo0, lo1;
            pah[0] = packh_hi(Sv[2 * kt][0], Sv[2 * kt][1], lo0, lo1);
            pal[0] = packh(lo0, lo1);
            pah[1] = packh_hi(Sv[2 * kt][2], Sv[2 * kt][3], lo0, lo1);
            pal[1] = packh(lo0, lo1);
            pah[2] = packh_hi(Sv[2 * kt + 1][0], Sv[2 * kt + 1][1], lo0, lo1);
            pal[2] = packh(lo0, lo1);
            pah[3] = packh_hi(Sv[2 * kt + 1][2], Sv[2 * kt + 1][3], lo0, lo1);
            pal[3] = packh(lo0, lo1);
            #pragma unroll
            for (int ni = 0; ni < 4; ni++) {
                uint32_t vb[4];
                ldsm4(vb, smem_u32(&sVh[(16 * ni + b_row) * FKP + 16 * kt + b_col]));
                mma_f16(O[2 * ni + 0], pah, vb[0], vb[1]);
                mma_f16(O[2 * ni + 0], pal, vb[0], vb[1]);
                mma_f16(O[2 * ni + 1], pah, vb[2], vb[3]);
                mma_f16(O[2 * ni + 1], pal, vb[2], vb[3]);
            }
        }
    }

    ls0 += __shfl_xor_sync(0xffffffffu, ls0, 1);
    ls0 += __shfl_xor_sync(0xffffffffu, ls0, 2);
    ls1 += __shfl_xor_sync(0xffffffffu, ls1, 1);
    ls1 += __shfl_xor_sync(0xffffffffu, ls1, 2);
    float rs0 = 1.0f / ls0, rs1 = 1.0f / ls1;
    if (tig == 0) {
        rs_g[bh * S_ + r0] = rs0;
        rs_g[bh * S_ + r1] = rs1;
    }

    #pragma unroll
    for (int nt = 0; nt < 8; nt++) {
        int col = h * D_ + 8 * nt + 2 * tig;
        float o0 = O[nt][0] * rs0, o1 = O[nt][1] * rs0;
        float o2 = O[nt][2] * rs1, o3 = O[nt][3] * rs1;
        __half h0, l0, h1, l1;
        split_f32h(o0, h0, l0); split_f32h(o1, h1, l1);
        *(__half2*)&ctxh[(size_t)(b * S_ + r0) * F_ + col] = __half2(h0, h1);
        *(__half2*)&ctxl[(size_t)(b * S_ + r0) * F_ + col] = __half2(l0, l1);
        split_f32h(o2, h0, l0); split_f32h(o3, h1, l1);
        *(__half2*)&ctxh[(size_t)(b * S_ + r1) * F_ + col] = __half2(h0, h1);
        *(__half2*)&ctxl[(size_t)(b * S_ + r1) * F_ + col] = __half2(l0, l1);
    }
}

// ---------------- Pass 2: recompute QK, write normalized attn once -------
#define AW_SMEM_BYTES ((2*128*FKP + 64*FKP) * 2)

__global__ __launch_bounds__(256, 2)
void attn_write_mma(const __half* __restrict__ qh_g, const __half* __restrict__ ql_g,
                    const __half* __restrict__ kh_g,
                    const float* __restrict__ rs_g,
                    float* __restrict__ attn) {
    extern __shared__ __half asm_[];
    __half* sQh = asm_;
    __half* sQl = asm_ + 128 * FKP;
    __half* sKh = asm_ + 2 * 128 * FKP;

    int tid = threadIdx.x;
    int warp = tid >> 5, lane = tid & 31;
    int gid = lane >> 2, tig = lane & 3;
    int bh = blockIdx.y;
    int b = bh >> 4, h = bh & 15;
    int q0 = blockIdx.x * 128;

    #pragma unroll
    for (int i = 0; i < 4; i++) {
        int f = tid + 256 * i;
        int r = f >> 3, g = f & 7;
        size_t src = (size_t)(b * S_ + q0 + r) * F_ + h * D_ + g * 8;
        *(uint4*)&sQh[r * FKP + g * 8] = *(const uint4*)(qh_g + src);
        *(uint4*)&sQl[r * FKP + g * 8] = *(const uint4*)(ql_g + src);
    }
    __syncthreads();

    int a_row = lane & 15, a_col = (lane & 16) >> 1;
    int b_row = (lane & 7) + ((lane & 16) >> 1), b_col = lane & 8;
    uint32_t qfh[4][4], qfl[4][4];
    #pragma unroll
    for (int ks = 0; ks < 4; ks++) {
        ldsm4(qfh[ks], smem_u32(&sQh[(16 * warp + a_row) * FKP + 16 * ks + a_col]));
        ldsm4(qfl[ks], smem_u32(&sQl[(16 * warp + a_row) * FKP + 16 * ks + a_col]));
    }

    int r0 = q0 + 16 * warp + gid;
    int r1 = r0 + 8;
    float rs0 = __ldg(&rs_g[bh * S_ + r0]);
    float rs1 = __ldg(&rs_g[bh * S_ + r1]);
    size_t arow0 = (size_t)(bh * S_ + r0) * S_;
    size_t arow1 = (size_t)(bh * S_ + r1) * S_;

    for (int jb = 0; jb < S_; jb += 64) {
        if (jb < q0 + 128) {
            __syncthreads();
            #pragma unroll
            for (int i = 0; i < 2; i++) {
                int f = tid + 256 * i;
                int r = f >> 3, g = f & 7;
                size_t src = (size_t)(b * S_ + jb + r) * F_ + h * D_ + g * 8;
                *(uint4*)&sKh[r * FKP + g * 8] = *(const uint4*)(kh_g + src);
            }
            __syncthreads();

            float Sv[8][4];
            #pragma unroll
            for (int i = 0; i < 8; i++)
                Sv[i][0] = Sv[i][1] = Sv[i][2] = Sv[i][3] = 0.f;
            #pragma unroll
            for (int ks = 0; ks < 4; ks++) {
                #pragma unroll
                for (int ni = 0; ni < 4; ni++) {
                    uint32_t kb[4];
                    ldsm4(kb, smem_u32(&sKh[(16 * ni + b_row) * FKP + 16 * ks + b_col]));
                    mma_f16(Sv[2 * ni + 0], qfh[ks], kb[0], kb[1]);
                    mma_f16(Sv[2 * ni + 0], qfl[ks], kb[0], kb[1]);
                    mma_f16(Sv[2 * ni + 1], qfh[ks], kb[2], kb[3]);
                    mma_f16(Sv[2 * ni + 1], qfl[ks], kb[2], kb[3]);
                }
            }

            bool needmask = (jb + 63 > q0 + 16 * warp);
            #pragma unroll
            for (int nt = 0; nt < 8; nt++) {
                int c0 = jb + 8 * nt + 2 * tig;
                float e0 = fexp_dot(Sv[nt][0]) * rs0;
                float e1 = fexp_dot(Sv[nt][1]) * rs0;
                float e2 = fexp_dot(Sv[nt][2]) * rs1;
                float e3 = fexp_dot(Sv[nt][3]) * rs1;
                if (needmask) {
                    if (c0 + 0 > r0) e0 = 0.f;
                    if (c0 + 1 > r0) e1 = 0.f;
                    if (c0 + 0 > r1) e2 = 0.f;
                    if (c0 + 1 > r1) e3 = 0.f;
                }
                __stcs((float2*)&attn[arow0 + c0], make_float2(e0, e1));
                __stcs((float2*)&attn[arow1 + c0], make_float2(e2, e3));
            }
        } else {
            #pragma unroll
            for (int nt = 0; nt < 8; nt++) {
                int c0 = jb + 8 * nt + 2 * tig;
                __stcs((float2*)&attn[arow0 + c0], make_float2(0.f, 0.f));
                __stcs((float2*)&attn[arow1 + c0], make_float2(0.f, 0.f));
            }
        }
    }
}

// ---------------- launch ----------------
extern "C" void kernel_launch(void* const* d_in, const int* in_sizes, int n_in,
                              void* d_out, int out_size) {
    const float* x      = (const float*)d_in[0];
    const float* Wq     = (const float*)d_in[1];
    const float* bq     = (const float*)d_in[2];
    const float* Wk     = (const float*)d_in[3];
    const float* bk     = (const float*)d_in[4];
    const float* Wv     = (const float*)d_in[5];
    const float* bv     = (const float*)d_in[6];
    const float* Wo     = (const float*)d_in[7];
    const float* bo     = (const float*)d_in[8];
    const float* gamma1 = (const float*)d_in[9];
    const float* beta1  = (const float*)d_in[10];
    const float* gamma2 = (const float*)d_in[11];
    const float* beta2  = (const float*)d_in[12];
    const float* pos    = (const float*)d_in[13];

    float* out = (float*)d_out;

    float *xn, *tmp, *rs, *attn_fb;
    cudaGetSymbolAddress((void**)&xn, g_xn);
    cudaGetSymbolAddress((void**)&tmp, g_tmp);
    cudaGetSymbolAddress((void**)&rs, g_rs);
    cudaGetSymbolAddress((void**)&attn_fb, g_attn_fallback);

    __half *xnh, *xnl, *qh, *ql, *kh, *vh, *ctxh, *ctxl;
    __half *wqt, *wkt, *wvt, *wot;
    cudaGetSymbolAddress((void**)&xnh, g_xn_hi);
    cudaGetSymbolAddress((void**)&xnl, g_xn_lo);
    cudaGetSymbolAddress((void**)&qh, g_qh);
    cudaGetSymbolAddress((void**)&ql, g_ql);
    cudaGetSymbolAddress((void**)&kh, g_kh);
    cudaGetSymbolAddress((void**)&vh, g_vh);
    cudaGetSymbolAddress((void**)&ctxh, g_ctx_hi);
    cudaGetSymbolAddress((void**)&ctxl, g_ctx_lo);
    cudaGetSymbolAddress((void**)&wqt, g_WqT);
    cudaGetSymbolAddress((void**)&wkt, g_WkT);
    cudaGetSymbolAddress((void**)&wvt, g_WvT);
    cudaGetSymbolAddress((void**)&wot, g_WoT);

    float* attn = (out_size > OUT_ELEMS) ? (out + OUT_ELEMS) : attn_fb;

    cudaFuncSetAttribute(flash_mma,
                         cudaFuncAttributeMaxDynamicSharedMemorySize,
                         FLASH_SMEM_BYTES);
    cudaFuncSetAttribute(attn_write_mma,
                         cudaFuncAttributeMaxDynamicSharedMemorySize,
                         AW_SMEM_BYTES);

    // 1) LN1 (with fp16 split outputs) + weight transposes (single fp16)
    ln_kernel<<<M_, 256>>>(x, gamma1, beta1, xn, xnh, xnl);
    dim3 tb(32, 8), tg(F_ / 32, F_ / 32);
    transpose_h_kernel<<<tg, tb>>>(Wq, wqt);
    transpose_h_kernel<<<tg, tb>>>(Wk, wkt);
    transpose_h_kernel<<<tg, tb>>>(Wv, wvt);
    transpose_h_kernel<<<tg, tb>>>(Wo, wot);

    // 2) Q/K/V projections (2-product fp16)
    dim3 ggrid(F_ / 128, M_ / 128);
    gemm_mma<<<ggrid, 256>>>(xnh, xnl, wqt, bq, nullptr, nullptr,
                             nullptr, qh, ql, nullptr);
    gemm_mma<<<ggrid, 256>>>(xnh, xnl, wkt, bk, pos, nullptr,
                             nullptr, nullptr, nullptr, kh);
    gemm_mma<<<ggrid, 256>>>(xnh, xnl, wvt, bv, nullptr, nullptr,
                             nullptr, nullptr, nullptr, vh);

    // 3) flash pass 1: rowsums + ctx
    dim3 fgrid(S_ / 128, BH_);
    flash_mma<<<fgrid, 256, FLASH_SMEM_BYTES>>>(qh, ql, kh, vh, ctxh, ctxl, rs);

    // 4) pass 2: write normalized attn exactly once
    attn_write_mma<<<fgrid, 256, AW_SMEM_BYTES>>>(qh, ql, kh, rs, attn);

    // 5) output projection + residual -> fp32 tmp
    gemm_mma<<<ggrid, 256>>>(ctxh, ctxl, wot, bo, nullptr, xn,
                             tmp, nullptr, nullptr, nullptr);

    // 6) LN2
    ln_kernel<<<M_, 256>>>(tmp, gamma2, beta2, out, nullptr, nullptr);
}

// round 12
// speedup vs baseline: 1.5133x; 1.0303x over previous
#include <cuda_runtime.h>
#include <cuda_fp16.h>
#include <cstdint>
#include <math.h>

// Problem constants
#define B_  2
#define S_  2048
#define F_  1024
#define H_  16
#define D_  64
#define M_  (B_ * S_)          // 4096 rows
#define BH_ (B_ * H_)          // 32
#define OUT_ELEMS (M_ * F_)    // 4194304
#define ATTN_ELEMS ((size_t)BH_ * S_ * S_)  // 134217728

// ---------------- device scratch (no allocations allowed) ----------------
__device__ float g_xn[OUT_ELEMS];
__device__ float g_tmp[OUT_ELEMS];
__device__ float g_rs[BH_ * S_];
__device__ float g_attn_fallback[ATTN_ELEMS];

__device__ __half g_xn_hi[OUT_ELEMS];
__device__ __half g_xn_lo[OUT_ELEMS];
__device__ __half g_qh[OUT_ELEMS];
__device__ __half g_ql[OUT_ELEMS];
__device__ __half g_kh[OUT_ELEMS];
__device__ __half g_vh[OUT_ELEMS];
__device__ __half g_ctx_hi[OUT_ELEMS];
__device__ __half g_ctx_lo[OUT_ELEMS];
__device__ __half g_WqT[F_ * F_];
__device__ __half g_WkT[F_ * F_];
__device__ __half g_WvT[F_ * F_];
__device__ __half g_WoT[F_ * F_];

// ---------------- helpers ----------------
__device__ __forceinline__ uint32_t smem_u32(const void* p) {
    uint32_t a;
    asm("{ .reg .u64 t; cvta.to.shared.u64 t, %1; cvt.u32.u64 %0, t; }"
        : "=r"(a) : "l"(p));
    return a;
}
__device__ __forceinline__ void ldsm4(uint32_t* r, uint32_t addr) {
    asm volatile("ldmatrix.sync.aligned.m8n8.x4.shared.b16 {%0,%1,%2,%3}, [%4];"
                 : "=r"(r[0]), "=r"(r[1]), "=r"(r[2]), "=r"(r[3]) : "r"(addr));
}
__device__ __forceinline__ void mma_f16(float* c, const uint32_t* a,
                                        uint32_t b0, uint32_t b1) {
    asm volatile("mma.sync.aligned.m16n8k16.row.col.f32.f16.f16.f32 "
                 "{%0,%1,%2,%3}, {%4,%5,%6,%7}, {%8,%9}, {%0,%1,%2,%3};"
                 : "+f"(c[0]), "+f"(c[1]), "+f"(c[2]), "+f"(c[3])
                 : "r"(a[0]), "r"(a[1]), "r"(a[2]), "r"(a[3]), "r"(b0), "r"(b1));
}
#define CP_ASYNC16(dst, src) \
    asm volatile("cp.async.cg.shared.global [%0], [%1], 16;" :: "r"(dst), "l"(src))
#define CP_COMMIT() asm volatile("cp.async.commit_group;")
#define CP_WAIT1() asm volatile("cp.async.wait_group 1;")
#define CP_WAIT0() asm volatile("cp.async.wait_group 0;")

__device__ __forceinline__ void split_f32h(float a, __half& hi, __half& lo) {
    hi = __float2half_rn(a);
    lo = __float2half_rn(a - __half2float(hi));
}
// exp(s*0.125) via FMA-pipe exp2 (no MUFU).
#define EXP_C1 0.18033688011112042f   // 0.125 * log2(e)
__device__ __forceinline__ float fexp_dot(float dot) {
    float y = dot * EXP_C1;
    y = fminf(fmaxf(y, -126.f), 126.f);
    float t = y + 12582912.f;
    int e = (__float_as_int(t) - 0x4B400000) << 23;
    float f = y - (t - 12582912.f);
    float p = 0.00133335581f;
    p = fmaf(p, f, 0.00961812910f);
    p = fmaf(p, f, 0.0555041086f);
    p = fmaf(p, f, 0.240226507f);
    p = fmaf(p, f, 0.693147182f);
    p = fmaf(p, f, 1.0f);
    return __int_as_float(__float_as_int(p) + e);
}
__device__ __forceinline__ uint32_t packh_hi(float a, float b, float& ra, float& rb) {
    __half2 h = __floats2half2_rn(a, b);
    ra = a - __low2float(h);
    rb = b - __high2float(h);
    return *(uint32_t*)&h;
}
__device__ __forceinline__ uint32_t packh(float a, float b) {
    __half2 h = __floats2half2_rn(a, b);
    return *(uint32_t*)&h;
}

// ---------------- LayerNorm (optional fp16 hi/lo split outputs) ----------
__global__ void ln_kernel(const float* __restrict__ x,
                          const float* __restrict__ gamma,
                          const float* __restrict__ beta,
                          float* __restrict__ out,
                          __half* __restrict__ hi,
                          __half* __restrict__ lo) {
    __shared__ float sred[8];
    int row = blockIdx.x;
    int t = threadIdx.x;
    const float4* xr = (const float4*)(x + (size_t)row * F_);
    float4 v = xr[t];

    float s = v.x + v.y + v.z + v.w;
    #pragma unroll
    for (int o = 16; o; o >>= 1) s += __shfl_xor_sync(0xffffffffu, s, o);
    if ((t & 31) == 0) sred[t >> 5] = s;
    __syncthreads();
    float tot = 0.f;
    #pragma unroll
    for (int i = 0; i < 8; i++) tot += sred[i];
    float mean = tot * (1.0f / F_);
    __syncthreads();

    float dx = v.x - mean, dy = v.y - mean, dz = v.z - mean, dw = v.w - mean;
    float ss = dx*dx + dy*dy + dz*dz + dw*dw;
    #pragma unroll
    for (int o = 16; o; o >>= 1) ss += __shfl_xor_sync(0xffffffffu, ss, o);
    if ((t & 31) == 0) sred[t >> 5] = ss;
    __syncthreads();
    float tot2 = 0.f;
    #pragma unroll
    for (int i = 0; i < 8; i++) tot2 += sred[i];
    float rstd = rsqrtf(tot2 * (1.0f / F_) + 1e-6f);

    float4 g4 = ((const float4*)gamma)[t];
    float4 b4 = ((const float4*)beta)[t];
    float4 o4;
    o4.x = dx * rstd * g4.x + b4.x;
    o4.y = dy * rstd * g4.y + b4.y;
    o4.z = dz * rstd * g4.z + b4.z;
    o4.w = dw * rstd * g4.w + b4.w;
    ((float4*)(out + (size_t)row * F_))[t] = o4;
    if (hi) {
        __half h0, l0, h1, l1, h2, l2, h3, l3;
        split_f32h(o4.x, h0, l0); split_f32h(o4.y, h1, l1);
        split_f32h(o4.z, h2, l2); split_f32h(o4.w, h3, l3);
        size_t base = (size_t)row * F_ + 4 * t;
        *(__half2*)&hi[base]     = __half2(h0, h1);
        *(__half2*)&hi[base + 2] = __half2(h2, h3);
        *(__half2*)&lo[base]     = __half2(l0, l1);
        *(__half2*)&lo[base + 2] = __half2(l2, l3);
    }
}

// ---------------- fused transpose: 4 weights -> fp16 T ------------------
__global__ void transpose_all_kernel(const float* __restrict__ W0, __half* __restrict__ T0,
                                     const float* __restrict__ W1, __half* __restrict__ T1,
                                     const float* __restrict__ W2, __half* __restrict__ T2,
                                     const float* __restrict__ W3, __half* __restrict__ T3) {
    const float* W = (blockIdx.z == 0) ? W0 : (blockIdx.z == 1) ? W1
                   : (blockIdx.z == 2) ? W2 : W3;
    __half* T = (blockIdx.z == 0) ? T0 : (blockIdx.z == 1) ? T1
              : (blockIdx.z == 2) ? T2 : T3;
    __shared__ float t[32][33];
    int bx = blockIdx.x * 32;  // n
    int by = blockIdx.y * 32;  // k
    int tx = threadIdx.x, ty = threadIdx.y;
    #pragma unroll
    for (int i = 0; i < 4; i++)
        t[ty + 8 * i][tx] = W[(size_t)(by + ty + 8 * i) * F_ + bx + tx];
    __syncthreads();
    #pragma unroll
    for (int i = 0; i < 4; i++) {
        float v = t[tx][ty + 8 * i];
        T[(size_t)(bx + ty + 8 * i) * F_ + by + tx] = __float2half_rn(v);
    }
}

// ---------------- GEMM core: cp.async 2-stage pipelined mma --------------
// stage layout (bytes): Ah @0, Al @10240, B @20480; stage stride 30720.
// K = F_ = 1024 -> 32 chunks of 32 (NKC). (R9/R10 bug: only 16 iterated.)
#define GBK32 32
#define NKC (F_ / GBK32)     // 32 chunks
#define G_ROWB 80            // 40 halfs per row
#define G_STAGE 30720
#define GEMM_SMEM_BYTES (2 * G_STAGE)

__device__ __forceinline__ void gemm_core(
        const __half* __restrict__ Ahi, const __half* __restrict__ Alo,
        const __half* __restrict__ Bt,
        const float* __restrict__ bias,
        const float* __restrict__ pos, const float* __restrict__ res,
        float* __restrict__ C, __half* __restrict__ Chi,
        __half* __restrict__ Clo, __half* __restrict__ Cs,
        char* smem, int m0, int n0) {
    uint32_t sb = smem_u32(smem);
    int tid = threadIdx.x;
    int warp = tid >> 5, lane = tid & 31;
    int mw = (warp >> 1) * 32;
    int nw = (warp & 1) * 64;

    float acc[2][8][4];
    #pragma unroll
    for (int i = 0; i < 2; i++)
        #pragma unroll
        for (int j = 0; j < 8; j++)
            #pragma unroll
            for (int c = 0; c < 4; c++) acc[i][j][c] = 0.f;

    int a_row = (lane & 15);
    int a_col = (lane & 16) >> 1;
    int b_row = (lane & 7) + ((lane & 16) >> 1);
    int b_col = (lane & 8);

    int ldr = tid >> 2, ldg = tid & 3;
    auto load_stage = [&](int st, int kc) {
        uint32_t base = sb + st * G_STAGE;
        #pragma unroll
        for (int i = 0; i < 2; i++) {
            int r = ldr + 64 * i;
            uint32_t off = r * G_ROWB + ldg * 16;
            const __half* a0 = Ahi + (size_t)(m0 + r) * F_ + kc + ldg * 8;
            const __half* a1 = Alo + (size_t)(m0 + r) * F_ + kc + ldg * 8;
            const __half* b0 = Bt  + (size_t)(n0 + r) * F_ + kc + ldg * 8;
            CP_ASYNC16(base + off, a0);
            CP_ASYNC16(base + 10240 + off, a1);
            CP_ASYNC16(base + 20480 + off, b0);
        }
    };

    load_stage(0, 0);
    CP_COMMIT();

    for (int i = 0; i < NKC; i++) {
        if (i < NKC - 1) {
            load_stage((i + 1) & 1, (i + 1) * GBK32);
            CP_COMMIT();
            CP_WAIT1();
        } else {
            CP_WAIT0();
        }
        __syncthreads();

        uint32_t stA  = sb + (i & 1) * G_STAGE;
        uint32_t stAl = stA + 10240;
        uint32_t stB  = stA + 20480;
        #pragma unroll
        for (int ks = 0; ks < 2; ks++) {
            int k0 = ks * 16;
            uint32_t ah[2][4], al[2][4];
            #pragma unroll
            for (int mi = 0; mi < 2; mi++) {
                uint32_t ao = (mw + 16 * mi + a_row) * G_ROWB + (k0 + a_col) * 2;
                ldsm4(ah[mi], stA + ao);
                ldsm4(al[mi], stAl + ao);
            }
            #pragma unroll
            for (int ni = 0; ni < 4; ni++) {
                uint32_t bb[4];
                ldsm4(bb, stB + (nw + 16 * ni + b_row) * G_ROWB + (k0 + b_col) * 2);
                #pragma unroll
                for (int mi = 0; mi < 2; mi++) {
                    mma_f16(acc[mi][2 * ni + 0], ah[mi], bb[0], bb[1]);
                    mma_f16(acc[mi][2 * ni + 0], al[mi], bb[0], bb[1]);
                    mma_f16(acc[mi][2 * ni + 1], ah[mi], bb[2], bb[3]);
                    mma_f16(acc[mi][2 * ni + 1], al[mi], bb[2], bb[3]);
                }
            }
        }
        __syncthreads();
    }

    int gid = lane >> 2, tig = lane & 3;
    #pragma unroll
    for (int mi = 0; mi < 2; mi++) {
        #pragma unroll
        for (int nj = 0; nj < 8; nj++) {
            int row = m0 + mw + 16 * mi + gid;
            int col = n0 + nw + 8 * nj + 2 * tig;
            #pragma unroll
            for (int half_ = 0; half_ < 2; half_++) {
                int r = row + half_ * 8;
                int s = r & (S_ - 1);
                float v0 = acc[mi][nj][half_ * 2 + 0] + bias[col];
                float v1 = acc[mi][nj][half_ * 2 + 1] + bias[col + 1];
                if (pos) {
                    v0 += pos[(size_t)s * D_ + (col & (D_ - 1))];
                    v1 += pos[(size_t)s * D_ + ((col + 1) & (D_ - 1))];
                }
                if (res) {
                    v0 += res[(size_t)r * F_ + col];
                    v1 += res[(size_t)r * F_ + col + 1];
                }
                if (C)
                    *(float2*)&C[(size_t)r * F_ + col] = make_float2(v0, v1);
                if (Chi) {
                    __half h0, l0, h1, l1;
                    split_f32h(v0, h0, l0); split_f32h(v1, h1, l1);
                    *(__half2*)&Chi[(size_t)r * F_ + col] = __half2(h0, h1);
                    *(__half2*)&Clo[(size_t)r * F_ + col] = __half2(l0, l1);
                }
                if (Cs)
                    *(__half2*)&Cs[(size_t)r * F_ + col] = __floats2half2_rn(v0, v1);
            }
        }
    }
}

// fused Q/K/V projection: blockIdx.z selects weight/bias/output
__global__ __launch_bounds__(256, 2)
void gemm_qkv(const __half* __restrict__ Ahi, const __half* __restrict__ Alo,
              const __half* __restrict__ Wq, const __half* __restrict__ Wk,
              const __half* __restrict__ Wv,
              const float* __restrict__ bq, const float* __restrict__ bk,
              const float* __restrict__ bv, const float* __restrict__ pos,
              __half* __restrict__ qh, __half* __restrict__ ql,
              __half* __restrict__ kh, __half* __restrict__ vh) {
    extern __shared__ char smem[];
    int z = blockIdx.z;
    const __half* Bt = (z == 0) ? Wq : (z == 1) ? Wk : Wv;
    const float* bias = (z == 0) ? bq : (z == 1) ? bk : bv;
    const float* pp = (z == 1) ? pos : nullptr;
    __half* chi = (z == 0) ? qh : nullptr;
    __half* clo = (z == 0) ? ql : nullptr;
    __half* cs  = (z == 1) ? kh : (z == 2) ? vh : nullptr;
    gemm_core(Ahi, Alo, Bt, bias, pp, nullptr, nullptr, chi, clo, cs,
              smem, blockIdx.y * 128, blockIdx.x * 128);
}

// single GEMM (output projection)
__global__ __launch_bounds__(256, 2)
void gemm_single(const __half* __restrict__ Ahi, const __half* __restrict__ Alo,
                 const __half* __restrict__ Bt, const float* __restrict__ bias,
                 const float* __restrict__ res, float* __restrict__ C) {
    extern __shared__ char smem[];
    gemm_core(Ahi, Alo, Bt, bias, nullptr, res, C, nullptr, nullptr, nullptr,
              smem, blockIdx.y * 128, blockIdx.x * 128);
}

// ---------------- Flash pass 1: rowsums + ctx (NO attn writes) -----------
// V stored transposed [d][key] in smem (scalar stores), PV B-frags via ldsm4.
#define FKP 72
#define FLASH_SMEM_BYTES ((2*128*FKP + 2*64*FKP) * 2)

__global__ __launch_bounds__(256, 2)
void flash_mma(const __half* __restrict__ qh_g, const __half* __restrict__ ql_g,
               const __half* __restrict__ kh_g,
               const __half* __restrict__ vh_g,
               __half* __restrict__ ctxh, __half* __restrict__ ctxl,
               float* __restrict__ rs_g) {
    extern __shared__ __half fsm[];
    __half* sQh = fsm;                    // [128][FKP]
    __half* sQl = fsm + 128 * FKP;
    __half* sKh = fsm + 2 * 128 * FKP;    // [64][FKP]  key rows
    __half* sVh = sKh + 64 * FKP;         // [64 d][FKP keys] (transposed)

    int tid = threadIdx.x;
    int warp = tid >> 5, lane = tid & 31;
    int gid = lane >> 2, tig = lane & 3;
    int bh = blockIdx.y;
    int b = bh >> 4, h = bh & 15;
    int q0 = blockIdx.x * 128;

    #pragma unroll
    for (int i = 0; i < 4; i++) {
        int f = tid + 256 * i;
        int r = f >> 3, g = f & 7;
        size_t src = (size_t)(b * S_ + q0 + r) * F_ + h * D_ + g * 8;
        *(uint4*)&sQh[r * FKP + g * 8] = *(const uint4*)(qh_g + src);
        *(uint4*)&sQl[r * FKP + g * 8] = *(const uint4*)(ql_g + src);
    }
    __syncthreads();

    int a_row = lane & 15, a_col = (lane & 16) >> 1;
    int b_row = (lane & 7) + ((lane & 16) >> 1), b_col = lane & 8;
    uint32_t qfh[4][4], qfl[4][4];
    #pragma unroll
    for (int ks = 0; ks < 4; ks++) {
        ldsm4(qfh[ks], smem_u32(&sQh[(16 * warp + a_row) * FKP + 16 * ks + a_col]));
        ldsm4(qfl[ks], smem_u32(&sQl[(16 * warp + a_row) * FKP + 16 * ks + a_col]));
    }

    float O[8][4];
    #pragma unroll
    for (int i = 0; i < 8; i++)
        #pragma unroll
        for (int c = 0; c < 4; c++) O[i][c] = 0.f;
    float ls0 = 0.f, ls1 = 0.f;

    int r0 = q0 + 16 * warp + gid;
    int r1 = r0 + 8;

    for (int jb = 0; jb < q0 + 128; jb += 64) {
        __syncthreads();
        #pragma unroll
        for (int i = 0; i < 2; i++) {
            int f = tid + 256 * i;
            int r = f >> 3, g = f & 7;
            size_t src = (size_t)(b * S_ + jb + r) * F_ + h * D_ + g * 8;
            *(uint4*)&sKh[r * FKP + g * 8] = *(const uint4*)(kh_g + src);
        }
        #pragma unroll
        for (int i = 0; i < 8; i++) {
            int idx = tid + 256 * i;
            int key = idx >> 5, dp = idx & 31;
            size_t src = (size_t)(b * S_ + jb + key) * F_ + h * D_ + 2 * dp;
            __half2 v2 = *(const __half2*)(vh_g + src);
            sVh[(2 * dp + 0) * FKP + key] = __low2half(v2);
            sVh[(2 * dp + 1) * FKP + key] = __high2half(v2);
        }
        __syncthreads();

        float Sv[8][4];
        #pragma unroll
        for (int i = 0; i < 8; i++)
            Sv[i][0] = Sv[i][1] = Sv[i][2] = Sv[i][3] = 0.f;
        #pragma unroll
        for (int ks = 0; ks < 4; ks++) {
            #pragma unroll
            for (int ni = 0; ni < 4; ni++) {
                uint32_t kb[4];
                ldsm4(kb, smem_u32(&sKh[(16 * ni + b_row) * FKP + 16 * ks + b_col]));
                mma_f16(Sv[2 * ni + 0], qfh[ks], kb[0], kb[1]);
                mma_f16(Sv[2 * ni + 0], qfl[ks], kb[0], kb[1]);
                mma_f16(Sv[2 * ni + 1], qfh[ks], kb[2], kb[3]);
                mma_f16(Sv[2 * ni + 1], qfl[ks], kb[2], kb[3]);
            }
        }

        bool needmask = (jb + 63 > q0 + 16 * warp);
        #pragma unroll
        for (int nt = 0; nt < 8; nt++) {
            int c0 = jb + 8 * nt + 2 * tig;
            float e0 = fexp_dot(Sv[nt][0]);
            float e1 = fexp_dot(Sv[nt][1]);
            float e2 = fexp_dot(Sv[nt][2]);
            float e3 = fexp_dot(Sv[nt][3]);
            if (needmask) {
                if (c0 + 0 > r0) e0 = 0.f;
                if (c0 + 1 > r0) e1 = 0.f;
                if (c0 + 0 > r1) e2 = 0.f;
                if (c0 + 1 > r1) e3 = 0.f;
            }
            Sv[nt][0] = e0; Sv[nt][1] = e1; Sv[nt][2] = e2; Sv[nt][3] = e3;
            ls0 += e0 + e1;
            ls1 += e2 + e3;
        }

        #pragma unroll
        for (int kt = 0; kt < 4; kt++) {
            uint32_t pah[4], pal[4];
            float lo0, lo1;
            pah[0] = packh_hi(Sv[2 * kt][0], Sv[2 * kt][1], lo0, lo1);
            pal[0] = packh(lo0, lo1);
            pah[1] = packh_hi(Sv[2 * kt][2], Sv[2 * kt][3], lo0, lo1);
            pal[1] = packh(lo0, lo1);
            pah[2] = packh_hi(Sv[2 * kt + 1][0], Sv[2 * kt + 1][1], lo0, lo1);
            pal[2] = packh(lo0, lo1);
            pah[3] = packh_hi(Sv[2 * kt + 1][2], Sv[2 * kt + 1][3], lo0, lo1);
            pal[3] = packh(lo0, lo1);
            #pragma unroll
            for (int ni = 0; ni < 4; ni++) {
                uint32_t vb[4];
                ldsm4(vb, smem_u32(&sVh[(16 * ni + b_row) * FKP + 16 * kt + b_col]));
                mma_f16(O[2 * ni + 0], pah, vb[0], vb[1]);
                mma_f16(O[2 * ni + 0], pal, vb[0], vb[1]);
                mma_f16(O[2 * ni + 1], pah, vb[2], vb[3]);
                mma_f16(O[2 * ni + 1], pal, vb[2], vb[3]);
            }
        }
    }

    ls0 += __shfl_xor_sync(0xffffffffu, ls0, 1);
    ls0 += __shfl_xor_sync(0xffffffffu, ls0, 2);
    ls1 += __shfl_xor_sync(0xffffffffu, ls1, 1);
    ls1 += __shfl_xor_sync(0xffffffffu, ls1, 2);
    float rs0 = 1.0f / ls0, rs1 = 1.0f / ls1;
    if (tig == 0) {
        rs_g[bh * S_ + r0] = rs0;
        rs_g[bh * S_ + r1] = rs1;
    }

    #pragma unroll
    for (int nt = 0; nt < 8; nt++) {
        int col = h * D_ + 8 * nt + 2 * tig;
        float o0 = O[nt][0] * rs0, o1 = O[nt][1] * rs0;
        float o2 = O[nt][2] * rs1, o3 = O[nt][3] * rs1;
        __half h0, l0, h1, l1;
        split_f32h(o0, h0, l0); split_f32h(o1, h1, l1);
        *(__half2*)&ctxh[(size_t)(b * S_ + r0) * F_ + col] = __half2(h0, h1);
        *(__half2*)&ctxl[(size_t)(b * S_ + r0) * F_ + col] = __half2(l0, l1);
        split_f32h(o2, h0, l0); split_f32h(o3, h1, l1);
        *(__half2*)&ctxh[(size_t)(b * S_ + r1) * F_ + col] = __half2(h0, h1);
        *(__half2*)&ctxl[(size_t)(b * S_ + r1) * F_ + col] = __half2(l0, l1);
    }
}

// ---------------- Pass 2: recompute QK, write normalized attn once -------
#define AW_SMEM_BYTES ((2*128*FKP + 64*FKP) * 2)

__global__ __launch_bounds__(256, 2)
void attn_write_mma(const __half* __restrict__ qh_g, const __half* __restrict__ ql_g,
                    const __half* __restrict__ kh_g,
                    const float* __restrict__ rs_g,
                    float* __restrict__ attn) {
    extern __shared__ __half asm_[];
    __half* sQh = asm_;
    __half* sQl = asm_ + 128 * FKP;
    __half* sKh = asm_ + 2 * 128 * FKP;

    int tid = threadIdx.x;
    int warp = tid >> 5, lane = tid & 31;
    int gid = lane >> 2, tig = lane & 3;
    int bh = blockIdx.y;
    int b = bh >> 4, h = bh & 15;
    int q0 = blockIdx.x * 128;

    #pragma unroll
    for (int i = 0; i < 4; i++) {
        int f = tid + 256 * i;
        int r = f >> 3, g = f & 7;
        size_t src = (size_t)(b * S_ + q0 + r) * F_ + h * D_ + g * 8;
        *(uint4*)&sQh[r * FKP + g * 8] = *(const uint4*)(qh_g + src);
        *(uint4*)&sQl[r * FKP + g * 8] = *(const uint4*)(ql_g + src);
    }
    __syncthreads();

    int a_row = lane & 15, a_col = (lane & 16) >> 1;
    int b_row = (lane & 7) + ((lane & 16) >> 1), b_col = lane & 8;
    uint32_t qfh[4][4], qfl[4][4];
    #pragma unroll
    for (int ks = 0; ks < 4; ks++) {
        ldsm4(qfh[ks], smem_u32(&sQh[(16 * warp + a_row) * FKP + 16 * ks + a_col]));
        ldsm4(qfl[ks], smem_u32(&sQl[(16 * warp + a_row) * FKP + 16 * ks + a_col]));
    }

    int r0 = q0 + 16 * warp + gid;
    int r1 = r0 + 8;
    float rs0 = __ldg(&rs_g[bh * S_ + r0]);
    float rs1 = __ldg(&rs_g[bh * S_ + r1]);
    size_t arow0 = (size_t)(bh * S_ + r0) * S_;
    size_t arow1 = (size_t)(bh * S_ + r1) * S_;

    for (int jb = 0; jb < S_; jb += 64) {
        if (jb < q0 + 128) {
            __syncthreads();
            #pragma unroll
            for (int i = 0; i < 2; i++) {
                int f = tid + 256 * i;
                int r = f >> 3, g = f & 7;
                size_t src = (size_t)(b * S_ + jb + r) * F_ + h * D_ + g * 8;
                *(uint4*)&sKh[r * FKP + g * 8] = *(const uint4*)(kh_g + src);
            }
            __syncthreads();

            float Sv[8][4];
            #pragma unroll
            for (int i = 0; i < 8; i++)
                Sv[i][0] = Sv[i][1] = Sv[i][2] = Sv[i][3] = 0.f;
            #pragma unroll
            for (int ks = 0; ks < 4; ks++) {
                #pragma unroll
                for (int ni = 0; ni < 4; ni++) {
                    uint32_t kb[4];
                    ldsm4(kb, smem_u32(&sKh[(16 * ni + b_row) * FKP + 16 * ks + b_col]));
                    mma_f16(Sv[2 * ni + 0], qfh[ks], kb[0], kb[1]);
                    mma_f16(Sv[2 * ni + 0], qfl[ks], kb[0], kb[1]);
                    mma_f16(Sv[2 * ni + 1], qfh[ks], kb[2], kb[3]);
                    mma_f16(Sv[2 * ni + 1], qfl[ks], kb[2], kb[3]);
                }
            }

            bool needmask = (jb + 63 > q0 + 16 * warp);
            #pragma unroll
            for (int nt = 0; nt < 8; nt++) {
                int c0 = jb + 8 * nt + 2 * tig;
                float e0 = fexp_dot(Sv[nt][0]) * rs0;
                float e1 = fexp_dot(Sv[nt][1]) * rs0;
                float e2 = fexp_dot(Sv[nt][2]) * rs1;
                float e3 = fexp_dot(Sv[nt][3]) * rs1;
                if (needmask) {
                    if (c0 + 0 > r0) e0 = 0.f;
                    if (c0 + 1 > r0) e1 = 0.f;
                    if (c0 + 0 > r1) e2 = 0.f;
                    if (c0 + 1 > r1) e3 = 0.f;
                }
                __stcs((float2*)&attn[arow0 + c0], make_float2(e0, e1));
                __stcs((float2*)&attn[arow1 + c0], make_float2(e2, e3));
            }
        } else {
            #pragma unroll
            for (int nt = 0; nt < 8; nt++) {
                int c0 = jb + 8 * nt + 2 * tig;
                __stcs((float2*)&attn[arow0 + c0], make_float2(0.f, 0.f));
                __stcs((float2*)&attn[arow1 + c0], make_float2(0.f, 0.f));
            }
        }
    }
}

// ---------------- launch ----------------
extern "C" void kernel_launch(void* const* d_in, const int* in_sizes, int n_in,
                              void* d_out, int out_size) {
    const float* x      = (const float*)d_in[0];
    const float* Wq     = (const float*)d_in[1];
    const float* bq     = (const float*)d_in[2];
    const float* Wk     = (const float*)d_in[3];
    const float* bk     = (const float*)d_in[4];
    const float* Wv     = (const float*)d_in[5];
    const float* bv     = (const float*)d_in[6];
    const float* Wo     = (const float*)d_in[7];
    const float* bo     = (const float*)d_in[8];
    const float* gamma1 = (const float*)d_in[9];
    const float* beta1  = (const float*)d_in[10];
    const float* gamma2 = (const float*)d_in[11];
    const float* beta2  = (const float*)d_in[12];
    const float* pos    = (const float*)d_in[13];

    float* out = (float*)d_out;

    float *xn, *tmp, *rs, *attn_fb;
    cudaGetSymbolAddress((void**)&xn, g_xn);
    cudaGetSymbolAddress((void**)&tmp, g_tmp);
    cudaGetSymbolAddress((void**)&rs, g_rs);
    cudaGetSymbolAddress((void**)&attn_fb, g_attn_fallback);

    __half *xnh, *xnl, *qh, *ql, *kh, *vh, *ctxh, *ctxl;
    __half *wqt, *wkt, *wvt, *wot;
    cudaGetSymbolAddress((void**)&xnh, g_xn_hi);
    cudaGetSymbolAddress((void**)&xnl, g_xn_lo);
    cudaGetSymbolAddress((void**)&qh, g_qh);
    cudaGetSymbolAddress((void**)&ql, g_ql);
    cudaGetSymbolAddress((void**)&kh, g_kh);
    cudaGetSymbolAddress((void**)&vh, g_vh);
    cudaGetSymbolAddress((void**)&ctxh, g_ctx_hi);
    cudaGetSymbolAddress((void**)&ctxl, g_ctx_lo);
    cudaGetSymbolAddress((void**)&wqt, g_WqT);
    cudaGetSymbolAddress((void**)&wkt, g_WkT);
    cudaGetSymbolAddress((void**)&wvt, g_WvT);
    cudaGetSymbolAddress((void**)&wot, g_WoT);

    float* attn = (out_size > OUT_ELEMS) ? (out + OUT_ELEMS) : attn_fb;

    cudaFuncSetAttribute(flash_mma, cudaFuncAttributeMaxDynamicSharedMemorySize,
                         FLASH_SMEM_BYTES);
    cudaFuncSetAttribute(attn_write_mma, cudaFuncAttributeMaxDynamicSharedMemorySize,
                         AW_SMEM_BYTES);
    cudaFuncSetAttribute(gemm_qkv, cudaFuncAttributeMaxDynamicSharedMemorySize,
                         GEMM_SMEM_BYTES);
    cudaFuncSetAttribute(gemm_single, cudaFuncAttributeMaxDynamicSharedMemorySize,
                         GEMM_SMEM_BYTES);

    // 1) weight transposes (fused) + LN1 with fp16 split outputs
    dim3 tb(32, 8), tg(F_ / 32, F_ / 32, 4);
    transpose_all_kernel<<<tg, tb>>>(Wq, wqt, Wk, wkt, Wv, wvt, Wo, wot);
    ln_kernel<<<M_, 256>>>(x, gamma1, beta1, xn, xnh, xnl);

    // 2) fused Q/K/V projections (cp.async pipelined)
    dim3 qkvgrid(F_ / 128, M_ / 128, 3);
    gemm_qkv<<<qkvgrid, 256, GEMM_SMEM_BYTES>>>(xnh, xnl, wqt, wkt, wvt,
                                                bq, bk, bv, pos,
                                                qh, ql, kh, vh);

    // 3) flash pass 1: rowsums + ctx
    dim3 fgrid(S_ / 128, BH_);
    flash_mma<<<fgrid, 256, FLASH_SMEM_BYTES>>>(qh, ql, kh, vh, ctxh, ctxl, rs);

    // 4) pass 2: write normalized attn exactly once
    attn_write_mma<<<fgrid, 256, AW_SMEM_BYTES>>>(qh, ql, kh, rs, attn);

    // 5) output projection + residual -> fp32 tmp
    dim3 ggrid(F_ / 128, M_ / 128);
    gemm_single<<<ggrid, 256, GEMM_SMEM_BYTES>>>(ctxh, ctxl, wot, bo, xn, tmp);

    // 6) LN2
    ln_kernel<<<M_, 256>>>(tmp, gamma2, beta2, out, nullptr, nullptr);
}

// round 13
// speedup vs baseline: 1.6254x; 1.0741x over previous
#include <cuda_runtime.h>
#include <cuda_fp16.h>
#include <cstdint>
#include <math.h>

// Problem constants
#define B_  2
#define S_  2048
#define F_  1024
#define H_  16
#define D_  64
#define M_  (B_ * S_)          // 4096 rows
#define BH_ (B_ * H_)          // 32
#define OUT_ELEMS (M_ * F_)    // 4194304
#define ATTN_ELEMS ((size_t)BH_ * S_ * S_)  // 134217728

// ---------------- device scratch (no allocations allowed) ----------------
__device__ float g_xn[OUT_ELEMS];
__device__ float g_tmp[OUT_ELEMS];
__device__ float g_rs[BH_ * S_];
__device__ float g_attn_fallback[ATTN_ELEMS];

__device__ __half g_xn_hi[OUT_ELEMS];
__device__ __half g_xn_lo[OUT_ELEMS];
__device__ __half g_qh[OUT_ELEMS];
__device__ __half g_ql[OUT_ELEMS];
__device__ __half g_kh[OUT_ELEMS];
__device__ __half g_vh[OUT_ELEMS];
__device__ __half g_ctx_hi[OUT_ELEMS];
__device__ __half g_ctx_lo[OUT_ELEMS];
__device__ __half g_WqT[F_ * F_];
__device__ __half g_WkT[F_ * F_];
__device__ __half g_WvT[F_ * F_];
__device__ __half g_WoT[F_ * F_];

// ---------------- helpers ----------------
__device__ __forceinline__ uint32_t smem_u32(const void* p) {
    uint32_t a;
    asm("{ .reg .u64 t; cvta.to.shared.u64 t, %1; cvt.u32.u64 %0, t; }"
        : "=r"(a) : "l"(p));
    return a;
}
__device__ __forceinline__ void ldsm4(uint32_t* r, uint32_t addr) {
    asm volatile("ldmatrix.sync.aligned.m8n8.x4.shared.b16 {%0,%1,%2,%3}, [%4];"
                 : "=r"(r[0]), "=r"(r[1]), "=r"(r[2]), "=r"(r[3]) : "r"(addr));
}
__device__ __forceinline__ void ldsm4t(uint32_t* r, uint32_t addr) {
    asm volatile("ldmatrix.sync.aligned.m8n8.x4.trans.shared.b16 {%0,%1,%2,%3}, [%4];"
                 : "=r"(r[0]), "=r"(r[1]), "=r"(r[2]), "=r"(r[3]) : "r"(addr));
}
__device__ __forceinline__ void mma_f16(float* c, const uint32_t* a,
                                        uint32_t b0, uint32_t b1) {
    asm volatile("mma.sync.aligned.m16n8k16.row.col.f32.f16.f16.f32 "
                 "{%0,%1,%2,%3}, {%4,%5,%6,%7}, {%8,%9}, {%0,%1,%2,%3};"
                 : "+f"(c[0]), "+f"(c[1]), "+f"(c[2]), "+f"(c[3])
                 : "r"(a[0]), "r"(a[1]), "r"(a[2]), "r"(a[3]), "r"(b0), "r"(b1));
}
#define CP_ASYNC16(dst, src) \
    asm volatile("cp.async.cg.shared.global [%0], [%1], 16;" :: "r"(dst), "l"(src))
#define CP_COMMIT() asm volatile("cp.async.commit_group;")
#define CP_WAIT1() asm volatile("cp.async.wait_group 1;")
#define CP_WAIT0() asm volatile("cp.async.wait_group 0;")

__device__ __forceinline__ void split_f32h(float a, __half& hi, __half& lo) {
    hi = __float2half_rn(a);
    lo = __float2half_rn(a - __half2float(hi));
}
// exp(s*0.125) via FMA-pipe exp2 (no MUFU).
#define EXP_C1 0.18033688011112042f   // 0.125 * log2(e)
__device__ __forceinline__ float fexp_dot(float dot) {
    float y = dot * EXP_C1;
    y = fminf(fmaxf(y, -126.f), 126.f);
    float t = y + 12582912.f;
    int e = (__float_as_int(t) - 0x4B400000) << 23;
    float f = y - (t - 12582912.f);
    float p = 0.00133335581f;
    p = fmaf(p, f, 0.00961812910f);
    p = fmaf(p, f, 0.0555041086f);
    p = fmaf(p, f, 0.240226507f);
    p = fmaf(p, f, 0.693147182f);
    p = fmaf(p, f, 1.0f);
    return __int_as_float(__float_as_int(p) + e);
}
__device__ __forceinline__ uint32_t packh_hi(float a, float b, float& ra, float& rb) {
    __half2 h = __floats2half2_rn(a, b);
    ra = a - __low2float(h);
    rb = b - __high2float(h);
    return *(uint32_t*)&h;
}
__device__ __forceinline__ uint32_t packh(float a, float b) {
    __half2 h = __floats2half2_rn(a, b);
    return *(uint32_t*)&h;
}

// ---------------- LayerNorm (optional fp16 hi/lo split outputs) ----------
__global__ void ln_kernel(const float* __restrict__ x,
                          const float* __restrict__ gamma,
                          const float* __restrict__ beta,
                          float* __restrict__ out,
                          __half* __restrict__ hi,
                          __half* __restrict__ lo) {
    __shared__ float sred[8];
    int row = blockIdx.x;
    int t = threadIdx.x;
    const float4* xr = (const float4*)(x + (size_t)row * F_);
    float4 v = xr[t];

    float s = v.x + v.y + v.z + v.w;
    #pragma unroll
    for (int o = 16; o; o >>= 1) s += __shfl_xor_sync(0xffffffffu, s, o);
    if ((t & 31) == 0) sred[t >> 5] = s;
    __syncthreads();
    float tot = 0.f;
    #pragma unroll
    for (int i = 0; i < 8; i++) tot += sred[i];
    float mean = tot * (1.0f / F_);
    __syncthreads();

    float dx = v.x - mean, dy = v.y - mean, dz = v.z - mean, dw = v.w - mean;
    float ss = dx*dx + dy*dy + dz*dz + dw*dw;
    #pragma unroll
    for (int o = 16; o; o >>= 1) ss += __shfl_xor_sync(0xffffffffu, ss, o);
    if ((t & 31) == 0) sred[t >> 5] = ss;
    __syncthreads();
    float tot2 = 0.f;
    #pragma unroll
    for (int i = 0; i < 8; i++) tot2 += sred[i];
    float rstd = rsqrtf(tot2 * (1.0f / F_) + 1e-6f);

    float4 g4 = ((const float4*)gamma)[t];
    float4 b4 = ((const float4*)beta)[t];
    float4 o4;
    o4.x = dx * rstd * g4.x + b4.x;
    o4.y = dy * rstd * g4.y + b4.y;
    o4.z = dz * rstd * g4.z + b4.z;
    o4.w = dw * rstd * g4.w + b4.w;
    ((float4*)(out + (size_t)row * F_))[t] = o4;
    if (hi) {
        __half h0, l0, h1, l1, h2, l2, h3, l3;
        split_f32h(o4.x, h0, l0); split_f32h(o4.y, h1, l1);
        split_f32h(o4.z, h2, l2); split_f32h(o4.w, h3, l3);
        size_t base = (size_t)row * F_ + 4 * t;
        *(__half2*)&hi[base]     = __half2(h0, h1);
        *(__half2*)&hi[base + 2] = __half2(h2, h3);
        *(__half2*)&lo[base]     = __half2(l0, l1);
        *(__half2*)&lo[base + 2] = __half2(l2, l3);
    }
}

// ---------------- fused transpose: 4 weights -> fp16 T ------------------
__global__ void transpose_all_kernel(const float* __restrict__ W0, __half* __restrict__ T0,
                                     const float* __restrict__ W1, __half* __restrict__ T1,
                                     const float* __restrict__ W2, __half* __restrict__ T2,
                                     const float* __restrict__ W3, __half* __restrict__ T3) {
    const float* W = (blockIdx.z == 0) ? W0 : (blockIdx.z == 1) ? W1
                   : (blockIdx.z == 2) ? W2 : W3;
    __half* T = (blockIdx.z == 0) ? T0 : (blockIdx.z == 1) ? T1
              : (blockIdx.z == 2) ? T2 : T3;
    __shared__ float t[32][33];
    int bx = blockIdx.x * 32;  // n
    int by = blockIdx.y * 32;  // k
    int tx = threadIdx.x, ty = threadIdx.y;
    #pragma unroll
    for (int i = 0; i < 4; i++)
        t[ty + 8 * i][tx] = W[(size_t)(by + ty + 8 * i) * F_ + bx + tx];
    __syncthreads();
    #pragma unroll
    for (int i = 0; i < 4; i++) {
        float v = t[tx][ty + 8 * i];
        T[(size_t)(bx + ty + 8 * i) * F_ + by + tx] = __float2half_rn(v);
    }
}

// ---------------- GEMM core: cp.async 2-stage pipelined mma --------------
// stage layout (bytes): Ah @0, Al @10240, B @20480; stage stride 30720.
#define GBK32 32
#define NKC (F_ / GBK32)     // 32 chunks
#define G_ROWB 80            // 40 halfs per row
#define G_STAGE 30720
#define GEMM_SMEM_BYTES (2 * G_STAGE)

__device__ __forceinline__ void gemm_core(
        const __half* __restrict__ Ahi, const __half* __restrict__ Alo,
        const __half* __restrict__ Bt,
        const float* __restrict__ bias,
        const float* __restrict__ pos, const float* __restrict__ res,
        float* __restrict__ C, __half* __restrict__ Chi,
        __half* __restrict__ Clo, __half* __restrict__ Cs,
        char* smem, int m0, int n0) {
    uint32_t sb = smem_u32(smem);
    int tid = threadIdx.x;
    int warp = tid >> 5, lane = tid & 31;
    int mw = (warp >> 1) * 32;
    int nw = (warp & 1) * 64;

    float acc[2][8][4];
    #pragma unroll
    for (int i = 0; i < 2; i++)
        #pragma unroll
        for (int j = 0; j < 8; j++)
            #pragma unroll
            for (int c = 0; c < 4; c++) acc[i][j][c] = 0.f;

    int a_row = (lane & 15);
    int a_col = (lane & 16) >> 1;
    int b_row = (lane & 7) + ((lane & 16) >> 1);
    int b_col = (lane & 8);

    int ldr = tid >> 2, ldg = tid & 3;
    auto load_stage = [&](int st, int kc) {
        uint32_t base = sb + st * G_STAGE;
        #pragma unroll
        for (int i = 0; i < 2; i++) {
            int r = ldr + 64 * i;
            uint32_t off = r * G_ROWB + ldg * 16;
            const __half* a0 = Ahi + (size_t)(m0 + r) * F_ + kc + ldg * 8;
            const __half* a1 = Alo + (size_t)(m0 + r) * F_ + kc + ldg * 8;
            const __half* b0 = Bt  + (size_t)(n0 + r) * F_ + kc + ldg * 8;
            CP_ASYNC16(base + off, a0);
            CP_ASYNC16(base + 10240 + off, a1);
            CP_ASYNC16(base + 20480 + off, b0);
        }
    };

    load_stage(0, 0);
    CP_COMMIT();

    for (int i = 0; i < NKC; i++) {
        if (i < NKC - 1) {
            load_stage((i + 1) & 1, (i + 1) * GBK32);
            CP_COMMIT();
            CP_WAIT1();
        } else {
            CP_WAIT0();
        }
        __syncthreads();

        uint32_t stA  = sb + (i & 1) * G_STAGE;
        uint32_t stAl = stA + 10240;
        uint32_t stB  = stA + 20480;
        #pragma unroll
        for (int ks = 0; ks < 2; ks++) {
            int k0 = ks * 16;
            uint32_t ah[2][4], al[2][4];
            #pragma unroll
            for (int mi = 0; mi < 2; mi++) {
                uint32_t ao = (mw + 16 * mi + a_row) * G_ROWB + (k0 + a_col) * 2;
                ldsm4(ah[mi], stA + ao);
                ldsm4(al[mi], stAl + ao);
            }
            #pragma unroll
            for (int ni = 0; ni < 4; ni++) {
                uint32_t bb[4];
                ldsm4(bb, stB + (nw + 16 * ni + b_row) * G_ROWB + (k0 + b_col) * 2);
                #pragma unroll
                for (int mi = 0; mi < 2; mi++) {
                    mma_f16(acc[mi][2 * ni + 0], ah[mi], bb[0], bb[1]);
                    mma_f16(acc[mi][2 * ni + 0], al[mi], bb[0], bb[1]);
                    mma_f16(acc[mi][2 * ni + 1], ah[mi], bb[2], bb[3]);
                    mma_f16(acc[mi][2 * ni + 1], al[mi], bb[2], bb[3]);
                }
            }
        }
        __syncthreads();
    }

    int gid = lane >> 2, tig = lane & 3;
    #pragma unroll
    for (int mi = 0; mi < 2; mi++) {
        #pragma unroll
        for (int nj = 0; nj < 8; nj++) {
            int row = m0 + mw + 16 * mi + gid;
            int col = n0 + nw + 8 * nj + 2 * tig;
            #pragma unroll
            for (int half_ = 0; half_ < 2; half_++) {
                int r = row + half_ * 8;
                int s = r & (S_ - 1);
                float v0 = acc[mi][nj][half_ * 2 + 0] + bias[col];
                float v1 = acc[mi][nj][half_ * 2 + 1] + bias[col + 1];
                if (pos) {
                    v0 += pos[(size_t)s * D_ + (col & (D_ - 1))];
                    v1 += pos[(size_t)s * D_ + ((col + 1) & (D_ - 1))];
                }
                if (res) {
                    v0 += res[(size_t)r * F_ + col];
                    v1 += res[(size_t)r * F_ + col + 1];
                }
                if (C)
                    *(float2*)&C[(size_t)r * F_ + col] = make_float2(v0, v1);
                if (Chi) {
                    __half h0, l0, h1, l1;
                    split_f32h(v0, h0, l0); split_f32h(v1, h1, l1);
                    *(__half2*)&Chi[(size_t)r * F_ + col] = __half2(h0, h1);
                    *(__half2*)&Clo[(size_t)r * F_ + col] = __half2(l0, l1);
                }
                if (Cs)
                    *(__half2*)&Cs[(size_t)r * F_ + col] = __floats2half2_rn(v0, v1);
            }
        }
    }
}

// fused Q/K/V projection: blockIdx.z selects weight/bias/output
__global__ __launch_bounds__(256, 2)
void gemm_qkv(const __half* __restrict__ Ahi, const __half* __restrict__ Alo,
              const __half* __restrict__ Wq, const __half* __restrict__ Wk,
              const __half* __restrict__ Wv,
              const float* __restrict__ bq, const float* __restrict__ bk,
              const float* __restrict__ bv, const float* __restrict__ pos,
              __half* __restrict__ qh, __half* __restrict__ ql,
              __half* __restrict__ kh, __half* __restrict__ vh) {
    extern __shared__ char smem[];
    int z = blockIdx.z;
    const __half* Bt = (z == 0) ? Wq : (z == 1) ? Wk : Wv;
    const float* bias = (z == 0) ? bq : (z == 1) ? bk : bv;
    const float* pp = (z == 1) ? pos : nullptr;
    __half* chi = (z == 0) ? qh : nullptr;
    __half* clo = (z == 0) ? ql : nullptr;
    __half* cs  = (z == 1) ? kh : (z == 2) ? vh : nullptr;
    gemm_core(Ahi, Alo, Bt, bias, pp, nullptr, nullptr, chi, clo, cs,
              smem, blockIdx.y * 128, blockIdx.x * 128);
}

// single GEMM (output projection)
__global__ __launch_bounds__(256, 2)
void gemm_single(const __half* __restrict__ Ahi, const __half* __restrict__ Alo,
                 const __half* __restrict__ Bt, const float* __restrict__ bias,
                 const float* __restrict__ res, float* __restrict__ C) {
    extern __shared__ char smem[];
    gemm_core(Ahi, Alo, Bt, bias, nullptr, res, C, nullptr, nullptr, nullptr,
              smem, blockIdx.y * 128, blockIdx.x * 128);
}

// ---------------- Flash pass 1: rowsums + ctx (NO attn writes) -----------
// K and V tiles double-buffered via cp.async (row-major [key][d]).
// PV B-fragments via ldmatrix.trans (equiv. to scalar-transpose path,
// established by identical rel_err of R9/R10).
#define FKP 72
#define KV_STAGE (2 * 64 * FKP)   // halfs per stage (K + V)
#define FLASH_SMEM_BYTES ((2*128*FKP + 2*KV_STAGE) * 2)

__global__ __launch_bounds__(256, 2)
void flash_mma(const __half* __restrict__ qh_g, const __half* __restrict__ ql_g,
               const __half* __restrict__ kh_g,
               const __half* __restrict__ vh_g,
               __half* __restrict__ ctxh, __half* __restrict__ ctxl,
               float* __restrict__ rs_g) {
    extern __shared__ __half fsm[];
    __half* sQh = fsm;                    // [128][FKP]
    __half* sQl = fsm + 128 * FKP;
    __half* sKV = fsm + 2 * 128 * FKP;    // stage st: K, then V (64 rows each)

    int tid = threadIdx.x;
    int warp = tid >> 5, lane = tid & 31;
    int gid = lane >> 2, tig = lane & 3;
    int bh = blockIdx.y;
    int b = bh >> 4, h = bh & 15;
    int q0 = blockIdx.x * 128;

    #pragma unroll
    for (int i = 0; i < 4; i++) {
        int f = tid + 256 * i;
        int r = f >> 3, g = f & 7;
        size_t src = (size_t)(b * S_ + q0 + r) * F_ + h * D_ + g * 8;
        *(uint4*)&sQh[r * FKP + g * 8] = *(const uint4*)(qh_g + src);
        *(uint4*)&sQl[r * FKP + g * 8] = *(const uint4*)(ql_g + src);
    }
    __syncthreads();

    int a_row = lane & 15, a_col = (lane & 16) >> 1;
    int b_row = (lane & 7) + ((lane & 16) >> 1), b_col = lane & 8;
    uint32_t qfh[4][4], qfl[4][4];
    #pragma unroll
    for (int ks = 0; ks < 4; ks++) {
        ldsm4(qfh[ks], smem_u32(&sQh[(16 * warp + a_row) * FKP + 16 * ks + a_col]));
        ldsm4(qfl[ks], smem_u32(&sQl[(16 * warp + a_row) * FKP + 16 * ks + a_col]));
    }

    uint32_t kvb = smem_u32(sKV);
    auto load_kv = [&](int st, int jb) {
        uint32_t base = kvb + st * (KV_STAGE * 2);
        #pragma unroll
        for (int i = 0; i < 2; i++) {
            int f = tid + 256 * i;
            int r = f >> 3, g = f & 7;
            size_t src = (size_t)(b * S_ + jb + r) * F_ + h * D_ + g * 8;
            uint32_t off = (r * FKP + g * 8) * 2;
            CP_ASYNC16(base + off, kh_g + src);
            CP_ASYNC16(base + 64 * FKP * 2 + off, vh_g + src);
        }
    };

    float O[8][4];
    #pragma unroll
    for (int i = 0; i < 8; i++)
        #pragma unroll
        for (int c = 0; c < 4; c++) O[i][c] = 0.f;
    float ls0 = 0.f, ls1 = 0.f;

    int r0 = q0 + 16 * warp + gid;
    int r1 = r0 + 8;
    int niter = (q0 + 128) / 64;

    load_kv(0, 0);
    CP_COMMIT();

    for (int it = 0; it < niter; it++) {
        int jb = it * 64;
        if (it < niter - 1) {
            load_kv((it + 1) & 1, jb + 64);
            CP_COMMIT();
            CP_WAIT1();
        } else {
            CP_WAIT0();
        }
        __syncthreads();

        const __half* sKh = sKV + (it & 1) * KV_STAGE;
        const __half* sVh = sKh + 64 * FKP;

        float Sv[8][4];
        #pragma unroll
        for (int i = 0; i < 8; i++)
            Sv[i][0] = Sv[i][1] = Sv[i][2] = Sv[i][3] = 0.f;
        #pragma unroll
        for (int ks = 0; ks < 4; ks++) {
            #pragma unroll
            for (int ni = 0; ni < 4; ni++) {
                uint32_t kb[4];
                ldsm4(kb, smem_u32(&sKh[(16 * ni + b_row) * FKP + 16 * ks + b_col]));
                mma_f16(Sv[2 * ni + 0], qfh[ks], kb[0], kb[1]);
                mma_f16(Sv[2 * ni + 0], qfl[ks], kb[0], kb[1]);
                mma_f16(Sv[2 * ni + 1], qfh[ks], kb[2], kb[3]);
                mma_f16(Sv[2 * ni + 1], qfl[ks], kb[2], kb[3]);
            }
        }

        bool needmask = (jb + 63 > q0 + 16 * warp);
        #pragma unroll
        for (int nt = 0; nt < 8; nt++) {
            int c0 = jb + 8 * nt + 2 * tig;
            float e0 = fexp_dot(Sv[nt][0]);
            float e1 = fexp_dot(Sv[nt][1]);
            float e2 = fexp_dot(Sv[nt][2]);
            float e3 = fexp_dot(Sv[nt][3]);
            if (needmask) {
                if (c0 + 0 > r0) e0 = 0.f;
                if (c0 + 1 > r0) e1 = 0.f;
                if (c0 + 0 > r1) e2 = 0.f;
                if (c0 + 1 > r1) e3 = 0.f;
            }
            Sv[nt][0] = e0; Sv[nt][1] = e1; Sv[nt][2] = e2; Sv[nt][3] = e3;
            ls0 += e0 + e1;
            ls1 += e2 + e3;
        }

        // P @ V; V fragments via ldmatrix.trans from key-major rows
        #pragma unroll
        for (int kt = 0; kt < 4; kt++) {
            uint32_t pah[4], pal[4];
            float lo0, lo1;
            pah[0] = packh_hi(Sv[2 * kt][0], Sv[2 * kt][1], lo0, lo1);
            pal[0] = packh(lo0, lo1);
            pah[1] = packh_hi(Sv[2 * kt][2], Sv[2 * kt][3], lo0, lo1);
            pal[1] = packh(lo0, lo1);
            pah[2] = packh_hi(Sv[2 * kt + 1][0], Sv[2 * kt + 1][1], lo0, lo1);
            pal[2] = packh(lo0, lo1);
            pah[3] = packh_hi(Sv[2 * kt + 1][2], Sv[2 * kt + 1][3], lo0, lo1);
            pal[3] = packh(lo0, lo1);
            #pragma unroll
            for (int ni = 0; ni < 4; ni++) {
                uint32_t vb[4];
                ldsm4t(vb, smem_u32(&sVh[(16 * kt + (lane & 15)) * FKP
                                         + 16 * ni + ((lane & 16) >> 1)]));
                mma_f16(O[2 * ni + 0], pah, vb[0], vb[1]);
                mma_f16(O[2 * ni + 0], pal, vb[0], vb[1]);
                mma_f16(O[2 * ni + 1], pah, vb[2], vb[3]);
                mma_f16(O[2 * ni + 1], pal, vb[2], vb[3]);
            }
        }
        __syncthreads();
    }

    ls0 += __shfl_xor_sync(0xffffffffu, ls0, 1);
    ls0 += __shfl_xor_sync(0xffffffffu, ls0, 2);
    ls1 += __shfl_xor_sync(0xffffffffu, ls1, 1);
    ls1 += __shfl_xor_sync(0xffffffffu, ls1, 2);
    float rs0 = 1.0f / ls0, rs1 = 1.0f / ls1;
    if (tig == 0) {
        rs_g[bh * S_ + r0] = rs0;
        rs_g[bh * S_ + r1] = rs1;
    }

    #pragma unroll
    for (int nt = 0; nt < 8; nt++) {
        int col = h * D_ + 8 * nt + 2 * tig;
        float o0 = O[nt][0] * rs0, o1 = O[nt][1] * rs0;
        float o2 = O[nt][2] * rs1, o3 = O[nt][3] * rs1;
        __half h0, l0, h1, l1;
        split_f32h(o0, h0, l0); split_f32h(o1, h1, l1);
        *(__half2*)&ctxh[(size_t)(b * S_ + r0) * F_ + col] = __half2(h0, h1);
        *(__half2*)&ctxl[(size_t)(b * S_ + r0) * F_ + col] = __half2(l0, l1);
        split_f32h(o2, h0, l0); split_f32h(o3, h1, l1);
        *(__half2*)&ctxh[(size_t)(b * S_ + r1) * F_ + col] = __half2(h0, h1);
        *(__half2*)&ctxl[(size_t)(b * S_ + r1) * F_ + col] = __half2(l0, l1);
    }
}

// ---------------- Pass 2: recompute QK, write normalized attn once -------
// K tiles double-buffered via cp.async.
#define AW_SMEM_BYTES ((2*128*FKP + 2*64*FKP) * 2)

__global__ __launch_bounds__(256, 2)
void attn_write_mma(const __half* __restrict__ qh_g, const __half* __restrict__ ql_g,
                    const __half* __restrict__ kh_g,
                    const float* __restrict__ rs_g,
                    float* __restrict__ attn) {
    extern __shared__ __half asm_[];
    __half* sQh = asm_;
    __half* sQl = asm_ + 128 * FKP;
    __half* sKst = asm_ + 2 * 128 * FKP;  // 2 stages of [64][FKP]

    int tid = threadIdx.x;
    int warp = tid >> 5, lane = tid & 31;
    int gid = lane >> 2, tig = lane & 3;
    int bh = blockIdx.y;
    int b = bh >> 4, h = bh & 15;
    int q0 = blockIdx.x * 128;

    #pragma unroll
    for (int i = 0; i < 4; i++) {
        int f = tid + 256 * i;
        int r = f >> 3, g = f & 7;
        size_t src = (size_t)(b * S_ + q0 + r) * F_ + h * D_ + g * 8;
        *(uint4*)&sQh[r * FKP + g * 8] = *(const uint4*)(qh_g + src);
        *(uint4*)&sQl[r * FKP + g * 8] = *(const uint4*)(ql_g + src);
    }
    __syncthreads();

    int a_row = lane & 15, a_col = (lane & 16) >> 1;
    int b_row = (lane & 7) + ((lane & 16) >> 1), b_col = lane & 8;
    uint32_t qfh[4][4], qfl[4][4];
    #pragma unroll
    for (int ks = 0; ks < 4; ks++) {
        ldsm4(qfh[ks], smem_u32(&sQh[(16 * warp + a_row) * FKP + 16 * ks + a_col]));
        ldsm4(qfl[ks], smem_u32(&sQl[(16 * warp + a_row) * FKP + 16 * ks + a_col]));
    }

    uint32_t kb0 = smem_u32(sKst);
    auto load_k = [&](int st, int jb) {
        uint32_t base = kb0 + st * (64 * FKP * 2);
        #pragma unroll
        for (int i = 0; i < 2; i++) {
            int f = tid + 256 * i;
            int r = f >> 3, g = f & 7;
            size_t src = (size_t)(b * S_ + jb + r) * F_ + h * D_ + g * 8;
            CP_ASYNC16(base + (r * FKP + g * 8) * 2, kh_g + src);
        }
    };

    int r0 = q0 + 16 * warp + gid;
    int r1 = r0 + 8;
    float rs0 = __ldg(&rs_g[bh * S_ + r0]);
    float rs1 = __ldg(&rs_g[bh * S_ + r1]);
    size_t arow0 = (size_t)(bh * S_ + r0) * S_;
    size_t arow1 = (size_t)(bh * S_ + r1) * S_;

    int ncaus = (q0 + 128) / 64;

    load_k(0, 0);
    CP_COMMIT();

    for (int it = 0; it < ncaus; it++) {
        int jb = it * 64;
        if (it < ncaus - 1) {
            load_k((it + 1) & 1, jb + 64);
            CP_COMMIT();
            CP_WAIT1();
        } else {
            CP_WAIT0();
        }
        __syncthreads();

        const __half* sKh = sKst + (it & 1) * 64 * FKP;

        float Sv[8][4];
        #pragma unroll
        for (int i = 0; i < 8; i++)
            Sv[i][0] = Sv[i][1] = Sv[i][2] = Sv[i][3] = 0.f;
        #pragma unroll
        for (int ks = 0; ks < 4; ks++) {
            #pragma unroll
            for (int ni = 0; ni < 4; ni++) {
                uint32_t kb[4];
                ldsm4(kb, smem_u32(&sKh[(16 * ni + b_row) * FKP + 16 * ks + b_col]));
                mma_f16(Sv[2 * ni + 0], qfh[ks], kb[0], kb[1]);
                mma_f16(Sv[2 * ni + 0], qfl[ks], kb[0], kb[1]);
                mma_f16(Sv[2 * ni + 1], qfh[ks], kb[2], kb[3]);
                mma_f16(Sv[2 * ni + 1], qfl[ks], kb[2], kb[3]);
            }
        }

        bool needmask = (jb + 63 > q0 + 16 * warp);
        #pragma unroll
        for (int nt = 0; nt < 8; nt++) {
            int c0 = jb + 8 * nt + 2 * tig;
            float e0 = fexp_dot(Sv[nt][0]) * rs0;
            float e1 = fexp_dot(Sv[nt][1]) * rs0;
            float e2 = fexp_dot(Sv[nt][2]) * rs1;
            float e3 = fexp_dot(Sv[nt][3]) * rs1;
            if (needmask) {
                if (c0 + 0 > r0) e0 = 0.f;
                if (c0 + 1 > r0) e1 = 0.f;
                if (c0 + 0 > r1) e2 = 0.f;
                if (c0 + 1 > r1) e3 = 0.f;
            }
            __stcs((float2*)&attn[arow0 + c0], make_float2(e0, e1));
            __stcs((float2*)&attn[arow1 + c0], make_float2(e2, e3));
        }
        __syncthreads();
    }

    // fully-masked region: stream zeros
    for (int jb = ncaus * 64; jb < S_; jb += 64) {
        #pragma unroll
        for (int nt = 0; nt < 8; nt++) {
            int c0 = jb + 8 * nt + 2 * tig;
            __stcs((float2*)&attn[arow0 + c0], make_float2(0.f, 0.f));
            __stcs((float2*)&attn[arow1 + c0], make_float2(0.f, 0.f));
        }
    }
}

// ---------------- launch ----------------
extern "C" void kernel_launch(void* const* d_in, const int* in_sizes, int n_in,
                              void* d_out, int out_size) {
    const float* x      = (const float*)d_in[0];
    const float* Wq     = (const float*)d_in[1];
    const float* bq     = (const float*)d_in[2];
    const float* Wk     = (const float*)d_in[3];
    const float* bk     = (const float*)d_in[4];
    const float* Wv     = (const float*)d_in[5];
    const float* bv     = (const float*)d_in[6];
    const float* Wo     = (const float*)d_in[7];
    const float* bo     = (const float*)d_in[8];
    const float* gamma1 = (const float*)d_in[9];
    const float* beta1  = (const float*)d_in[10];
    const float* gamma2 = (const float*)d_in[11];
    const float* beta2  = (const float*)d_in[12];
    const float* pos    = (const float*)d_in[13];

    float* out = (float*)d_out;

    float *xn, *tmp, *rs, *attn_fb;
    cudaGetSymbolAddress((void**)&xn, g_xn);
    cudaGetSymbolAddress((void**)&tmp, g_tmp);
    cudaGetSymbolAddress((void**)&rs, g_rs);
    cudaGetSymbolAddress((void**)&attn_fb, g_attn_fallback);

    __half *xnh, *xnl, *qh, *ql, *kh, *vh, *ctxh, *ctxl;
    __half *wqt, *wkt, *wvt, *wot;
    cudaGetSymbolAddress((void**)&xnh, g_xn_hi);
    cudaGetSymbolAddress((void**)&xnl, g_xn_lo);
    cudaGetSymbolAddress((void**)&qh, g_qh);
    cudaGetSymbolAddress((void**)&ql, g_ql);
    cudaGetSymbolAddress((void**)&kh, g_kh);
    cudaGetSymbolAddress((void**)&vh, g_vh);
    cudaGetSymbolAddress((void**)&ctxh, g_ctx_hi);
    cudaGetSymbolAddress((void**)&ctxl, g_ctx_lo);
    cudaGetSymbolAddress((void**)&wqt, g_WqT);
    cudaGetSymbolAddress((void**)&wkt, g_WkT);
    cudaGetSymbolAddress((void**)&wvt, g_WvT);
    cudaGetSymbolAddress((void**)&wot, g_WoT);

    float* attn = (out_size > OUT_ELEMS) ? (out + OUT_ELEMS) : attn_fb;

    cudaFuncSetAttribute(flash_mma, cudaFuncAttributeMaxDynamicSharedMemorySize,
                         FLASH_SMEM_BYTES);
    cudaFuncSetAttribute(attn_write_mma, cudaFuncAttributeMaxDynamicSharedMemorySize,
                         AW_SMEM_BYTES);
    cudaFuncSetAttribute(gemm_qkv, cudaFuncAttributeMaxDynamicSharedMemorySize,
                         GEMM_SMEM_BYTES);
    cudaFuncSetAttribute(gemm_single, cudaFuncAttributeMaxDynamicSharedMemorySize,
                         GEMM_SMEM_BYTES);

    // 1) weight transposes (fused) + LN1 with fp16 split outputs
    dim3 tb(32, 8), tg(F_ / 32, F_ / 32, 4);
    transpose_all_kernel<<<tg, tb>>>(Wq, wqt, Wk, wkt, Wv, wvt, Wo, wot);
    ln_kernel<<<M_, 256>>>(x, gamma1, beta1, xn, xnh, xnl);

    // 2) fused Q/K/V projections (cp.async pipelined)
    dim3 qkvgrid(F_ / 128, M_ / 128, 3);
    gemm_qkv<<<qkvgrid, 256, GEMM_SMEM_BYTES>>>(xnh, xnl, wqt, wkt, wvt,
                                                bq, bk, bv, pos,
                                                qh, ql, kh, vh);

    // 3) flash pass 1: rowsums + ctx (cp.async double-buffered K/V)
    dim3 fgrid(S_ / 128, BH_);
    flash_mma<<<fgrid, 256, FLASH_SMEM_BYTES>>>(qh, ql, kh, vh, ctxh, ctxl, rs);

    // 4) pass 2: write normalized attn exactly once (cp.async K)
    attn_write_mma<<<fgrid, 256, AW_SMEM_BYTES>>>(qh, ql, kh, rs, attn);

    // 5) output projection + residual -> fp32 tmp
    dim3 ggrid(F_ / 128, M_ / 128);
    gemm_single<<<ggrid, 256, GEMM_SMEM_BYTES>>>(ctxh, ctxl, wot, bo, xn, tmp);

    // 6) LN2
    ln_kernel<<<M_, 256>>>(tmp, gamma2, beta2, out, nullptr, nullptr);
}

// round 14
// speedup vs baseline: 1.8125x; 1.1151x over previous
#include <cuda_runtime.h>
#include <cuda_fp16.h>
#include <cstdint>
#include <math.h>

// Problem constants
#define B_  2
#define S_  2048
#define F_  1024
#define H_  16
#define D_  64
#define M_  (B_ * S_)          // 4096 rows
#define BH_ (B_ * H_)          // 32
#define OUT_ELEMS (M_ * F_)    // 4194304
#define ATTN_ELEMS ((size_t)BH_ * S_ * S_)  // 134217728

// ---------------- device scratch (no allocations allowed) ----------------
__device__ float g_xn[OUT_ELEMS];
__device__ float g_tmp[OUT_ELEMS];
__device__ float g_rs[BH_ * S_];
__device__ float g_attn_fallback[ATTN_ELEMS];

__device__ __half g_xn_hi[OUT_ELEMS];
__device__ __half g_xn_lo[OUT_ELEMS];
__device__ __half g_qh[OUT_ELEMS];
__device__ __half g_ql[OUT_ELEMS];
__device__ __half g_kh[OUT_ELEMS];
__device__ __half g_vh[OUT_ELEMS];
__device__ __half g_ctx_hi[OUT_ELEMS];
__device__ __half g_ctx_lo[OUT_ELEMS];
__device__ __half g_WqT[F_ * F_];
__device__ __half g_WkT[F_ * F_];
__device__ __half g_WvT[F_ * F_];
__device__ __half g_WoT[F_ * F_];

// ---------------- helpers ----------------
__device__ __forceinline__ uint32_t smem_u32(const void* p) {
    uint32_t a;
    asm("{ .reg .u64 t; cvta.to.shared.u64 t, %1; cvt.u32.u64 %0, t; }"
        : "=r"(a) : "l"(p));
    return a;
}
__device__ __forceinline__ void ldsm4(uint32_t* r, uint32_t addr) {
    asm volatile("ldmatrix.sync.aligned.m8n8.x4.shared.b16 {%0,%1,%2,%3}, [%4];"
                 : "=r"(r[0]), "=r"(r[1]), "=r"(r[2]), "=r"(r[3]) : "r"(addr));
}
__device__ __forceinline__ void ldsm4t(uint32_t* r, uint32_t addr) {
    asm volatile("ldmatrix.sync.aligned.m8n8.x4.trans.shared.b16 {%0,%1,%2,%3}, [%4];"
                 : "=r"(r[0]), "=r"(r[1]), "=r"(r[2]), "=r"(r[3]) : "r"(addr));
}
__device__ __forceinline__ void mma_f16(float* c, const uint32_t* a,
                                        uint32_t b0, uint32_t b1) {
    asm volatile("mma.sync.aligned.m16n8k16.row.col.f32.f16.f16.f32 "
                 "{%0,%1,%2,%3}, {%4,%5,%6,%7}, {%8,%9}, {%0,%1,%2,%3};"
                 : "+f"(c[0]), "+f"(c[1]), "+f"(c[2]), "+f"(c[3])
                 : "r"(a[0]), "r"(a[1]), "r"(a[2]), "r"(a[3]), "r"(b0), "r"(b1));
}
#define CP_ASYNC16(dst, src) \
    asm volatile("cp.async.cg.shared.global [%0], [%1], 16;" :: "r"(dst), "l"(src))
#define CP_COMMIT() asm volatile("cp.async.commit_group;")
#define CP_WAIT1() asm volatile("cp.async.wait_group 1;")
#define CP_WAIT0() asm volatile("cp.async.wait_group 0;")

__device__ __forceinline__ void split_f32h(float a, __half& hi, __half& lo) {
    hi = __float2half_rn(a);
    lo = __float2half_rn(a - __half2float(hi));
}
// exp(s*0.125) via FMA-pipe exp2 (no MUFU).
#define EXP_C1 0.18033688011112042f   // 0.125 * log2(e)
__device__ __forceinline__ float fexp_dot(float dot) {
    float y = dot * EXP_C1;
    y = fminf(fmaxf(y, -126.f), 126.f);
    float t = y + 12582912.f;
    int e = (__float_as_int(t) - 0x4B400000) << 23;
    float f = y - (t - 12582912.f);
    float p = 0.00133335581f;
    p = fmaf(p, f, 0.00961812910f);
    p = fmaf(p, f, 0.0555041086f);
    p = fmaf(p, f, 0.240226507f);
    p = fmaf(p, f, 0.693147182f);
    p = fmaf(p, f, 1.0f);
    return __int_as_float(__float_as_int(p) + e);
}
__device__ __forceinline__ uint32_t packh(float a, float b) {
    __half2 h = __floats2half2_rn(a, b);
    return *(uint32_t*)&h;
}

// ---------------- LayerNorm (optional fp16 hi/lo split outputs) ----------
__global__ void ln_kernel(const float* __restrict__ x,
                          const float* __restrict__ gamma,
                          const float* __restrict__ beta,
                          float* __restrict__ out,
                          __half* __restrict__ hi,
                          __half* __restrict__ lo) {
    __shared__ float sred[8];
    int row = blockIdx.x;
    int t = threadIdx.x;
    const float4* xr = (const float4*)(x + (size_t)row * F_);
    float4 v = xr[t];

    float s = v.x + v.y + v.z + v.w;
    #pragma unroll
    for (int o = 16; o; o >>= 1) s += __shfl_xor_sync(0xffffffffu, s, o);
    if ((t & 31) == 0) sred[t >> 5] = s;
    __syncthreads();
    float tot = 0.f;
    #pragma unroll
    for (int i = 0; i < 8; i++) tot += sred[i];
    float mean = tot * (1.0f / F_);
    __syncthreads();

    float dx = v.x - mean, dy = v.y - mean, dz = v.z - mean, dw = v.w - mean;
    float ss = dx*dx + dy*dy + dz*dz + dw*dw;
    #pragma unroll
    for (int o = 16; o; o >>= 1) ss += __shfl_xor_sync(0xffffffffu, ss, o);
    if ((t & 31) == 0) sred[t >> 5] = ss;
    __syncthreads();
    float tot2 = 0.f;
    #pragma unroll
    for (int i = 0; i < 8; i++) tot2 += sred[i];
    float rstd = rsqrtf(tot2 * (1.0f / F_) + 1e-6f);

    float4 g4 = ((const float4*)gamma)[t];
    float4 b4 = ((const float4*)beta)[t];
    float4 o4;
    o4.x = dx * rstd * g4.x + b4.x;
    o4.y = dy * rstd * g4.y + b4.y;
    o4.z = dz * rstd * g4.z + b4.z;
    o4.w = dw * rstd * g4.w + b4.w;
    ((float4*)(out + (size_t)row * F_))[t] = o4;
    if (hi) {
        __half h0, l0, h1, l1, h2, l2, h3, l3;
        split_f32h(o4.x, h0, l0); split_f32h(o4.y, h1, l1);
        split_f32h(o4.z, h2, l2); split_f32h(o4.w, h3, l3);
        size_t base = (size_t)row * F_ + 4 * t;
        *(__half2*)&hi[base]     = __half2(h0, h1);
        *(__half2*)&hi[base + 2] = __half2(h2, h3);
        *(__half2*)&lo[base]     = __half2(l0, l1);
        *(__half2*)&lo[base + 2] = __half2(l2, l3);
    }
}

// ---------------- fused transpose: 4 weights -> fp16 T ------------------
__global__ void transpose_all_kernel(const float* __restrict__ W0, __half* __restrict__ T0,
                                     const float* __restrict__ W1, __half* __restrict__ T1,
                                     const float* __restrict__ W2, __half* __restrict__ T2,
                                     const float* __restrict__ W3, __half* __restrict__ T3) {
    const float* W = (blockIdx.z == 0) ? W0 : (blockIdx.z == 1) ? W1
                   : (blockIdx.z == 2) ? W2 : W3;
    __half* T = (blockIdx.z == 0) ? T0 : (blockIdx.z == 1) ? T1
              : (blockIdx.z == 2) ? T2 : T3;
    __shared__ float t[32][33];
    int bx = blockIdx.x * 32;  // n
    int by = blockIdx.y * 32;  // k
    int tx = threadIdx.x, ty = threadIdx.y;
    #pragma unroll
    for (int i = 0; i < 4; i++)
        t[ty + 8 * i][tx] = W[(size_t)(by + ty + 8 * i) * F_ + bx + tx];
    __syncthreads();
    #pragma unroll
    for (int i = 0; i < 4; i++) {
        float v = t[tx][ty + 8 * i];
        T[(size_t)(bx + ty + 8 * i) * F_ + by + tx] = __float2half_rn(v);
    }
}

// ---------------- GEMM core: cp.async 2-stage pipelined mma --------------
#define GBK32 32
#define NKC (F_ / GBK32)     // 32 chunks
#define G_ROWB 80            // 40 halfs per row
#define G_STAGE 30720
#define GEMM_SMEM_BYTES (2 * G_STAGE)

__device__ __forceinline__ void gemm_core(
        const __half* __restrict__ Ahi, const __half* __restrict__ Alo,
        const __half* __restrict__ Bt,
        const float* __restrict__ bias,
        const float* __restrict__ pos, const float* __restrict__ res,
        float* __restrict__ C, __half* __restrict__ Chi,
        __half* __restrict__ Clo, __half* __restrict__ Cs,
        char* smem, int m0, int n0) {
    uint32_t sb = smem_u32(smem);
    int tid = threadIdx.x;
    int warp = tid >> 5, lane = tid & 31;
    int mw = (warp >> 1) * 32;
    int nw = (warp & 1) * 64;

    float acc[2][8][4];
    #pragma unroll
    for (int i = 0; i < 2; i++)
        #pragma unroll
        for (int j = 0; j < 8; j++)
            #pragma unroll
            for (int c = 0; c < 4; c++) acc[i][j][c] = 0.f;

    int a_row = (lane & 15);
    int a_col = (lane & 16) >> 1;
    int b_row = (lane & 7) + ((lane & 16) >> 1);
    int b_col = (lane & 8);

    int ldr = tid >> 2, ldg = tid & 3;
    auto load_stage = [&](int st, int kc) {
        uint32_t base = sb + st * G_STAGE;
        #pragma unroll
        for (int i = 0; i < 2; i++) {
            int r = ldr + 64 * i;
            uint32_t off = r * G_ROWB + ldg * 16;
            const __half* a0 = Ahi + (size_t)(m0 + r) * F_ + kc + ldg * 8;
            const __half* a1 = Alo + (size_t)(m0 + r) * F_ + kc + ldg * 8;
            const __half* b0 = Bt  + (size_t)(n0 + r) * F_ + kc + ldg * 8;
            CP_ASYNC16(base + off, a0);
            CP_ASYNC16(base + 10240 + off, a1);
            CP_ASYNC16(base + 20480 + off, b0);
        }
    };

    load_stage(0, 0);
    CP_COMMIT();

    for (int i = 0; i < NKC; i++) {
        if (i < NKC - 1) {
            load_stage((i + 1) & 1, (i + 1) * GBK32);
            CP_COMMIT();
            CP_WAIT1();
        } else {
            CP_WAIT0();
        }
        __syncthreads();

        uint32_t stA  = sb + (i & 1) * G_STAGE;
        uint32_t stAl = stA + 10240;
        uint32_t stB  = stA + 20480;
        #pragma unroll
        for (int ks = 0; ks < 2; ks++) {
            int k0 = ks * 16;
            uint32_t ah[2][4], al[2][4];
            #pragma unroll
            for (int mi = 0; mi < 2; mi++) {
                uint32_t ao = (mw + 16 * mi + a_row) * G_ROWB + (k0 + a_col) * 2;
                ldsm4(ah[mi], stA + ao);
                ldsm4(al[mi], stAl + ao);
            }
            #pragma unroll
            for (int ni = 0; ni < 4; ni++) {
                uint32_t bb[4];
                ldsm4(bb, stB + (nw + 16 * ni + b_row) * G_ROWB + (k0 + b_col) * 2);
                #pragma unroll
                for (int mi = 0; mi < 2; mi++) {
                    mma_f16(acc[mi][2 * ni + 0], ah[mi], bb[0], bb[1]);
                    mma_f16(acc[mi][2 * ni + 0], al[mi], bb[0], bb[1]);
                    mma_f16(acc[mi][2 * ni + 1], ah[mi], bb[2], bb[3]);
                    mma_f16(acc[mi][2 * ni + 1], al[mi], bb[2], bb[3]);
                }
            }
        }
        __syncthreads();
    }

    int gid = lane >> 2, tig = lane & 3;
    #pragma unroll
    for (int mi = 0; mi < 2; mi++) {
        #pragma unroll
        for (int nj = 0; nj < 8; nj++) {
            int row = m0 + mw + 16 * mi + gid;
            int col = n0 + nw + 8 * nj + 2 * tig;
            #pragma unroll
            for (int half_ = 0; half_ < 2; half_++) {
                int r = row + half_ * 8;
                int s = r & (S_ - 1);
                float v0 = acc[mi][nj][half_ * 2 + 0] + bias[col];
                float v1 = acc[mi][nj][half_ * 2 + 1] + bias[col + 1];
                if (pos) {
                    v0 += pos[(size_t)s * D_ + (col & (D_ - 1))];
                    v1 += pos[(size_t)s * D_ + ((col + 1) & (D_ - 1))];
                }
                if (res) {
                    v0 += res[(size_t)r * F_ + col];
                    v1 += res[(size_t)r * F_ + col + 1];
                }
                if (C)
                    *(float2*)&C[(size_t)r * F_ + col] = make_float2(v0, v1);
                if (Chi) {
                    __half h0, l0, h1, l1;
                    split_f32h(v0, h0, l0); split_f32h(v1, h1, l1);
                    *(__half2*)&Chi[(size_t)r * F_ + col] = __half2(h0, h1);
                    *(__half2*)&Clo[(size_t)r * F_ + col] = __half2(l0, l1);
                }
                if (Cs)
                    *(__half2*)&Cs[(size_t)r * F_ + col] = __floats2half2_rn(v0, v1);
            }
        }
    }
}

// fused Q/K/V projection: blockIdx.z selects weight/bias/output
__global__ __launch_bounds__(256, 2)
void gemm_qkv(const __half* __restrict__ Ahi, const __half* __restrict__ Alo,
              const __half* __restrict__ Wq, const __half* __restrict__ Wk,
              const __half* __restrict__ Wv,
              const float* __restrict__ bq, const float* __restrict__ bk,
              const float* __restrict__ bv, const float* __restrict__ pos,
              __half* __restrict__ qh, __half* __restrict__ ql,
              __half* __restrict__ kh, __half* __restrict__ vh) {
    extern __shared__ char smem[];
    int z = blockIdx.z;
    const __half* Bt = (z == 0) ? Wq : (z == 1) ? Wk : Wv;
    const float* bias = (z == 0) ? bq : (z == 1) ? bk : bv;
    const float* pp = (z == 1) ? pos : nullptr;
    __half* chi = (z == 0) ? qh : nullptr;
    __half* clo = (z == 0) ? ql : nullptr;
    __half* cs  = (z == 1) ? kh : (z == 2) ? vh : nullptr;
    gemm_core(Ahi, Alo, Bt, bias, pp, nullptr, nullptr, chi, clo, cs,
              smem, blockIdx.y * 128, blockIdx.x * 128);
}

// single GEMM (output projection)
__global__ __launch_bounds__(256, 2)
void gemm_single(const __half* __restrict__ Ahi, const __half* __restrict__ Alo,
                 const __half* __restrict__ Bt, const float* __restrict__ bias,
                 const float* __restrict__ res, float* __restrict__ C) {
    extern __shared__ char smem[];
    gemm_core(Ahi, Alo, Bt, bias, nullptr, res, C, nullptr, nullptr, nullptr,
              smem, blockIdx.y * 128, blockIdx.x * 128);
}

// ---------------- Flash pass 1: rowsums + ctx (NO attn writes) -----------
// K/V double-buffered via cp.async; PV uses single fp16 P (hi only).
#define FKP 72
#define KV_STAGE (2 * 64 * FKP)   // halfs per stage (K + V)
#define FLASH_SMEM_BYTES ((2*128*FKP + 2*KV_STAGE) * 2)

__global__ __launch_bounds__(256, 2)
void flash_mma(const __half* __restrict__ qh_g, const __half* __restrict__ ql_g,
               const __half* __restrict__ kh_g,
               const __half* __restrict__ vh_g,
               __half* __restrict__ ctxh, __half* __restrict__ ctxl,
               float* __restrict__ rs_g) {
    extern __shared__ __half fsm[];
    __half* sQh = fsm;                    // [128][FKP]
    __half* sQl = fsm + 128 * FKP;
    __half* sKV = fsm + 2 * 128 * FKP;    // stage st: K, then V (64 rows each)

    int tid = threadIdx.x;
    int warp = tid >> 5, lane = tid & 31;
    int gid = lane >> 2, tig = lane & 3;
    int bh = blockIdx.y;
    int b = bh >> 4, h = bh & 15;
    int q0 = blockIdx.x * 128;

    #pragma unroll
    for (int i = 0; i < 4; i++) {
        int f = tid + 256 * i;
        int r = f >> 3, g = f & 7;
        size_t src = (size_t)(b * S_ + q0 + r) * F_ + h * D_ + g * 8;
        *(uint4*)&sQh[r * FKP + g * 8] = *(const uint4*)(qh_g + src);
        *(uint4*)&sQl[r * FKP + g * 8] = *(const uint4*)(ql_g + src);
    }
    __syncthreads();

    int a_row = lane & 15, a_col = (lane & 16) >> 1;
    int b_row = (lane & 7) + ((lane & 16) >> 1), b_col = lane & 8;
    uint32_t qfh[4][4], qfl[4][4];
    #pragma unroll
    for (int ks = 0; ks < 4; ks++) {
        ldsm4(qfh[ks], smem_u32(&sQh[(16 * warp + a_row) * FKP + 16 * ks + a_col]));
        ldsm4(qfl[ks], smem_u32(&sQl[(16 * warp + a_row) * FKP + 16 * ks + a_col]));
    }

    uint32_t kvb = smem_u32(sKV);
    auto load_kv = [&](int st, int jb) {
        uint32_t base = kvb + st * (KV_STAGE * 2);
        #pragma unroll
        for (int i = 0; i < 2; i++) {
            int f = tid + 256 * i;
            int r = f >> 3, g = f & 7;
            size_t src = (size_t)(b * S_ + jb + r) * F_ + h * D_ + g * 8;
            uint32_t off = (r * FKP + g * 8) * 2;
            CP_ASYNC16(base + off, kh_g + src);
            CP_ASYNC16(base + 64 * FKP * 2 + off, vh_g + src);
        }
    };

    float O[8][4];
    #pragma unroll
    for (int i = 0; i < 8; i++)
        #pragma unroll
        for (int c = 0; c < 4; c++) O[i][c] = 0.f;
    float ls0 = 0.f, ls1 = 0.f;

    int r0 = q0 + 16 * warp + gid;
    int r1 = r0 + 8;
    int niter = (q0 + 128) / 64;

    load_kv(0, 0);
    CP_COMMIT();

    for (int it = 0; it < niter; it++) {
        int jb = it * 64;
        if (it < niter - 1) {
            load_kv((it + 1) & 1, jb + 64);
            CP_COMMIT();
            CP_WAIT1();
        } else {
            CP_WAIT0();
        }
        __syncthreads();

        const __half* sKh = sKV + (it & 1) * KV_STAGE;
        const __half* sVh = sKh + 64 * FKP;

        float Sv[8][4];
        #pragma unroll
        for (int i = 0; i < 8; i++)
            Sv[i][0] = Sv[i][1] = Sv[i][2] = Sv[i][3] = 0.f;
        #pragma unroll
        for (int ks = 0; ks < 4; ks++) {
            #pragma unroll
            for (int ni = 0; ni < 4; ni++) {
                uint32_t kb[4];
                ldsm4(kb, smem_u32(&sKh[(16 * ni + b_row) * FKP + 16 * ks + b_col]));
                mma_f16(Sv[2 * ni + 0], qfh[ks], kb[0], kb[1]);
                mma_f16(Sv[2 * ni + 0], qfl[ks], kb[0], kb[1]);
                mma_f16(Sv[2 * ni + 1], qfh[ks], kb[2], kb[3]);
                mma_f16(Sv[2 * ni + 1], qfl[ks], kb[2], kb[3]);
            }
        }

        bool needmask = (jb + 63 > q0 + 16 * warp);
        #pragma unroll
        for (int nt = 0; nt < 8; nt++) {
            int c0 = jb + 8 * nt + 2 * tig;
            float e0 = fexp_dot(Sv[nt][0]);
            float e1 = fexp_dot(Sv[nt][1]);
            float e2 = fexp_dot(Sv[nt][2]);
            float e3 = fexp_dot(Sv[nt][3]);
            if (needmask) {
                if (c0 + 0 > r0) e0 = 0.f;
                if (c0 + 1 > r0) e1 = 0.f;
                if (c0 + 0 > r1) e2 = 0.f;
                if (c0 + 1 > r1) e3 = 0.f;
            }
            Sv[nt][0] = e0; Sv[nt][1] = e1; Sv[nt][2] = e2; Sv[nt][3] = e3;
            ls0 += e0 + e1;
            ls1 += e2 + e3;
        }

        // P @ V; single fp16 P operand (lo dropped; ~2^-12 ctx error)
        #pragma unroll
        for (int kt = 0; kt < 4; kt++) {
            uint32_t pah[4];
            pah[0] = packh(Sv[2 * kt][0], Sv[2 * kt][1]);
            pah[1] = packh(Sv[2 * kt][2], Sv[2 * kt][3]);
            pah[2] = packh(Sv[2 * kt + 1][0], Sv[2 * kt + 1][1]);
            pah[3] = packh(Sv[2 * kt + 1][2], Sv[2 * kt + 1][3]);
            #pragma unroll
            for (int ni = 0; ni < 4; ni++) {
                uint32_t vb[4];
                ldsm4t(vb, smem_u32(&sVh[(16 * kt + (lane & 15)) * FKP
                                         + 16 * ni + ((lane & 16) >> 1)]));
                mma_f16(O[2 * ni + 0], pah, vb[0], vb[1]);
                mma_f16(O[2 * ni + 1], pah, vb[2], vb[3]);
            }
        }
        __syncthreads();
    }

    ls0 += __shfl_xor_sync(0xffffffffu, ls0, 1);
    ls0 += __shfl_xor_sync(0xffffffffu, ls0, 2);
    ls1 += __shfl_xor_sync(0xffffffffu, ls1, 1);
    ls1 += __shfl_xor_sync(0xffffffffu, ls1, 2);
    float rs0 = 1.0f / ls0, rs1 = 1.0f / ls1;
    if (tig == 0) {
        rs_g[bh * S_ + r0] = rs0;
        rs_g[bh * S_ + r1] = rs1;
    }

    #pragma unroll
    for (int nt = 0; nt < 8; nt++) {
        int col = h * D_ + 8 * nt + 2 * tig;
        float o0 = O[nt][0] * rs0, o1 = O[nt][1] * rs0;
        float o2 = O[nt][2] * rs1, o3 = O[nt][3] * rs1;
        __half h0, l0, h1, l1;
        split_f32h(o0, h0, l0); split_f32h(o1, h1, l1);
        *(__half2*)&ctxh[(size_t)(b * S_ + r0) * F_ + col] = __half2(h0, h1);
        *(__half2*)&ctxl[(size_t)(b * S_ + r0) * F_ + col] = __half2(l0, l1);
        split_f32h(o2, h0, l0); split_f32h(o3, h1, l1);
        *(__half2*)&ctxh[(size_t)(b * S_ + r1) * F_ + col] = __half2(h0, h1);
        *(__half2*)&ctxl[(size_t)(b * S_ + r1) * F_ + col] = __half2(l0, l1);
    }
}

// ---------------- Pass 2: recompute QK, write normalized attn once -------
#define AW_SMEM_BYTES ((2*128*FKP + 2*64*FKP) * 2)

__global__ __launch_bounds__(256, 2)
void attn_write_mma(const __half* __restrict__ qh_g, const __half* __restrict__ ql_g,
                    const __half* __restrict__ kh_g,
                    const float* __restrict__ rs_g,
                    float* __restrict__ attn) {
    extern __shared__ __half asm_[];
    __half* sQh = asm_;
    __half* sQl = asm_ + 128 * FKP;
    __half* sKst = asm_ + 2 * 128 * FKP;  // 2 stages of [64][FKP]

    int tid = threadIdx.x;
    int warp = tid >> 5, lane = tid & 31;
    int gid = lane >> 2, tig = lane & 3;
    int bh = blockIdx.y;
    int b = bh >> 4, h = bh & 15;
    int q0 = blockIdx.x * 128;

    #pragma unroll
    for (int i = 0; i < 4; i++) {
        int f = tid + 256 * i;
        int r = f >> 3, g = f & 7;
        size_t src = (size_t)(b * S_ + q0 + r) * F_ + h * D_ + g * 8;
        *(uint4*)&sQh[r * FKP + g * 8] = *(const uint4*)(qh_g + src);
        *(uint4*)&sQl[r * FKP + g * 8] = *(const uint4*)(ql_g + src);
    }
    __syncthreads();

    int a_row = lane & 15, a_col = (lane & 16) >> 1;
    int b_row = (lane & 7) + ((lane & 16) >> 1), b_col = lane & 8;
    uint32_t qfh[4][4], qfl[4][4];
    #pragma unroll
    for (int ks = 0; ks < 4; ks++) {
        ldsm4(qfh[ks], smem_u32(&sQh[(16 * warp + a_row) * FKP + 16 * ks + a_col]));
        ldsm4(qfl[ks], smem_u32(&sQl[(16 * warp + a_row) * FKP + 16 * ks + a_col]));
    }

    uint32_t kb0 = smem_u32(sKst);
    auto load_k = [&](int st, int jb) {
        uint32_t base = kb0 + st * (64 * FKP * 2);
        #pragma unroll
        for (int i = 0; i < 2; i++) {
            int f = tid + 256 * i;
            int r = f >> 3, g = f & 7;
            size_t src = (size_t)(b * S_ + jb + r) * F_ + h * D_ + g * 8;
            CP_ASYNC16(base + (r * FKP + g * 8) * 2, kh_g + src);
        }
    };

    int r0 = q0 + 16 * warp + gid;
    int r1 = r0 + 8;
    float rs0 = __ldg(&rs_g[bh * S_ + r0]);
    float rs1 = __ldg(&rs_g[bh * S_ + r1]);
    size_t arow0 = (size_t)(bh * S_ + r0) * S_;
    size_t arow1 = (size_t)(bh * S_ + r1) * S_;

    int ncaus = (q0 + 128) / 64;

    load_k(0, 0);
    CP_COMMIT();

    for (int it = 0; it < ncaus; it++) {
        int jb = it * 64;
        if (it < ncaus - 1) {
            load_k((it + 1) & 1, jb + 64);
            CP_COMMIT();
            CP_WAIT1();
        } else {
            CP_WAIT0();
        }
        __syncthreads();

        const __half* sKh = sKst + (it & 1) * 64 * FKP;

        float Sv[8][4];
        #pragma unroll
        for (int i = 0; i < 8; i++)
            Sv[i][0] = Sv[i][1] = Sv[i][2] = Sv[i][3] = 0.f;
        #pragma unroll
        for (int ks = 0; ks < 4; ks++) {
            #pragma unroll
            for (int ni = 0; ni < 4; ni++) {
                uint32_t kb[4];
                ldsm4(kb, smem_u32(&sKh[(16 * ni + b_row) * FKP + 16 * ks + b_col]));
                mma_f16(Sv[2 * ni + 0], qfh[ks], kb[0], kb[1]);
                mma_f16(Sv[2 * ni + 0], qfl[ks], kb[0], kb[1]);
                mma_f16(Sv[2 * ni + 1], qfh[ks], kb[2], kb[3]);
                mma_f16(Sv[2 * ni + 1], qfl[ks], kb[2], kb[3]);
            }
        }

        bool needmask = (jb + 63 > q0 + 16 * warp);
        #pragma unroll
        for (int nt = 0; nt < 8; nt++) {
            int c0 = jb + 8 * nt + 2 * tig;
            float e0 = fexp_dot(Sv[nt][0]) * rs0;
            float e1 = fexp_dot(Sv[nt][1]) * rs0;
            float e2 = fexp_dot(Sv[nt][2]) * rs1;
            float e3 = fexp_dot(Sv[nt][3]) * rs1;
            if (needmask) {
                if (c0 + 0 > r0) e0 = 0.f;
                if (c0 + 1 > r0) e1 = 0.f;
                if (c0 + 0 > r1) e2 = 0.f;
                if (c0 + 1 > r1) e3 = 0.f;
            }
            __stcs((float2*)&attn[arow0 + c0], make_float2(e0, e1));
            __stcs((float2*)&attn[arow1 + c0], make_float2(e2, e3));
        }
        __syncthreads();
    }

    // fully-masked region: stream zeros
    for (int jb = ncaus * 64; jb < S_; jb += 64) {
        #pragma unroll
        for (int nt = 0; nt < 8; nt++) {
            int c0 = jb + 8 * nt + 2 * tig;
            __stcs((float2*)&attn[arow0 + c0], make_float2(0.f, 0.f));
            __stcs((float2*)&attn[arow1 + c0], make_float2(0.f, 0.f));
        }
    }
}

// ---------------- launch ----------------
extern "C" void kernel_launch(void* const* d_in, const int* in_sizes, int n_in,
                              void* d_out, int out_size) {
    const float* x      = (const float*)d_in[0];
    const float* Wq     = (const float*)d_in[1];
    const float* bq     = (const float*)d_in[2];
    const float* Wk     = (const float*)d_in[3];
    const float* bk     = (const float*)d_in[4];
    const float* Wv     = (const float*)d_in[5];
    const float* bv     = (const float*)d_in[6];
    const float* Wo     = (const float*)d_in[7];
    const float* bo     = (const float*)d_in[8];
    const float* gamma1 = (const float*)d_in[9];
    const float* beta1  = (const float*)d_in[10];
    const float* gamma2 = (const float*)d_in[11];
    const float* beta2  = (const float*)d_in[12];
    const float* pos    = (const float*)d_in[13];

    float* out = (float*)d_out;

    float *xn, *tmp, *rs, *attn_fb;
    cudaGetSymbolAddress((void**)&xn, g_xn);
    cudaGetSymbolAddress((void**)&tmp, g_tmp);
    cudaGetSymbolAddress((void**)&rs, g_rs);
    cudaGetSymbolAddress((void**)&attn_fb, g_attn_fallback);

    __half *xnh, *xnl, *qh, *ql, *kh, *vh, *ctxh, *ctxl;
    __half *wqt, *wkt, *wvt, *wot;
    cudaGetSymbolAddress((void**)&xnh, g_xn_hi);
    cudaGetSymbolAddress((void**)&xnl, g_xn_lo);
    cudaGetSymbolAddress((void**)&qh, g_qh);
    cudaGetSymbolAddress((void**)&ql, g_ql);
    cudaGetSymbolAddress((void**)&kh, g_kh);
    cudaGetSymbolAddress((void**)&vh, g_vh);
    cudaGetSymbolAddress((void**)&ctxh, g_ctx_hi);
    cudaGetSymbolAddress((void**)&ctxl, g_ctx_lo);
    cudaGetSymbolAddress((void**)&wqt, g_WqT);
    cudaGetSymbolAddress((void**)&wkt, g_WkT);
    cudaGetSymbolAddress((void**)&wvt, g_WvT);
    cudaGetSymbolAddress((void**)&wot, g_WoT);

    float* attn = (out_size > OUT_ELEMS) ? (out + OUT_ELEMS) : attn_fb;

    // one-time side stream + fork/join events (created outside capture on
    // the first, uncaptured call; identical launch pattern every call)
    static cudaStream_t s2 = nullptr;
    static cudaEvent_t e_fork = nullptr, e_join = nullptr;
    if (!s2) {
        cudaStreamCreateWithFlags(&s2, cudaStreamNonBlocking);
        cudaEventCreateWithFlags(&e_fork, cudaEventDisableTiming);
        cudaEventCreateWithFlags(&e_join, cudaEventDisableTiming);
    }

    cudaFuncSetAttribute(flash_mma, cudaFuncAttributeMaxDynamicSharedMemorySize,
                         FLASH_SMEM_BYTES);
    cudaFuncSetAttribute(attn_write_mma, cudaFuncAttributeMaxDynamicSharedMemorySize,
                         AW_SMEM_BYTES);
    cudaFuncSetAttribute(gemm_qkv, cudaFuncAttributeMaxDynamicSharedMemorySize,
                         GEMM_SMEM_BYTES);
    cudaFuncSetAttribute(gemm_single, cudaFuncAttributeMaxDynamicSharedMemorySize,
                         GEMM_SMEM_BYTES);

    // 1) weight transposes (fused) + LN1 with fp16 split outputs
    dim3 tb(32, 8), tg(F_ / 32, F_ / 32, 4);
    transpose_all_kernel<<<tg, tb>>>(Wq, wqt, Wk, wkt, Wv, wvt, Wo, wot);
    ln_kernel<<<M_, 256>>>(x, gamma1, beta1, xn, xnh, xnl);

    // 2) fused Q/K/V projections (cp.async pipelined)
    dim3 qkvgrid(F_ / 128, M_ / 128, 3);
    gemm_qkv<<<qkvgrid, 256, GEMM_SMEM_BYTES>>>(xnh, xnl, wqt, wkt, wvt,
                                                bq, bk, bv, pos,
                                                qh, ql, kh, vh);

    // 3) flash pass 1: rowsums + ctx
    dim3 fgrid(S_ / 128, BH_);
    flash_mma<<<fgrid, 256, FLASH_SMEM_BYTES>>>(qh, ql, kh, vh, ctxh, ctxl, rs);

    // 4) fork: attn_write on side stream, overlapping gemm_single + LN2
    cudaEventRecord(e_fork, 0);
    cudaStreamWaitEvent(s2, e_fork, 0);
    attn_write_mma<<<fgrid, 256, AW_SMEM_BYTES, s2>>>(qh, ql, kh, rs, attn);
    cudaEventRecord(e_join, s2);

    // 5) output projection + residual -> fp32 tmp (main stream)
    dim3 ggrid(F_ / 128, M_ / 128);
    gemm_single<<<ggrid, 256, GEMM_SMEM_BYTES>>>(ctxh, ctxl, wot, bo, xn, tmp);

    // 6) LN2 (main stream), then join side stream
    ln_kernel<<<M_, 256>>>(tmp, gamma2, beta2, out, nullptr, nullptr);
    cudaStreamWaitEvent(0, e_join, 0);
}

// round 15
// speedup vs baseline: 1.9570x; 1.0798x over previous
#include <cuda_runtime.h>
#include <cuda_fp16.h>
#include <cstdint>
#include <math.h>

// Problem constants
#define B_  2
#define S_  2048
#define F_  1024
#define H_  16
#define D_  64
#define M_  (B_ * S_)          // 4096 rows
#define BH_ (B_ * H_)          // 32
#define OUT_ELEMS (M_ * F_)    // 4194304
#define ATTN_ELEMS ((size_t)BH_ * S_ * S_)  // 134217728

// ---------------- device scratch (no allocations allowed) ----------------
__device__ float g_xn[OUT_ELEMS];
__device__ float g_tmp[OUT_ELEMS];
__device__ float g_rs[BH_ * S_];
__device__ float g_attn_fallback[ATTN_ELEMS];

__device__ __half g_xn_hi[OUT_ELEMS];
__device__ __half g_xn_lo[OUT_ELEMS];
__device__ __half g_qh[OUT_ELEMS];      // single fp16 Q
__device__ __half g_kh[OUT_ELEMS];
__device__ __half g_vh[OUT_ELEMS];
__device__ __half g_ctx_hi[OUT_ELEMS];
__device__ __half g_ctx_lo[OUT_ELEMS];
__device__ __half g_WqT[F_ * F_];
__device__ __half g_WkT[F_ * F_];
__device__ __half g_WvT[F_ * F_];
__device__ __half g_WoT[F_ * F_];

// ---------------- helpers ----------------
__device__ __forceinline__ uint32_t smem_u32(const void* p) {
    uint32_t a;
    asm("{ .reg .u64 t; cvta.to.shared.u64 t, %1; cvt.u32.u64 %0, t; }"
        : "=r"(a) : "l"(p));
    return a;
}
__device__ __forceinline__ void ldsm4(uint32_t* r, uint32_t addr) {
    asm volatile("ldmatrix.sync.aligned.m8n8.x4.shared.b16 {%0,%1,%2,%3}, [%4];"
                 : "=r"(r[0]), "=r"(r[1]), "=r"(r[2]), "=r"(r[3]) : "r"(addr));
}
__device__ __forceinline__ void ldsm4t(uint32_t* r, uint32_t addr) {
    asm volatile("ldmatrix.sync.aligned.m8n8.x4.trans.shared.b16 {%0,%1,%2,%3}, [%4];"
                 : "=r"(r[0]), "=r"(r[1]), "=r"(r[2]), "=r"(r[3]) : "r"(addr));
}
__device__ __forceinline__ void mma_f16(float* c, const uint32_t* a,
                                        uint32_t b0, uint32_t b1) {
    asm volatile("mma.sync.aligned.m16n8k16.row.col.f32.f16.f16.f32 "
                 "{%0,%1,%2,%3}, {%4,%5,%6,%7}, {%8,%9}, {%0,%1,%2,%3};"
                 : "+f"(c[0]), "+f"(c[1]), "+f"(c[2]), "+f"(c[3])
                 : "r"(a[0]), "r"(a[1]), "r"(a[2]), "r"(a[3]), "r"(b0), "r"(b1));
}
#define CP_ASYNC16(dst, src) \
    asm volatile("cp.async.cg.shared.global [%0], [%1], 16;" :: "r"(dst), "l"(src))
#define CP_COMMIT() asm volatile("cp.async.commit_group;")
#define CP_WAIT1() asm volatile("cp.async.wait_group 1;")
#define CP_WAIT0() asm volatile("cp.async.wait_group 0;")

__device__ __forceinline__ void split_f32h(float a, __half& hi, __half& lo) {
    hi = __float2half_rn(a);
    lo = __float2half_rn(a - __half2float(hi));
}
// exp(s*0.125) via FMA-pipe exp2 (no MUFU).
#define EXP_C1 0.18033688011112042f   // 0.125 * log2(e)
__device__ __forceinline__ float fexp_dot(float dot) {
    float y = dot * EXP_C1;
    y = fminf(fmaxf(y, -126.f), 126.f);
    float t = y + 12582912.f;
    int e = (__float_as_int(t) - 0x4B400000) << 23;
    float f = y - (t - 12582912.f);
    float p = 0.00133335581f;
    p = fmaf(p, f, 0.00961812910f);
    p = fmaf(p, f, 0.0555041086f);
    p = fmaf(p, f, 0.240226507f);
    p = fmaf(p, f, 0.693147182f);
    p = fmaf(p, f, 1.0f);
    return __int_as_float(__float_as_int(p) + e);
}
__device__ __forceinline__ uint32_t packh(float a, float b) {
    __half2 h = __floats2half2_rn(a, b);
    return *(uint32_t*)&h;
}

// ---------------- LayerNorm (optional fp16 hi/lo split outputs) ----------
__global__ void ln_kernel(const float* __restrict__ x,
                          const float* __restrict__ gamma,
                          const float* __restrict__ beta,
                          float* __restrict__ out,
                          __half* __restrict__ hi,
                          __half* __restrict__ lo) {
    __shared__ float sred[8];
    int row = blockIdx.x;
    int t = threadIdx.x;
    const float4* xr = (const float4*)(x + (size_t)row * F_);
    float4 v = xr[t];

    float s = v.x + v.y + v.z + v.w;
    #pragma unroll
    for (int o = 16; o; o >>= 1) s += __shfl_xor_sync(0xffffffffu, s, o);
    if ((t & 31) == 0) sred[t >> 5] = s;
    __syncthreads();
    float tot = 0.f;
    #pragma unroll
    for (int i = 0; i < 8; i++) tot += sred[i];
    float mean = tot * (1.0f / F_);
    __syncthreads();

    float dx = v.x - mean, dy = v.y - mean, dz = v.z - mean, dw = v.w - mean;
    float ss = dx*dx + dy*dy + dz*dz + dw*dw;
    #pragma unroll
    for (int o = 16; o; o >>= 1) ss += __shfl_xor_sync(0xffffffffu, ss, o);
    if ((t & 31) == 0) sred[t >> 5] = ss;
    __syncthreads();
    float tot2 = 0.f;
    #pragma unroll
    for (int i = 0; i < 8; i++) tot2 += sred[i];
    float rstd = rsqrtf(tot2 * (1.0f / F_) + 1e-6f);

    float4 g4 = ((const float4*)gamma)[t];
    float4 b4 = ((const float4*)beta)[t];
    float4 o4;
    o4.x = dx * rstd * g4.x + b4.x;
    o4.y = dy * rstd * g4.y + b4.y;
    o4.z = dz * rstd * g4.z + b4.z;
    o4.w = dw * rstd * g4.w + b4.w;
    ((float4*)(out + (size_t)row * F_))[t] = o4;
    if (hi) {
        __half h0, l0, h1, l1, h2, l2, h3, l3;
        split_f32h(o4.x, h0, l0); split_f32h(o4.y, h1, l1);
        split_f32h(o4.z, h2, l2); split_f32h(o4.w, h3, l3);
        size_t base = (size_t)row * F_ + 4 * t;
        *(__half2*)&hi[base]     = __half2(h0, h1);
        *(__half2*)&hi[base + 2] = __half2(h2, h3);
        *(__half2*)&lo[base]     = __half2(l0, l1);
        *(__half2*)&lo[base + 2] = __half2(l2, l3);
    }
}

// ---------------- fused transpose: 4 weights -> fp16 T ------------------
__global__ void transpose_all_kernel(const float* __restrict__ W0, __half* __restrict__ T0,
                                     const float* __restrict__ W1, __half* __restrict__ T1,
                                     const float* __restrict__ W2, __half* __restrict__ T2,
                                     const float* __restrict__ W3, __half* __restrict__ T3) {
    const float* W = (blockIdx.z == 0) ? W0 : (blockIdx.z == 1) ? W1
                   : (blockIdx.z == 2) ? W2 : W3;
    __half* T = (blockIdx.z == 0) ? T0 : (blockIdx.z == 1) ? T1
              : (blockIdx.z == 2) ? T2 : T3;
    __shared__ float t[32][33];
    int bx = blockIdx.x * 32;  // n
    int by = blockIdx.y * 32;  // k
    int tx = threadIdx.x, ty = threadIdx.y;
    #pragma unroll
    for (int i = 0; i < 4; i++)
        t[ty + 8 * i][tx] = W[(size_t)(by + ty + 8 * i) * F_ + bx + tx];
    __syncthreads();
    #pragma unroll
    for (int i = 0; i < 4; i++) {
        float v = t[tx][ty + 8 * i];
        T[(size_t)(bx + ty + 8 * i) * F_ + by + tx] = __float2half_rn(v);
    }
}

// ---------------- GEMM core: cp.async 2-stage pipelined mma --------------
#define GBK32 32
#define NKC (F_ / GBK32)     // 32 chunks
#define G_ROWB 80            // 40 halfs per row
#define G_STAGE 30720
#define GEMM_SMEM_BYTES (2 * G_STAGE)

__device__ __forceinline__ void gemm_core(
        const __half* __restrict__ Ahi, const __half* __restrict__ Alo,
        const __half* __restrict__ Bt,
        const float* __restrict__ bias,
        const float* __restrict__ pos, const float* __restrict__ res,
        float* __restrict__ C, __half* __restrict__ Chi,
        __half* __restrict__ Clo, __half* __restrict__ Cs,
        char* smem, int m0, int n0) {
    uint32_t sb = smem_u32(smem);
    int tid = threadIdx.x;
    int warp = tid >> 5, lane = tid & 31;
    int mw = (warp >> 1) * 32;
    int nw = (warp & 1) * 64;

    float acc[2][8][4];
    #pragma unroll
    for (int i = 0; i < 2; i++)
        #pragma unroll
        for (int j = 0; j < 8; j++)
            #pragma unroll
            for (int c = 0; c < 4; c++) acc[i][j][c] = 0.f;

    int a_row = (lane & 15);
    int a_col = (lane & 16) >> 1;
    int b_row = (lane & 7) + ((lane & 16) >> 1);
    int b_col = (lane & 8);

    int ldr = tid >> 2, ldg = tid & 3;
    auto load_stage = [&](int st, int kc) {
        uint32_t base = sb + st * G_STAGE;
        #pragma unroll
        for (int i = 0; i < 2; i++) {
            int r = ldr + 64 * i;
            uint32_t off = r * G_ROWB + ldg * 16;
            const __half* a0 = Ahi + (size_t)(m0 + r) * F_ + kc + ldg * 8;
            const __half* a1 = Alo + (size_t)(m0 + r) * F_ + kc + ldg * 8;
            const __half* b0 = Bt  + (size_t)(n0 + r) * F_ + kc + ldg * 8;
            CP_ASYNC16(base + off, a0);
            CP_ASYNC16(base + 10240 + off, a1);
            CP_ASYNC16(base + 20480 + off, b0);
        }
    };

    load_stage(0, 0);
    CP_COMMIT();

    for (int i = 0; i < NKC; i++) {
        if (i < NKC - 1) {
            load_stage((i + 1) & 1, (i + 1) * GBK32);
            CP_COMMIT();
            CP_WAIT1();
        } else {
            CP_WAIT0();
        }
        __syncthreads();

        uint32_t stA  = sb + (i & 1) * G_STAGE;
        uint32_t stAl = stA + 10240;
        uint32_t stB  = stA + 20480;
        #pragma unroll
        for (int ks = 0; ks < 2; ks++) {
            int k0 = ks * 16;
            uint32_t ah[2][4], al[2][4];
            #pragma unroll
            for (int mi = 0; mi < 2; mi++) {
                uint32_t ao = (mw + 16 * mi + a_row) * G_ROWB + (k0 + a_col) * 2;
                ldsm4(ah[mi], stA + ao);
                ldsm4(al[mi], stAl + ao);
            }
            #pragma unroll
            for (int ni = 0; ni < 4; ni++) {
                uint32_t bb[4];
                ldsm4(bb, stB + (nw + 16 * ni + b_row) * G_ROWB + (k0 + b_col) * 2);
                #pragma unroll
                for (int mi = 0; mi < 2; mi++) {
                    mma_f16(acc[mi][2 * ni + 0], ah[mi], bb[0], bb[1]);
                    mma_f16(acc[mi][2 * ni + 0], al[mi], bb[0], bb[1]);
                    mma_f16(acc[mi][2 * ni + 1], ah[mi], bb[2], bb[3]);
                    mma_f16(acc[mi][2 * ni + 1], al[mi], bb[2], bb[3]);
                }
            }
        }
        __syncthreads();
    }

    int gid = lane >> 2, tig = lane & 3;
    #pragma unroll
    for (int mi = 0; mi < 2; mi++) {
        #pragma unroll
        for (int nj = 0; nj < 8; nj++) {
            int row = m0 + mw + 16 * mi + gid;
            int col = n0 + nw + 8 * nj + 2 * tig;
            #pragma unroll
            for (int half_ = 0; half_ < 2; half_++) {
                int r = row + half_ * 8;
                int s = r & (S_ - 1);
                float v0 = acc[mi][nj][half_ * 2 + 0] + bias[col];
                float v1 = acc[mi][nj][half_ * 2 + 1] + bias[col + 1];
                if (pos) {
                    v0 += pos[(size_t)s * D_ + (col & (D_ - 1))];
                    v1 += pos[(size_t)s * D_ + ((col + 1) & (D_ - 1))];
                }
                if (res) {
                    v0 += res[(size_t)r * F_ + col];
                    v1 += res[(size_t)r * F_ + col + 1];
                }
                if (C)
                    *(float2*)&C[(size_t)r * F_ + col] = make_float2(v0, v1);
                if (Chi) {
                    __half h0, l0, h1, l1;
                    split_f32h(v0, h0, l0); split_f32h(v1, h1, l1);
                    *(__half2*)&Chi[(size_t)r * F_ + col] = __half2(h0, h1);
                    *(__half2*)&Clo[(size_t)r * F_ + col] = __half2(l0, l1);
                }
                if (Cs)
                    *(__half2*)&Cs[(size_t)r * F_ + col] = __floats2half2_rn(v0, v1);
            }
        }
    }
}

// fused Q/K/V projection: blockIdx.z selects weight/bias/output (all fp16 single)
__global__ __launch_bounds__(256, 2)
void gemm_qkv(const __half* __restrict__ Ahi, const __half* __restrict__ Alo,
              const __half* __restrict__ Wq, const __half* __restrict__ Wk,
              const __half* __restrict__ Wv,
              const float* __restrict__ bq, const float* __restrict__ bk,
              const float* __restrict__ bv, const float* __restrict__ pos,
              __half* __restrict__ qh,
              __half* __restrict__ kh, __half* __restrict__ vh) {
    extern __shared__ char smem[];
    int z = blockIdx.z;
    const __half* Bt = (z == 0) ? Wq : (z == 1) ? Wk : Wv;
    const float* bias = (z == 0) ? bq : (z == 1) ? bk : bv;
    const float* pp = (z == 1) ? pos : nullptr;
    __half* cs = (z == 0) ? qh : (z == 1) ? kh : vh;
    gemm_core(Ahi, Alo, Bt, bias, pp, nullptr, nullptr, nullptr, nullptr, cs,
              smem, blockIdx.y * 128, blockIdx.x * 128);
}

// single GEMM (output projection)
__global__ __launch_bounds__(256, 2)
void gemm_single(const __half* __restrict__ Ahi, const __half* __restrict__ Alo,
                 const __half* __restrict__ Bt, const float* __restrict__ bias,
                 const float* __restrict__ res, float* __restrict__ C) {
    extern __shared__ char smem[];
    gemm_core(Ahi, Alo, Bt, bias, nullptr, res, C, nullptr, nullptr, nullptr,
              smem, blockIdx.y * 128, blockIdx.x * 128);
}

// ---------------- Flash pass 1: rowsums + ctx (NO attn writes) -----------
// Single fp16 Q and P; K/V double-buffered via cp.async.
#define FKP 72
#define KV_STAGE (2 * 64 * FKP)   // halfs per stage (K + V)
#define FLASH_SMEM_BYTES ((128*FKP + 2*KV_STAGE) * 2)

__global__ __launch_bounds__(256, 2)
void flash_mma(const __half* __restrict__ qh_g,
               const __half* __restrict__ kh_g,
               const __half* __restrict__ vh_g,
               __half* __restrict__ ctxh, __half* __restrict__ ctxl,
               float* __restrict__ rs_g) {
    extern __shared__ __half fsm[];
    __half* sQh = fsm;                    // [128][FKP]
    __half* sKV = fsm + 128 * FKP;        // stage st: K, then V (64 rows each)

    int tid = threadIdx.x;
    int warp = tid >> 5, lane = tid & 31;
    int gid = lane >> 2, tig = lane & 3;
    int bh = blockIdx.y;
    int b = bh >> 4, h = bh & 15;
    int q0 = blockIdx.x * 128;

    #pragma unroll
    for (int i = 0; i < 4; i++) {
        int f = tid + 256 * i;
        int r = f >> 3, g = f & 7;
        size_t src = (size_t)(b * S_ + q0 + r) * F_ + h * D_ + g * 8;
        *(uint4*)&sQh[r * FKP + g * 8] = *(const uint4*)(qh_g + src);
    }
    __syncthreads();

    int a_row = lane & 15, a_col = (lane & 16) >> 1;
    int b_row = (lane & 7) + ((lane & 16) >> 1), b_col = lane & 8;
    uint32_t qfh[4][4];
    #pragma unroll
    for (int ks = 0; ks < 4; ks++)
        ldsm4(qfh[ks], smem_u32(&sQh[(16 * warp + a_row) * FKP + 16 * ks + a_col]));

    uint32_t kvb = smem_u32(sKV);
    auto load_kv = [&](int st, int jb) {
        uint32_t base = kvb + st * (KV_STAGE * 2);
        #pragma unroll
        for (int i = 0; i < 2; i++) {
            int f = tid + 256 * i;
            int r = f >> 3, g = f & 7;
            size_t src = (size_t)(b * S_ + jb + r) * F_ + h * D_ + g * 8;
            uint32_t off = (r * FKP + g * 8) * 2;
            CP_ASYNC16(base + off, kh_g + src);
            CP_ASYNC16(base + 64 * FKP * 2 + off, vh_g + src);
        }
    };

    float O[8][4];
    #pragma unroll
    for (int i = 0; i < 8; i++)
        #pragma unroll
        for (int c = 0; c < 4; c++) O[i][c] = 0.f;
    float ls0 = 0.f, ls1 = 0.f;

    int r0 = q0 + 16 * warp + gid;
    int r1 = r0 + 8;
    int niter = (q0 + 128) / 64;

    load_kv(0, 0);
    CP_COMMIT();

    for (int it = 0; it < niter; it++) {
        int jb = it * 64;
        if (it < niter - 1) {
            load_kv((it + 1) & 1, jb + 64);
            CP_COMMIT();
            CP_WAIT1();
        } else {
            CP_WAIT0();
        }
        __syncthreads();

        const __half* sKh = sKV + (it & 1) * KV_STAGE;
        const __half* sVh = sKh + 64 * FKP;

        float Sv[8][4];
        #pragma unroll
        for (int i = 0; i < 8; i++)
            Sv[i][0] = Sv[i][1] = Sv[i][2] = Sv[i][3] = 0.f;
        #pragma unroll
        for (int ks = 0; ks < 4; ks++) {
            #pragma unroll
            for (int ni = 0; ni < 4; ni++) {
                uint32_t kb[4];
                ldsm4(kb, smem_u32(&sKh[(16 * ni + b_row) * FKP + 16 * ks + b_col]));
                mma_f16(Sv[2 * ni + 0], qfh[ks], kb[0], kb[1]);
                mma_f16(Sv[2 * ni + 1], qfh[ks], kb[2], kb[3]);
            }
        }

        bool needmask = (jb + 63 > q0 + 16 * warp);
        #pragma unroll
        for (int nt = 0; nt < 8; nt++) {
            int c0 = jb + 8 * nt + 2 * tig;
            float e0 = fexp_dot(Sv[nt][0]);
            float e1 = fexp_dot(Sv[nt][1]);
            float e2 = fexp_dot(Sv[nt][2]);
            float e3 = fexp_dot(Sv[nt][3]);
            if (needmask) {
                if (c0 + 0 > r0) e0 = 0.f;
                if (c0 + 1 > r0) e1 = 0.f;
                if (c0 + 0 > r1) e2 = 0.f;
                if (c0 + 1 > r1) e3 = 0.f;
            }
            Sv[nt][0] = e0; Sv[nt][1] = e1; Sv[nt][2] = e2; Sv[nt][3] = e3;
            ls0 += e0 + e1;
            ls1 += e2 + e3;
        }

        // P @ V; single fp16 P
        #pragma unroll
        for (int kt = 0; kt < 4; kt++) {
            uint32_t pah[4];
            pah[0] = packh(Sv[2 * kt][0], Sv[2 * kt][1]);
            pah[1] = packh(Sv[2 * kt][2], Sv[2 * kt][3]);
            pah[2] = packh(Sv[2 * kt + 1][0], Sv[2 * kt + 1][1]);
            pah[3] = packh(Sv[2 * kt + 1][2], Sv[2 * kt + 1][3]);
            #pragma unroll
            for (int ni = 0; ni < 4; ni++) {
                uint32_t vb[4];
                ldsm4t(vb, smem_u32(&sVh[(16 * kt + (lane & 15)) * FKP
                                         + 16 * ni + ((lane & 16) >> 1)]));
                mma_f16(O[2 * ni + 0], pah, vb[0], vb[1]);
                mma_f16(O[2 * ni + 1], pah, vb[2], vb[3]);
            }
        }
        __syncthreads();
    }

    ls0 += __shfl_xor_sync(0xffffffffu, ls0, 1);
    ls0 += __shfl_xor_sync(0xffffffffu, ls0, 2);
    ls1 += __shfl_xor_sync(0xffffffffu, ls1, 1);
    ls1 += __shfl_xor_sync(0xffffffffu, ls1, 2);
    float rs0 = 1.0f / ls0, rs1 = 1.0f / ls1;
    if (tig == 0) {
        rs_g[bh * S_ + r0] = rs0;
        rs_g[bh * S_ + r1] = rs1;
    }

    #pragma unroll
    for (int nt = 0; nt < 8; nt++) {
        int col = h * D_ + 8 * nt + 2 * tig;
        float o0 = O[nt][0] * rs0, o1 = O[nt][1] * rs0;
        float o2 = O[nt][2] * rs1, o3 = O[nt][3] * rs1;
        __half h0, l0, h1, l1;
        split_f32h(o0, h0, l0); split_f32h(o1, h1, l1);
        *(__half2*)&ctxh[(size_t)(b * S_ + r0) * F_ + col] = __half2(h0, h1);
        *(__half2*)&ctxl[(size_t)(b * S_ + r0) * F_ + col] = __half2(l0, l1);
        split_f32h(o2, h0, l0); split_f32h(o3, h1, l1);
        *(__half2*)&ctxh[(size_t)(b * S_ + r1) * F_ + col] = __half2(h0, h1);
        *(__half2*)&ctxl[(size_t)(b * S_ + r1) * F_ + col] = __half2(l0, l1);
    }
}

// ---------------- Pass 2: recompute QK, write normalized attn once -------
// Single fp16 Q; K double-buffered via cp.async.
#define AW_SMEM_BYTES ((128*FKP + 2*64*FKP) * 2)

__global__ __launch_bounds__(256, 2)
void attn_write_mma(const __half* __restrict__ qh_g,
                    const __half* __restrict__ kh_g,
                    const float* __restrict__ rs_g,
                    float* __restrict__ attn) {
    extern __shared__ __half asm_[];
    __half* sQh = asm_;
    __half* sKst = asm_ + 128 * FKP;      // 2 stages of [64][FKP]

    int tid = threadIdx.x;
    int warp = tid >> 5, lane = tid & 31;
    int gid = lane >> 2, tig = lane & 3;
    int bh = blockIdx.y;
    int b = bh >> 4, h = bh & 15;
    int q0 = blockIdx.x * 128;

    #pragma unroll
    for (int i = 0; i < 4; i++) {
        int f = tid + 256 * i;
        int r = f >> 3, g = f & 7;
        size_t src = (size_t)(b * S_ + q0 + r) * F_ + h * D_ + g * 8;
        *(uint4*)&sQh[r * FKP + g * 8] = *(const uint4*)(qh_g + src);
    }
    __syncthreads();

    int a_row = lane & 15, a_col = (lane & 16) >> 1;
    int b_row = (lane & 7) + ((lane & 16) >> 1), b_col = lane & 8;
    uint32_t qfh[4][4];
    #pragma unroll
    for (int ks = 0; ks < 4; ks++)
        ldsm4(qfh[ks], smem_u32(&sQh[(16 * warp + a_row) * FKP + 16 * ks + a_col]));

    uint32_t kb0 = smem_u32(sKst);
    auto load_k = [&](int st, int jb) {
        uint32_t base = kb0 + st * (64 * FKP * 2);
        #pragma unroll
        for (int i = 0; i < 2; i++) {
            int f = tid + 256 * i;
            int r = f >> 3, g = f & 7;
            size_t src = (size_t)(b * S_ + jb + r) * F_ + h * D_ + g * 8;
            CP_ASYNC16(base + (r * FKP + g * 8) * 2, kh_g + src);
        }
    };

    int r0 = q0 + 16 * warp + gid;
    int r1 = r0 + 8;
    float rs0 = __ldg(&rs_g[bh * S_ + r0]);
    float rs1 = __ldg(&rs_g[bh * S_ + r1]);
    size_t arow0 = (size_t)(bh * S_ + r0) * S_;
    size_t arow1 = (size_t)(bh * S_ + r1) * S_;

    int ncaus = (q0 + 128) / 64;

    load_k(0, 0);
    CP_COMMIT();

    for (int it = 0; it < ncaus; it++) {
        int jb = it * 64;
        if (it < ncaus - 1) {
            load_k((it + 1) & 1, jb + 64);
            CP_COMMIT();
            CP_WAIT1();
        } else {
            CP_WAIT0();
        }
        __syncthreads();

        const __half* sKh = sKst + (it & 1) * 64 * FKP;

        float Sv[8][4];
        #pragma unroll
        for (int i = 0; i < 8; i++)
            Sv[i][0] = Sv[i][1] = Sv[i][2] = Sv[i][3] = 0.f;
        #pragma unroll
        for (int ks = 0; ks < 4; ks++) {
            #pragma unroll
            for (int ni = 0; ni < 4; ni++) {
                uint32_t kb[4];
                ldsm4(kb, smem_u32(&sKh[(16 * ni + b_row) * FKP + 16 * ks + b_col]));
                mma_f16(Sv[2 * ni + 0], qfh[ks], kb[0], kb[1]);
                mma_f16(Sv[2 * ni + 1], qfh[ks], kb[2], kb[3]);
            }
        }

        bool needmask = (jb + 63 > q0 + 16 * warp);
        #pragma unroll
        for (int nt = 0; nt < 8; nt++) {
            int c0 = jb + 8 * nt + 2 * tig;
            float e0 = fexp_dot(Sv[nt][0]) * rs0;
            float e1 = fexp_dot(Sv[nt][1]) * rs0;
            float e2 = fexp_dot(Sv[nt][2]) * rs1;
            float e3 = fexp_dot(Sv[nt][3]) * rs1;
            if (needmask) {
                if (c0 + 0 > r0) e0 = 0.f;
                if (c0 + 1 > r0) e1 = 0.f;
                if (c0 + 0 > r1) e2 = 0.f;
                if (c0 + 1 > r1) e3 = 0.f;
            }
            __stcs((float2*)&attn[arow0 + c0], make_float2(e0, e1));
            __stcs((float2*)&attn[arow1 + c0], make_float2(e2, e3));
        }
        __syncthreads();
    }

    // fully-masked region: stream zeros
    for (int jb = ncaus * 64; jb < S_; jb += 64) {
        #pragma unroll
        for (int nt = 0; nt < 8; nt++) {
            int c0 = jb + 8 * nt + 2 * tig;
            __stcs((float2*)&attn[arow0 + c0], make_float2(0.f, 0.f));
            __stcs((float2*)&attn[arow1 + c0], make_float2(0.f, 0.f));
        }
    }
}

// ---------------- launch ----------------
extern "C" void kernel_launch(void* const* d_in, const int* in_sizes, int n_in,
                              void* d_out, int out_size) {
    const float* x      = (const float*)d_in[0];
    const float* Wq     = (const float*)d_in[1];
    const float* bq     = (const float*)d_in[2];
    const float* Wk     = (const float*)d_in[3];
    const float* bk     = (const float*)d_in[4];
    const float* Wv     = (const float*)d_in[5];
    const float* bv     = (const float*)d_in[6];
    const float* Wo     = (const float*)d_in[7];
    const float* bo     = (const float*)d_in[8];
    const float* gamma1 = (const float*)d_in[9];
    const float* beta1  = (const float*)d_in[10];
    const float* gamma2 = (const float*)d_in[11];
    const float* beta2  = (const float*)d_in[12];
    const float* pos    = (const float*)d_in[13];

    float* out = (float*)d_out;

    float *xn, *tmp, *rs, *attn_fb;
    cudaGetSymbolAddress((void**)&xn, g_xn);
    cudaGetSymbolAddress((void**)&tmp, g_tmp);
    cudaGetSymbolAddress((void**)&rs, g_rs);
    cudaGetSymbolAddress((void**)&attn_fb, g_attn_fallback);

    __half *xnh, *xnl, *qh, *kh, *vh, *ctxh, *ctxl;
    __half *wqt, *wkt, *wvt, *wot;
    cudaGetSymbolAddress((void**)&xnh, g_xn_hi);
    cudaGetSymbolAddress((void**)&xnl, g_xn_lo);
    cudaGetSymbolAddress((void**)&qh, g_qh);
    cudaGetSymbolAddress((void**)&kh, g_kh);
    cudaGetSymbolAddress((void**)&vh, g_vh);
    cudaGetSymbolAddress((void**)&ctxh, g_ctx_hi);
    cudaGetSymbolAddress((void**)&ctxl, g_ctx_lo);
    cudaGetSymbolAddress((void**)&wqt, g_WqT);
    cudaGetSymbolAddress((void**)&wkt, g_WkT);
    cudaGetSymbolAddress((void**)&wvt, g_WvT);
    cudaGetSymbolAddress((void**)&wot, g_WoT);

    float* attn = (out_size > OUT_ELEMS) ? (out + OUT_ELEMS) : attn_fb;

    // one-time side stream + fork/join events
    static cudaStream_t s2 = nullptr;
    static cudaEvent_t e_fork = nullptr, e_join = nullptr;
    if (!s2) {
        cudaStreamCreateWithFlags(&s2, cudaStreamNonBlocking);
        cudaEventCreateWithFlags(&e_fork, cudaEventDisableTiming);
        cudaEventCreateWithFlags(&e_join, cudaEventDisableTiming);
    }

    cudaFuncSetAttribute(flash_mma, cudaFuncAttributeMaxDynamicSharedMemorySize,
                         FLASH_SMEM_BYTES);
    cudaFuncSetAttribute(attn_write_mma, cudaFuncAttributeMaxDynamicSharedMemorySize,
                         AW_SMEM_BYTES);
    cudaFuncSetAttribute(gemm_qkv, cudaFuncAttributeMaxDynamicSharedMemorySize,
                         GEMM_SMEM_BYTES);
    cudaFuncSetAttribute(gemm_single, cudaFuncAttributeMaxDynamicSharedMemorySize,
                         GEMM_SMEM_BYTES);

    // 1) weight transposes (fused) + LN1 with fp16 split outputs
    dim3 tb(32, 8), tg(F_ / 32, F_ / 32, 4);
    transpose_all_kernel<<<tg, tb>>>(Wq, wqt, Wk, wkt, Wv, wvt, Wo, wot);
    ln_kernel<<<M_, 256>>>(x, gamma1, beta1, xn, xnh, xnl);

    // 2) fused Q/K/V projections (cp.async pipelined; all fp16-single outs)
    dim3 qkvgrid(F_ / 128, M_ / 128, 3);
    gemm_qkv<<<qkvgrid, 256, GEMM_SMEM_BYTES>>>(xnh, xnl, wqt, wkt, wvt,
                                                bq, bk, bv, pos,
                                                qh, kh, vh);

    // 3) flash pass 1: rowsums + ctx
    dim3 fgrid(S_ / 128, BH_);
    flash_mma<<<fgrid, 256, FLASH_SMEM_BYTES>>>(qh, kh, vh, ctxh, ctxl, rs);

    // 4) fork: attn_write on side stream, overlapping gemm_single + LN2
    cudaEventRecord(e_fork, 0);
    cudaStreamWaitEvent(s2, e_fork, 0);
    attn_write_mma<<<fgrid, 256, AW_SMEM_BYTES, s2>>>(qh, kh, rs, attn);
    cudaEventRecord(e_join, s2);

    // 5) output projection + residual -> fp32 tmp (main stream)
    dim3 ggrid(F_ / 128, M_ / 128);
    gemm_single<<<ggrid, 256, GEMM_SMEM_BYTES>>>(ctxh, ctxl, wot, bo, xn, tmp);

    // 6) LN2 (main stream), then join side stream
    ln_kernel<<<M_, 256>>>(tmp, gamma2, beta2, out, nullptr, nullptr);
    cudaStreamWaitEvent(0, e_join, 0);
}

// round 16
// speedup vs baseline: 1.9856x; 1.0146x over previous
#include <cuda_runtime.h>
#include <cuda_fp16.h>
#include <cstdint>
#include <math.h>

// Problem constants
#define B_  2
#define S_  2048
#define F_  1024
#define H_  16
#define D_  64
#define M_  (B_ * S_)          // 4096 rows
#define BH_ (B_ * H_)          // 32
#define OUT_ELEMS (M_ * F_)    // 4194304
#define ATTN_ELEMS ((size_t)BH_ * S_ * S_)  // 134217728

// ---------------- device scratch (no allocations allowed) ----------------
__device__ float g_xn[OUT_ELEMS];
__device__ float g_tmp[OUT_ELEMS];
__device__ float g_rs[BH_ * S_];
__device__ float g_attn_fallback[ATTN_ELEMS];

__device__ __half g_xn_hi[OUT_ELEMS];
__device__ __half g_xn_lo[OUT_ELEMS];
__device__ __half g_qh[OUT_ELEMS];
__device__ __half g_kh[OUT_ELEMS];
__device__ __half g_vh[OUT_ELEMS];
__device__ __half g_ctx_hi[OUT_ELEMS];
__device__ __half g_ctx_lo[OUT_ELEMS];
__device__ __half g_WqT[F_ * F_];
__device__ __half g_WkT[F_ * F_];
__device__ __half g_WvT[F_ * F_];
__device__ __half g_WoT[F_ * F_];

// ---------------- helpers ----------------
__device__ __forceinline__ uint32_t smem_u32(const void* p) {
    uint32_t a;
    asm("{ .reg .u64 t; cvta.to.shared.u64 t, %1; cvt.u32.u64 %0, t; }"
        : "=r"(a) : "l"(p));
    return a;
}
__device__ __forceinline__ void ldsm4(uint32_t* r, uint32_t addr) {
    asm volatile("ldmatrix.sync.aligned.m8n8.x4.shared.b16 {%0,%1,%2,%3}, [%4];"
                 : "=r"(r[0]), "=r"(r[1]), "=r"(r[2]), "=r"(r[3]) : "r"(addr));
}
__device__ __forceinline__ void ldsm4t(uint32_t* r, uint32_t addr) {
    asm volatile("ldmatrix.sync.aligned.m8n8.x4.trans.shared.b16 {%0,%1,%2,%3}, [%4];"
                 : "=r"(r[0]), "=r"(r[1]), "=r"(r[2]), "=r"(r[3]) : "r"(addr));
}
__device__ __forceinline__ void mma_f16(float* c, const uint32_t* a,
                                        uint32_t b0, uint32_t b1) {
    asm volatile("mma.sync.aligned.m16n8k16.row.col.f32.f16.f16.f32 "
                 "{%0,%1,%2,%3}, {%4,%5,%6,%7}, {%8,%9}, {%0,%1,%2,%3};"
                 : "+f"(c[0]), "+f"(c[1]), "+f"(c[2]), "+f"(c[3])
                 : "r"(a[0]), "r"(a[1]), "r"(a[2]), "r"(a[3]), "r"(b0), "r"(b1));
}
#define CP_ASYNC16(dst, src) \
    asm volatile("cp.async.cg.shared.global [%0], [%1], 16;" :: "r"(dst), "l"(src))
#define CP_COMMIT() asm volatile("cp.async.commit_group;")
#define CP_WAIT1() asm volatile("cp.async.wait_group 1;")
#define CP_WAIT0() asm volatile("cp.async.wait_group 0;")

__device__ __forceinline__ void split_f32h(float a, __half& hi, __half& lo) {
    hi = __float2half_rn(a);
    lo = __float2half_rn(a - __half2float(hi));
}
// exp(s*0.125) via FMA-pipe exp2 (no MUFU).
#define EXP_C1 0.18033688011112042f   // 0.125 * log2(e)
__device__ __forceinline__ float fexp_dot(float dot) {
    float y = dot * EXP_C1;
    y = fminf(fmaxf(y, -126.f), 126.f);
    float t = y + 12582912.f;
    int e = (__float_as_int(t) - 0x4B400000) << 23;
    float f = y - (t - 12582912.f);
    float p = 0.00133335581f;
    p = fmaf(p, f, 0.00961812910f);
    p = fmaf(p, f, 0.0555041086f);
    p = fmaf(p, f, 0.240226507f);
    p = fmaf(p, f, 0.693147182f);
    p = fmaf(p, f, 1.0f);
    return __int_as_float(__float_as_int(p) + e);
}
__device__ __forceinline__ uint32_t packh(float a, float b) {
    __half2 h = __floats2half2_rn(a, b);
    return *(uint32_t*)&h;
}

// ---------------- LayerNorm (optional fp16 hi/lo split outputs) ----------
__global__ void ln_kernel(const float* __restrict__ x,
                          const float* __restrict__ gamma,
                          const float* __restrict__ beta,
                          float* __restrict__ out,
                          __half* __restrict__ hi,
                          __half* __restrict__ lo) {
    __shared__ float sred[8];
    int row = blockIdx.x;
    int t = threadIdx.x;
    const float4* xr = (const float4*)(x + (size_t)row * F_);
    float4 v = xr[t];

    float s = v.x + v.y + v.z + v.w;
    #pragma unroll
    for (int o = 16; o; o >>= 1) s += __shfl_xor_sync(0xffffffffu, s, o);
    if ((t & 31) == 0) sred[t >> 5] = s;
    __syncthreads();
    float tot = 0.f;
    #pragma unroll
    for (int i = 0; i < 8; i++) tot += sred[i];
    float mean = tot * (1.0f / F_);
    __syncthreads();

    float dx = v.x - mean, dy = v.y - mean, dz = v.z - mean, dw = v.w - mean;
    float ss = dx*dx + dy*dy + dz*dz + dw*dw;
    #pragma unroll
    for (int o = 16; o; o >>= 1) ss += __shfl_xor_sync(0xffffffffu, ss, o);
    if ((t & 31) == 0) sred[t >> 5] = ss;
    __syncthreads();
    float tot2 = 0.f;
    #pragma unroll
    for (int i = 0; i < 8; i++) tot2 += sred[i];
    float rstd = rsqrtf(tot2 * (1.0f / F_) + 1e-6f);

    float4 g4 = ((const float4*)gamma)[t];
    float4 b4 = ((const float4*)beta)[t];
    float4 o4;
    o4.x = dx * rstd * g4.x + b4.x;
    o4.y = dy * rstd * g4.y + b4.y;
    o4.z = dz * rstd * g4.z + b4.z;
    o4.w = dw * rstd * g4.w + b4.w;
    ((float4*)(out + (size_t)row * F_))[t] = o4;
    if (hi) {
        __half h0, l0, h1, l1, h2, l2, h3, l3;
        split_f32h(o4.x, h0, l0); split_f32h(o4.y, h1, l1);
        split_f32h(o4.z, h2, l2); split_f32h(o4.w, h3, l3);
        size_t base = (size_t)row * F_ + 4 * t;
        *(__half2*)&hi[base]     = __half2(h0, h1);
        *(__half2*)&hi[base + 2] = __half2(h2, h3);
        *(__half2*)&lo[base]     = __half2(l0, l1);
        *(__half2*)&lo[base + 2] = __half2(l2, l3);
    }
}

// ---------------- fused transpose: 4 weights -> fp16 T ------------------
__global__ void transpose_all_kernel(const float* __restrict__ W0, __half* __restrict__ T0,
                                     const float* __restrict__ W1, __half* __restrict__ T1,
                                     const float* __restrict__ W2, __half* __restrict__ T2,
                                     const float* __restrict__ W3, __half* __restrict__ T3) {
    const float* W = (blockIdx.z == 0) ? W0 : (blockIdx.z == 1) ? W1
                   : (blockIdx.z == 2) ? W2 : W3;
    __half* T = (blockIdx.z == 0) ? T0 : (blockIdx.z == 1) ? T1
              : (blockIdx.z == 2) ? T2 : T3;
    __shared__ float t[32][33];
    int bx = blockIdx.x * 32;  // n
    int by = blockIdx.y * 32;  // k
    int tx = threadIdx.x, ty = threadIdx.y;
    #pragma unroll
    for (int i = 0; i < 4; i++)
        t[ty + 8 * i][tx] = W[(size_t)(by + ty + 8 * i) * F_ + bx + tx];
    __syncthreads();
    #pragma unroll
    for (int i = 0; i < 4; i++) {
        float v = t[tx][ty + 8 * i];
        T[(size_t)(bx + ty + 8 * i) * F_ + by + tx] = __float2half_rn(v);
    }
}

// ---------------- GEMM core: cp.async 2-stage pipelined mma --------------
#define GBK32 32
#define NKC (F_ / GBK32)     // 32 chunks
#define G_ROWB 80            // 40 halfs per row
#define G_STAGE 30720
#define GEMM_SMEM_BYTES (2 * G_STAGE)

__device__ __forceinline__ void gemm_core(
        const __half* __restrict__ Ahi, const __half* __restrict__ Alo,
        const __half* __restrict__ Bt,
        const float* __restrict__ bias,
        const float* __restrict__ pos, const float* __restrict__ res,
        float* __restrict__ C, __half* __restrict__ Chi,
        __half* __restrict__ Clo, __half* __restrict__ Cs,
        char* smem, int m0, int n0) {
    uint32_t sb = smem_u32(smem);
    int tid = threadIdx.x;
    int warp = tid >> 5, lane = tid & 31;
    int mw = (warp >> 1) * 32;
    int nw = (warp & 1) * 64;

    float acc[2][8][4];
    #pragma unroll
    for (int i = 0; i < 2; i++)
        #pragma unroll
        for (int j = 0; j < 8; j++)
            #pragma unroll
            for (int c = 0; c < 4; c++) acc[i][j][c] = 0.f;

    int a_row = (lane & 15);
    int a_col = (lane & 16) >> 1;
    int b_row = (lane & 7) + ((lane & 16) >> 1);
    int b_col = (lane & 8);

    int ldr = tid >> 2, ldg = tid & 3;
    auto load_stage = [&](int st, int kc) {
        uint32_t base = sb + st * G_STAGE;
        #pragma unroll
        for (int i = 0; i < 2; i++) {
            int r = ldr + 64 * i;
            uint32_t off = r * G_ROWB + ldg * 16;
            const __half* a0 = Ahi + (size_t)(m0 + r) * F_ + kc + ldg * 8;
            const __half* a1 = Alo + (size_t)(m0 + r) * F_ + kc + ldg * 8;
            const __half* b0 = Bt  + (size_t)(n0 + r) * F_ + kc + ldg * 8;
            CP_ASYNC16(base + off, a0);
            CP_ASYNC16(base + 10240 + off, a1);
            CP_ASYNC16(base + 20480 + off, b0);
        }
    };

    load_stage(0, 0);
    CP_COMMIT();

    for (int i = 0; i < NKC; i++) {
        if (i < NKC - 1) {
            load_stage((i + 1) & 1, (i + 1) * GBK32);
            CP_COMMIT();
            CP_WAIT1();
        } else {
            CP_WAIT0();
        }
        __syncthreads();

        uint32_t stA  = sb + (i & 1) * G_STAGE;
        uint32_t stAl = stA + 10240;
        uint32_t stB  = stA + 20480;
        #pragma unroll
        for (int ks = 0; ks < 2; ks++) {
            int k0 = ks * 16;
            uint32_t ah[2][4], al[2][4];
            #pragma unroll
            for (int mi = 0; mi < 2; mi++) {
                uint32_t ao = (mw + 16 * mi + a_row) * G_ROWB + (k0 + a_col) * 2;
                ldsm4(ah[mi], stA + ao);
                ldsm4(al[mi], stAl + ao);
            }
            #pragma unroll
            for (int ni = 0; ni < 4; ni++) {
                uint32_t bb[4];
                ldsm4(bb, stB + (nw + 16 * ni + b_row) * G_ROWB + (k0 + b_col) * 2);
                #pragma unroll
                for (int mi = 0; mi < 2; mi++) {
                    mma_f16(acc[mi][2 * ni + 0], ah[mi], bb[0], bb[1]);
                    mma_f16(acc[mi][2 * ni + 0], al[mi], bb[0], bb[1]);
                    mma_f16(acc[mi][2 * ni + 1], ah[mi], bb[2], bb[3]);
                    mma_f16(acc[mi][2 * ni + 1], al[mi], bb[2], bb[3]);
                }
            }
        }
        __syncthreads();
    }

    int gid = lane >> 2, tig = lane & 3;
    #pragma unroll
    for (int mi = 0; mi < 2; mi++) {
        #pragma unroll
        for (int nj = 0; nj < 8; nj++) {
            int row = m0 + mw + 16 * mi + gid;
            int col = n0 + nw + 8 * nj + 2 * tig;
            #pragma unroll
            for (int half_ = 0; half_ < 2; half_++) {
                int r = row + half_ * 8;
                int s = r & (S_ - 1);
                float v0 = acc[mi][nj][half_ * 2 + 0] + bias[col];
                float v1 = acc[mi][nj][half_ * 2 + 1] + bias[col + 1];
                if (pos) {
                    v0 += pos[(size_t)s * D_ + (col & (D_ - 1))];
                    v1 += pos[(size_t)s * D_ + ((col + 1) & (D_ - 1))];
                }
                if (res) {
                    v0 += res[(size_t)r * F_ + col];
                    v1 += res[(size_t)r * F_ + col + 1];
                }
                if (C)
                    *(float2*)&C[(size_t)r * F_ + col] = make_float2(v0, v1);
                if (Chi) {
                    __half h0, l0, h1, l1;
                    split_f32h(v0, h0, l0); split_f32h(v1, h1, l1);
                    *(__half2*)&Chi[(size_t)r * F_ + col] = __half2(h0, h1);
                    *(__half2*)&Clo[(size_t)r * F_ + col] = __half2(l0, l1);
                }
                if (Cs)
                    *(__half2*)&Cs[(size_t)r * F_ + col] = __floats2half2_rn(v0, v1);
            }
        }
    }
}

// fused Q/K/V projection: blockIdx.z selects weight/bias/output (all fp16 single)
__global__ __launch_bounds__(256, 2)
void gemm_qkv(const __half* __restrict__ Ahi, const __half* __restrict__ Alo,
              const __half* __restrict__ Wq, const __half* __restrict__ Wk,
              const __half* __restrict__ Wv,
              const float* __restrict__ bq, const float* __restrict__ bk,
              const float* __restrict__ bv, const float* __restrict__ pos,
              __half* __restrict__ qh,
              __half* __restrict__ kh, __half* __restrict__ vh) {
    extern __shared__ char smem[];
    int z = blockIdx.z;
    const __half* Bt = (z == 0) ? Wq : (z == 1) ? Wk : Wv;
    const float* bias = (z == 0) ? bq : (z == 1) ? bk : bv;
    const float* pp = (z == 1) ? pos : nullptr;
    __half* cs = (z == 0) ? qh : (z == 1) ? kh : vh;
    gemm_core(Ahi, Alo, Bt, bias, pp, nullptr, nullptr, nullptr, nullptr, cs,
              smem, blockIdx.y * 128, blockIdx.x * 128);
}

// single GEMM (output projection)
__global__ __launch_bounds__(256, 2)
void gemm_single(const __half* __restrict__ Ahi, const __half* __restrict__ Alo,
                 const __half* __restrict__ Bt, const float* __restrict__ bias,
                 const float* __restrict__ res, float* __restrict__ C) {
    extern __shared__ char smem[];
    gemm_core(Ahi, Alo, Bt, bias, nullptr, res, C, nullptr, nullptr, nullptr,
              smem, blockIdx.y * 128, blockIdx.x * 128);
}

// ---------------- Flash pass 1: rowsums + ctx (NO attn writes) -----------
// Single fp16 Q and P; K/V double-buffered via cp.async. Heavy-first order.
#define FKP 72
#define KV_STAGE (2 * 64 * FKP)   // halfs per stage (K + V)
#define FLASH_SMEM_BYTES ((128*FKP + 2*KV_STAGE) * 2)

__global__ __launch_bounds__(256, 2)
void flash_mma(const __half* __restrict__ qh_g,
               const __half* __restrict__ kh_g,
               const __half* __restrict__ vh_g,
               __half* __restrict__ ctxh, __half* __restrict__ ctxl,
               float* __restrict__ rs_g) {
    extern __shared__ __half fsm[];
    __half* sQh = fsm;                    // [128][FKP]
    __half* sKV = fsm + 128 * FKP;        // stage st: K, then V (64 rows each)

    int tid = threadIdx.x;
    int warp = tid >> 5, lane = tid & 31;
    int gid = lane >> 2, tig = lane & 3;
    int bh = blockIdx.y;
    int b = bh >> 4, h = bh & 15;
    int q0 = (gridDim.x - 1 - blockIdx.x) * 128;   // heavy tiles first

    #pragma unroll
    for (int i = 0; i < 4; i++) {
        int f = tid + 256 * i;
        int r = f >> 3, g = f & 7;
        size_t src = (size_t)(b * S_ + q0 + r) * F_ + h * D_ + g * 8;
        *(uint4*)&sQh[r * FKP + g * 8] = *(const uint4*)(qh_g + src);
    }
    __syncthreads();

    int a_row = lane & 15, a_col = (lane & 16) >> 1;
    int b_row = (lane & 7) + ((lane & 16) >> 1), b_col = lane & 8;
    uint32_t qfh[4][4];
    #pragma unroll
    for (int ks = 0; ks < 4; ks++)
        ldsm4(qfh[ks], smem_u32(&sQh[(16 * warp + a_row) * FKP + 16 * ks + a_col]));

    uint32_t kvb = smem_u32(sKV);
    auto load_kv = [&](int st, int jb) {
        uint32_t base = kvb + st * (KV_STAGE * 2);
        #pragma unroll
        for (int i = 0; i < 2; i++) {
            int f = tid + 256 * i;
            int r = f >> 3, g = f & 7;
            size_t src = (size_t)(b * S_ + jb + r) * F_ + h * D_ + g * 8;
            uint32_t off = (r * FKP + g * 8) * 2;
            CP_ASYNC16(base + off, kh_g + src);
            CP_ASYNC16(base + 64 * FKP * 2 + off, vh_g + src);
        }
    };

    float O[8][4];
    #pragma unroll
    for (int i = 0; i < 8; i++)
        #pragma unroll
        for (int c = 0; c < 4; c++) O[i][c] = 0.f;
    float ls0 = 0.f, ls1 = 0.f;

    int r0 = q0 + 16 * warp + gid;
    int r1 = r0 + 8;
    int niter = (q0 + 128) / 64;

    load_kv(0, 0);
    CP_COMMIT();

    for (int it = 0; it < niter; it++) {
        int jb = it * 64;
        if (it < niter - 1) {
            load_kv((it + 1) & 1, jb + 64);
            CP_COMMIT();
            CP_WAIT1();
        } else {
            CP_WAIT0();
        }
        __syncthreads();

        const __half* sKh = sKV + (it & 1) * KV_STAGE;
        const __half* sVh = sKh + 64 * FKP;

        float Sv[8][4];
        #pragma unroll
        for (int i = 0; i < 8; i++)
            Sv[i][0] = Sv[i][1] = Sv[i][2] = Sv[i][3] = 0.f;
        #pragma unroll
        for (int ks = 0; ks < 4; ks++) {
            #pragma unroll
            for (int ni = 0; ni < 4; ni++) {
                uint32_t kb[4];
                ldsm4(kb, smem_u32(&sKh[(16 * ni + b_row) * FKP + 16 * ks + b_col]));
                mma_f16(Sv[2 * ni + 0], qfh[ks], kb[0], kb[1]);
                mma_f16(Sv[2 * ni + 1], qfh[ks], kb[2], kb[3]);
            }
        }

        bool needmask = (jb + 63 > q0 + 16 * warp);
        #pragma unroll
        for (int nt = 0; nt < 8; nt++) {
            int c0 = jb + 8 * nt + 2 * tig;
            float e0 = fexp_dot(Sv[nt][0]);
            float e1 = fexp_dot(Sv[nt][1]);
            float e2 = fexp_dot(Sv[nt][2]);
            float e3 = fexp_dot(Sv[nt][3]);
            if (needmask) {
                if (c0 + 0 > r0) e0 = 0.f;
                if (c0 + 1 > r0) e1 = 0.f;
                if (c0 + 0 > r1) e2 = 0.f;
                if (c0 + 1 > r1) e3 = 0.f;
            }
            Sv[nt][0] = e0; Sv[nt][1] = e1; Sv[nt][2] = e2; Sv[nt][3] = e3;
            ls0 += e0 + e1;
            ls1 += e2 + e3;
        }

        // P @ V; single fp16 P
        #pragma unroll
        for (int kt = 0; kt < 4; kt++) {
            uint32_t pah[4];
            pah[0] = packh(Sv[2 * kt][0], Sv[2 * kt][1]);
            pah[1] = packh(Sv[2 * kt][2], Sv[2 * kt][3]);
            pah[2] = packh(Sv[2 * kt + 1][0], Sv[2 * kt + 1][1]);
            pah[3] = packh(Sv[2 * kt + 1][2], Sv[2 * kt + 1][3]);
            #pragma unroll
            for (int ni = 0; ni < 4; ni++) {
                uint32_t vb[4];
                ldsm4t(vb, smem_u32(&sVh[(16 * kt + (lane & 15)) * FKP
                                         + 16 * ni + ((lane & 16) >> 1)]));
                mma_f16(O[2 * ni + 0], pah, vb[0], vb[1]);
                mma_f16(O[2 * ni + 1], pah, vb[2], vb[3]);
            }
        }
        __syncthreads();
    }

    ls0 += __shfl_xor_sync(0xffffffffu, ls0, 1);
    ls0 += __shfl_xor_sync(0xffffffffu, ls0, 2);
    ls1 += __shfl_xor_sync(0xffffffffu, ls1, 1);
    ls1 += __shfl_xor_sync(0xffffffffu, ls1, 2);
    float rs0 = 1.0f / ls0, rs1 = 1.0f / ls1;
    if (tig == 0) {
        rs_g[bh * S_ + r0] = rs0;
        rs_g[bh * S_ + r1] = rs1;
    }

    #pragma unroll
    for (int nt = 0; nt < 8; nt++) {
        int col = h * D_ + 8 * nt + 2 * tig;
        float o0 = O[nt][0] * rs0, o1 = O[nt][1] * rs0;
        float o2 = O[nt][2] * rs1, o3 = O[nt][3] * rs1;
        __half h0, l0, h1, l1;
        split_f32h(o0, h0, l0); split_f32h(o1, h1, l1);
        *(__half2*)&ctxh[(size_t)(b * S_ + r0) * F_ + col] = __half2(h0, h1);
        *(__half2*)&ctxl[(size_t)(b * S_ + r0) * F_ + col] = __half2(l0, l1);
        split_f32h(o2, h0, l0); split_f32h(o3, h1, l1);
        *(__half2*)&ctxh[(size_t)(b * S_ + r1) * F_ + col] = __half2(h0, h1);
        *(__half2*)&ctxl[(size_t)(b * S_ + r1) * F_ + col] = __half2(l0, l1);
    }
}

// ---------------- Pass 2: recompute QK, write normalized attn once -------
// Single fp16 Q; K double-buffered. Heavy-first order; float4 zero-fill.
#define AW_SMEM_BYTES ((128*FKP + 2*64*FKP) * 2)

__global__ __launch_bounds__(256, 2)
void attn_write_mma(const __half* __restrict__ qh_g,
                    const __half* __restrict__ kh_g,
                    const float* __restrict__ rs_g,
                    float* __restrict__ attn) {
    extern __shared__ __half asm_[];
    __half* sQh = asm_;
    __half* sKst = asm_ + 128 * FKP;      // 2 stages of [64][FKP]

    int tid = threadIdx.x;
    int warp = tid >> 5, lane = tid & 31;
    int gid = lane >> 2, tig = lane & 3;
    int bh = blockIdx.y;
    int b = bh >> 4, h = bh & 15;
    int q0 = (gridDim.x - 1 - blockIdx.x) * 128;   // heavy tiles first

    #pragma unroll
    for (int i = 0; i < 4; i++) {
        int f = tid + 256 * i;
        int r = f >> 3, g = f & 7;
        size_t src = (size_t)(b * S_ + q0 + r) * F_ + h * D_ + g * 8;
        *(uint4*)&sQh[r * FKP + g * 8] = *(const uint4*)(qh_g + src);
    }
    __syncthreads();

    int a_row = lane & 15, a_col = (lane & 16) >> 1;
    int b_row = (lane & 7) + ((lane & 16) >> 1), b_col = lane & 8;
    uint32_t qfh[4][4];
    #pragma unroll
    for (int ks = 0; ks < 4; ks++)
        ldsm4(qfh[ks], smem_u32(&sQh[(16 * warp + a_row) * FKP + 16 * ks + a_col]));

    uint32_t kb0 = smem_u32(sKst);
    auto load_k = [&](int st, int jb) {
        uint32_t base = kb0 + st * (64 * FKP * 2);
        #pragma unroll
        for (int i = 0; i < 2; i++) {
            int f = tid + 256 * i;
            int r = f >> 3, g = f & 7;
            size_t src = (size_t)(b * S_ + jb + r) * F_ + h * D_ + g * 8;
            CP_ASYNC16(base + (r * FKP + g * 8) * 2, kh_g + src);
        }
    };

    int r0 = q0 + 16 * warp + gid;
    int r1 = r0 + 8;
    float rs0 = __ldg(&rs_g[bh * S_ + r0]);
    float rs1 = __ldg(&rs_g[bh * S_ + r1]);
    size_t arow0 = (size_t)(bh * S_ + r0) * S_;
    size_t arow1 = (size_t)(bh * S_ + r1) * S_;

    int ncaus = (q0 + 128) / 64;

    load_k(0, 0);
    CP_COMMIT();

    for (int it = 0; it < ncaus; it++) {
        int jb = it * 64;
        if (it < ncaus - 1) {
            load_k((it + 1) & 1, jb + 64);
            CP_COMMIT();
            CP_WAIT1();
        } else {
            CP_WAIT0();
        }
        __syncthreads();

        const __half* sKh = sKst + (it & 1) * 64 * FKP;

        float Sv[8][4];
        #pragma unroll
        for (int i = 0; i < 8; i++)
            Sv[i][0] = Sv[i][1] = Sv[i][2] = Sv[i][3] = 0.f;
        #pragma unroll
        for (int ks = 0; ks < 4; ks++) {
            #pragma unroll
            for (int ni = 0; ni < 4; ni++) {
                uint32_t kb[4];
                ldsm4(kb, smem_u32(&sKh[(16 * ni + b_row) * FKP + 16 * ks + b_col]));
                mma_f16(Sv[2 * ni + 0], qfh[ks], kb[0], kb[1]);
                mma_f16(Sv[2 * ni + 1], qfh[ks], kb[2], kb[3]);
            }
        }

        bool needmask = (jb + 63 > q0 + 16 * warp);
        #pragma unroll
        for (int nt = 0; nt < 8; nt++) {
            int c0 = jb + 8 * nt + 2 * tig;
            float e0 = fexp_dot(Sv[nt][0]) * rs0;
            float e1 = fexp_dot(Sv[nt][1]) * rs0;
            float e2 = fexp_dot(Sv[nt][2]) * rs1;
            float e3 = fexp_dot(Sv[nt][3]) * rs1;
            if (needmask) {
                if (c0 + 0 > r0) e0 = 0.f;
                if (c0 + 1 > r0) e1 = 0.f;
                if (c0 + 0 > r1) e2 = 0.f;
                if (c0 + 1 > r1) e3 = 0.f;
            }
            __stcs((float2*)&attn[arow0 + c0], make_float2(e0, e1));
            __stcs((float2*)&attn[arow1 + c0], make_float2(e2, e3));
        }
        __syncthreads();
    }

    // fully-masked region: stream zeros with float4 (16B per store)
    {
        int zstart = ncaus * 64;
        float4 z4 = make_float4(0.f, 0.f, 0.f, 0.f);
        for (int c = zstart + 4 * tig; c < S_; c += 16) {
            __stcs((float4*)&attn[arow0 + c], z4);
            __stcs((float4*)&attn[arow1 + c], z4);
        }
    }
}

// ---------------- launch ----------------
extern "C" void kernel_launch(void* const* d_in, const int* in_sizes, int n_in,
                              void* d_out, int out_size) {
    const float* x      = (const float*)d_in[0];
    const float* Wq     = (const float*)d_in[1];
    const float* bq     = (const float*)d_in[2];
    const float* Wk     = (const float*)d_in[3];
    const float* bk     = (const float*)d_in[4];
    const float* Wv     = (const float*)d_in[5];
    const float* bv     = (const float*)d_in[6];
    const float* Wo     = (const float*)d_in[7];
    const float* bo     = (const float*)d_in[8];
    const float* gamma1 = (const float*)d_in[9];
    const float* beta1  = (const float*)d_in[10];
    const float* gamma2 = (const float*)d_in[11];
    const float* beta2  = (const float*)d_in[12];
    const float* pos    = (const float*)d_in[13];

    float* out = (float*)d_out;

    float *xn, *tmp, *rs, *attn_fb;
    cudaGetSymbolAddress((void**)&xn, g_xn);
    cudaGetSymbolAddress((void**)&tmp, g_tmp);
    cudaGetSymbolAddress((void**)&rs, g_rs);
    cudaGetSymbolAddress((void**)&attn_fb, g_attn_fallback);

    __half *xnh, *xnl, *qh, *kh, *vh, *ctxh, *ctxl;
    __half *wqt, *wkt, *wvt, *wot;
    cudaGetSymbolAddress((void**)&xnh, g_xn_hi);
    cudaGetSymbolAddress((void**)&xnl, g_xn_lo);
    cudaGetSymbolAddress((void**)&qh, g_qh);
    cudaGetSymbolAddress((void**)&kh, g_kh);
    cudaGetSymbolAddress((void**)&vh, g_vh);
    cudaGetSymbolAddress((void**)&ctxh, g_ctx_hi);
    cudaGetSymbolAddress((void**)&ctxl, g_ctx_lo);
    cudaGetSymbolAddress((void**)&wqt, g_WqT);
    cudaGetSymbolAddress((void**)&wkt, g_WkT);
    cudaGetSymbolAddress((void**)&wvt, g_WvT);
    cudaGetSymbolAddress((void**)&wot, g_WoT);

    float* attn = (out_size > OUT_ELEMS) ? (out + OUT_ELEMS) : attn_fb;

    // one-time side stream + events
    static cudaStream_t s2 = nullptr;
    static cudaEvent_t e_fork = nullptr, e_join = nullptr;
    static cudaEvent_t e_t0 = nullptr, e_t1 = nullptr;
    if (!s2) {
        cudaStreamCreateWithFlags(&s2, cudaStreamNonBlocking);
        cudaEventCreateWithFlags(&e_fork, cudaEventDisableTiming);
        cudaEventCreateWithFlags(&e_join, cudaEventDisableTiming);
        cudaEventCreateWithFlags(&e_t0, cudaEventDisableTiming);
        cudaEventCreateWithFlags(&e_t1, cudaEventDisableTiming);
    }

    cudaFuncSetAttribute(flash_mma, cudaFuncAttributeMaxDynamicSharedMemorySize,
                         FLASH_SMEM_BYTES);
    cudaFuncSetAttribute(attn_write_mma, cudaFuncAttributeMaxDynamicSharedMemorySize,
                         AW_SMEM_BYTES);
    cudaFuncSetAttribute(gemm_qkv, cudaFuncAttributeMaxDynamicSharedMemorySize,
                         GEMM_SMEM_BYTES);
    cudaFuncSetAttribute(gemm_single, cudaFuncAttributeMaxDynamicSharedMemorySize,
                         GEMM_SMEM_BYTES);

    // 1) transposes on side stream, LN1 on main (independent); join before QKV
    cudaEventRecord(e_t0, 0);
    cudaStreamWaitEvent(s2, e_t0, 0);
    dim3 tb(32, 8), tg(F_ / 32, F_ / 32, 4);
    transpose_all_kernel<<<tg, tb, 0, s2>>>(Wq, wqt, Wk, wkt, Wv, wvt, Wo, wot);
    cudaEventRecord(e_t1, s2);
    ln_kernel<<<M_, 256>>>(x, gamma1, beta1, xn, xnh, xnl);
    cudaStreamWaitEvent(0, e_t1, 0);

    // 2) fused Q/K/V projections
    dim3 qkvgrid(F_ / 128, M_ / 128, 3);
    gemm_qkv<<<qkvgrid, 256, GEMM_SMEM_BYTES>>>(xnh, xnl, wqt, wkt, wvt,
                                                bq, bk, bv, pos,
                                                qh, kh, vh);

    // 3) flash pass 1: rowsums + ctx
    dim3 fgrid(S_ / 128, BH_);
    flash_mma<<<fgrid, 256, FLASH_SMEM_BYTES>>>(qh, kh, vh, ctxh, ctxl, rs);

    // 4) fork: attn_write on side stream, overlapping gemm_single + LN2
    cudaEventRecord(e_fork, 0);
    cudaStreamWaitEvent(s2, e_fork, 0);
    attn_write_mma<<<fgrid, 256, AW_SMEM_BYTES, s2>>>(qh, kh, rs, attn);
    cudaEventRecord(e_join, s2);

    // 5) output projection + residual -> fp32 tmp (main stream)
    dim3 ggrid(F_ / 128, M_ / 128);
    gemm_single<<<ggrid, 256, GEMM_SMEM_BYTES>>>(ctxh, ctxl, wot, bo, xn, tmp);

    // 6) LN2 (main stream), then join side stream
    ln_kernel<<<M_, 256>>>(tmp, gamma2, beta2, out, nullptr, nullptr);
    cudaStreamWaitEvent(0, e_join, 0);
}

// round 17
// speedup vs baseline: 2.0641x; 1.0395x over previous
#include <cuda_runtime.h>
#include <cuda_fp16.h>
#include <cstdint>
#include <math.h>

// Problem constants
#define B_  2
#define S_  2048
#define F_  1024
#define H_  16
#define D_  64
#define M_  (B_ * S_)          // 4096 rows
#define BH_ (B_ * H_)          // 32
#define OUT_ELEMS (M_ * F_)    // 4194304
#define ATTN_ELEMS ((size_t)BH_ * S_ * S_)  // 134217728

// ---------------- device scratch (no allocations allowed) ----------------
__device__ float g_xn[OUT_ELEMS];
__device__ float g_tmp[OUT_ELEMS];
__device__ float g_rs[BH_ * S_];
__device__ float g_attn_fallback[ATTN_ELEMS];

__device__ __half g_xn_hi[OUT_ELEMS];
__device__ __half g_xn_lo[OUT_ELEMS];
__device__ __half g_qh[OUT_ELEMS];
__device__ __half g_kh[OUT_ELEMS];
__device__ __half g_vh[OUT_ELEMS];
__device__ __half g_ctx_hi[OUT_ELEMS];
__device__ __half g_ctx_lo[OUT_ELEMS];
__device__ __half g_WqT[F_ * F_];
__device__ __half g_WkT[F_ * F_];
__device__ __half g_WvT[F_ * F_];
__device__ __half g_WoT[F_ * F_];

// ---------------- helpers ----------------
__device__ __forceinline__ uint32_t smem_u32(const void* p) {
    uint32_t a;
    asm("{ .reg .u64 t; cvta.to.shared.u64 t, %1; cvt.u32.u64 %0, t; }"
        : "=r"(a) : "l"(p));
    return a;
}
__device__ __forceinline__ void ldsm4(uint32_t* r, uint32_t addr) {
    asm volatile("ldmatrix.sync.aligned.m8n8.x4.shared.b16 {%0,%1,%2,%3}, [%4];"
                 : "=r"(r[0]), "=r"(r[1]), "=r"(r[2]), "=r"(r[3]) : "r"(addr));
}
__device__ __forceinline__ void ldsm4t(uint32_t* r, uint32_t addr) {
    asm volatile("ldmatrix.sync.aligned.m8n8.x4.trans.shared.b16 {%0,%1,%2,%3}, [%4];"
                 : "=r"(r[0]), "=r"(r[1]), "=r"(r[2]), "=r"(r[3]) : "r"(addr));
}
__device__ __forceinline__ void mma_f16(float* c, const uint32_t* a,
                                        uint32_t b0, uint32_t b1) {
    asm volatile("mma.sync.aligned.m16n8k16.row.col.f32.f16.f16.f32 "
                 "{%0,%1,%2,%3}, {%4,%5,%6,%7}, {%8,%9}, {%0,%1,%2,%3};"
                 : "+f"(c[0]), "+f"(c[1]), "+f"(c[2]), "+f"(c[3])
                 : "r"(a[0]), "r"(a[1]), "r"(a[2]), "r"(a[3]), "r"(b0), "r"(b1));
}
#define CP_ASYNC16(dst, src) \
    asm volatile("cp.async.cg.shared.global [%0], [%1], 16;" :: "r"(dst), "l"(src))
#define CP_COMMIT() asm volatile("cp.async.commit_group;")
#define CP_WAIT1() asm volatile("cp.async.wait_group 1;")
#define CP_WAIT0() asm volatile("cp.async.wait_group 0;")

__device__ __forceinline__ void split_f32h(float a, __half& hi, __half& lo) {
    hi = __float2half_rn(a);
    lo = __float2half_rn(a - __half2float(hi));
}
// exp(s*0.125) via FMA-pipe exp2 (no MUFU).
#define EXP_C1 0.18033688011112042f   // 0.125 * log2(e)
__device__ __forceinline__ float fexp_dot(float dot) {
    float y = dot * EXP_C1;
    y = fminf(fmaxf(y, -126.f), 126.f);
    float t = y + 12582912.f;
    int e = (__float_as_int(t) - 0x4B400000) << 23;
    float f = y - (t - 12582912.f);
    float p = 0.00133335581f;
    p = fmaf(p, f, 0.00961812910f);
    p = fmaf(p, f, 0.0555041086f);
    p = fmaf(p, f, 0.240226507f);
    p = fmaf(p, f, 0.693147182f);
    p = fmaf(p, f, 1.0f);
    return __int_as_float(__float_as_int(p) + e);
}
__device__ __forceinline__ uint32_t packh(float a, float b) {
    __half2 h = __floats2half2_rn(a, b);
    return *(uint32_t*)&h;
}

// ---------------- LayerNorm (optional fp16 hi/lo split outputs) ----------
__global__ void ln_kernel(const float* __restrict__ x,
                          const float* __restrict__ gamma,
                          const float* __restrict__ beta,
                          float* __restrict__ out,
                          __half* __restrict__ hi,
                          __half* __restrict__ lo) {
    __shared__ float sred[8];
    int row = blockIdx.x;
    int t = threadIdx.x;
    const float4* xr = (const float4*)(x + (size_t)row * F_);
    float4 v = xr[t];

    float s = v.x + v.y + v.z + v.w;
    #pragma unroll
    for (int o = 16; o; o >>= 1) s += __shfl_xor_sync(0xffffffffu, s, o);
    if ((t & 31) == 0) sred[t >> 5] = s;
    __syncthreads();
    float tot = 0.f;
    #pragma unroll
    for (int i = 0; i < 8; i++) tot += sred[i];
    float mean = tot * (1.0f / F_);
    __syncthreads();

    float dx = v.x - mean, dy = v.y - mean, dz = v.z - mean, dw = v.w - mean;
    float ss = dx*dx + dy*dy + dz*dz + dw*dw;
    #pragma unroll
    for (int o = 16; o; o >>= 1) ss += __shfl_xor_sync(0xffffffffu, ss, o);
    if ((t & 31) == 0) sred[t >> 5] = ss;
    __syncthreads();
    float tot2 = 0.f;
    #pragma unroll
    for (int i = 0; i < 8; i++) tot2 += sred[i];
    float rstd = rsqrtf(tot2 * (1.0f / F_) + 1e-6f);

    float4 g4 = ((const float4*)gamma)[t];
    float4 b4 = ((const float4*)beta)[t];
    float4 o4;
    o4.x = dx * rstd * g4.x + b4.x;
    o4.y = dy * rstd * g4.y + b4.y;
    o4.z = dz * rstd * g4.z + b4.z;
    o4.w = dw * rstd * g4.w + b4.w;
    ((float4*)(out + (size_t)row * F_))[t] = o4;
    if (hi) {
        __half h0, l0, h1, l1, h2, l2, h3, l3;
        split_f32h(o4.x, h0, l0); split_f32h(o4.y, h1, l1);
        split_f32h(o4.z, h2, l2); split_f32h(o4.w, h3, l3);
        size_t base = (size_t)row * F_ + 4 * t;
        *(__half2*)&hi[base]     = __half2(h0, h1);
        *(__half2*)&hi[base + 2] = __half2(h2, h3);
        *(__half2*)&lo[base]     = __half2(l0, l1);
        *(__half2*)&lo[base + 2] = __half2(l2, l3);
    }
}

// ---------------- fused transpose: 4 weights -> fp16 T ------------------
__global__ void transpose_all_kernel(const float* __restrict__ W0, __half* __restrict__ T0,
                                     const float* __restrict__ W1, __half* __restrict__ T1,
                                     const float* __restrict__ W2, __half* __restrict__ T2,
                                     const float* __restrict__ W3, __half* __restrict__ T3) {
    const float* W = (blockIdx.z == 0) ? W0 : (blockIdx.z == 1) ? W1
                   : (blockIdx.z == 2) ? W2 : W3;
    __half* T = (blockIdx.z == 0) ? T0 : (blockIdx.z == 1) ? T1
              : (blockIdx.z == 2) ? T2 : T3;
    __shared__ float t[32][33];
    int bx = blockIdx.x * 32;  // n
    int by = blockIdx.y * 32;  // k
    int tx = threadIdx.x, ty = threadIdx.y;
    #pragma unroll
    for (int i = 0; i < 4; i++)
        t[ty + 8 * i][tx] = W[(size_t)(by + ty + 8 * i) * F_ + bx + tx];
    __syncthreads();
    #pragma unroll
    for (int i = 0; i < 4; i++) {
        float v = t[tx][ty + 8 * i];
        T[(size_t)(bx + ty + 8 * i) * F_ + by + tx] = __float2half_rn(v);
    }
}

// ---------------- attn zero-fill: masked triangle, no inputs needed ------
__global__ void attn_zero_kernel(float* __restrict__ attn) {
    int band = blockIdx.x;          // 0..14 (band 15 has no zero cols)
    int bh = blockIdx.y;
    int z0 = (band + 1) * 128;
    int zn = S_ - z0;
    float4 z4 = make_float4(0.f, 0.f, 0.f, 0.f);
    for (int r = 0; r < 128; r++) {
        size_t rowb = ((size_t)bh * S_ + band * 128 + r) * S_ + z0;
        for (int c = threadIdx.x * 4; c < zn; c += 1024)
            __stcs((float4*)&attn[rowb + c], z4);
    }
}

// ---------------- GEMM core: cp.async 2-stage pipelined mma, BK=64 -------
#define GBK 64
#define NKC (F_ / GBK)       // 16 chunks
#define G_ROWB 144           // 72 halfs per row (64 data + 8 pad)
#define G_MATB (128 * G_ROWB)          // 18432 bytes per matrix
#define G_STAGE (3 * G_MATB)           // 55296 bytes
#define GEMM_SMEM_BYTES (2 * G_STAGE)  // 110592 bytes

__device__ __forceinline__ void gemm_core(
        const __half* __restrict__ Ahi, const __half* __restrict__ Alo,
        const __half* __restrict__ Bt,
        const float* __restrict__ bias,
        const float* __restrict__ pos, const float* __restrict__ res,
        float* __restrict__ C, __half* __restrict__ Chi,
        __half* __restrict__ Clo, __half* __restrict__ Cs,
        char* smem, int m0, int n0) {
    uint32_t sb = smem_u32(smem);
    int tid = threadIdx.x;
    int warp = tid >> 5, lane = tid & 31;
    int mw = (warp >> 1) * 32;
    int nw = (warp & 1) * 64;

    float acc[2][8][4];
    #pragma unroll
    for (int i = 0; i < 2; i++)
        #pragma unroll
        for (int j = 0; j < 8; j++)
            #pragma unroll
            for (int c = 0; c < 4; c++) acc[i][j][c] = 0.f;

    int a_row = (lane & 15);
    int a_col = (lane & 16) >> 1;
    int b_row = (lane & 7) + ((lane & 16) >> 1);
    int b_col = (lane & 8);

    auto load_stage = [&](int st, int kc) {
        uint32_t base = sb + st * G_STAGE;
        #pragma unroll
        for (int i = 0; i < 4; i++) {
            int f = tid + 256 * i;
            int r = f >> 3, g = f & 7;
            uint32_t off = r * G_ROWB + g * 16;
            const __half* a0 = Ahi + (size_t)(m0 + r) * F_ + kc + g * 8;
            const __half* a1 = Alo + (size_t)(m0 + r) * F_ + kc + g * 8;
            const __half* b0 = Bt  + (size_t)(n0 + r) * F_ + kc + g * 8;
            CP_ASYNC16(base + off, a0);
            CP_ASYNC16(base + G_MATB + off, a1);
            CP_ASYNC16(base + 2 * G_MATB + off, b0);
        }
    };

    load_stage(0, 0);
    CP_COMMIT();

    for (int i = 0; i < NKC; i++) {
        if (i < NKC - 1) {
            load_stage((i + 1) & 1, (i + 1) * GBK);
            CP_COMMIT();
            CP_WAIT1();
        } else {
            CP_WAIT0();
        }
        __syncthreads();

        uint32_t stA  = sb + (i & 1) * G_STAGE;
        uint32_t stAl = stA + G_MATB;
        uint32_t stB  = stA + 2 * G_MATB;
        #pragma unroll
        for (int ks = 0; ks < 4; ks++) {
            int k0 = ks * 16;
            uint32_t ah[2][4], al[2][4];
            #pragma unroll
            for (int mi = 0; mi < 2; mi++) {
                uint32_t ao = (mw + 16 * mi + a_row) * G_ROWB + (k0 + a_col) * 2;
                ldsm4(ah[mi], stA + ao);
                ldsm4(al[mi], stAl + ao);
            }
            #pragma unroll
            for (int ni = 0; ni < 4; ni++) {
                uint32_t bb[4];
                ldsm4(bb, stB + (nw + 16 * ni + b_row) * G_ROWB + (k0 + b_col) * 2);
                #pragma unroll
                for (int mi = 0; mi < 2; mi++) {
                    mma_f16(acc[mi][2 * ni + 0], ah[mi], bb[0], bb[1]);
                    mma_f16(acc[mi][2 * ni + 0], al[mi], bb[0], bb[1]);
                    mma_f16(acc[mi][2 * ni + 1], ah[mi], bb[2], bb[3]);
                    mma_f16(acc[mi][2 * ni + 1], al[mi], bb[2], bb[3]);
                }
            }
        }
        __syncthreads();
    }

    int gid = lane >> 2, tig = lane & 3;
    #pragma unroll
    for (int mi = 0; mi < 2; mi++) {
        #pragma unroll
        for (int nj = 0; nj < 8; nj++) {
            int row = m0 + mw + 16 * mi + gid;
            int col = n0 + nw + 8 * nj + 2 * tig;
            #pragma unroll
            for (int half_ = 0; half_ < 2; half_++) {
                int r = row + half_ * 8;
                int s = r & (S_ - 1);
                float v0 = acc[mi][nj][half_ * 2 + 0] + bias[col];
                float v1 = acc[mi][nj][half_ * 2 + 1] + bias[col + 1];
                if (pos) {
                    v0 += pos[(size_t)s * D_ + (col & (D_ - 1))];
                    v1 += pos[(size_t)s * D_ + ((col + 1) & (D_ - 1))];
                }
                if (res) {
                    v0 += res[(size_t)r * F_ + col];
                    v1 += res[(size_t)r * F_ + col + 1];
                }
                if (C)
                    *(float2*)&C[(size_t)r * F_ + col] = make_float2(v0, v1);
                if (Chi) {
                    __half h0, l0, h1, l1;
                    split_f32h(v0, h0, l0); split_f32h(v1, h1, l1);
                    *(__half2*)&Chi[(size_t)r * F_ + col] = __half2(h0, h1);
                    *(__half2*)&Clo[(size_t)r * F_ + col] = __half2(l0, l1);
                }
                if (Cs)
                    *(__half2*)&Cs[(size_t)r * F_ + col] = __floats2half2_rn(v0, v1);
            }
        }
    }
}

// fused Q/K/V projection: blockIdx.z selects weight/bias/output (all fp16 single)
__global__ __launch_bounds__(256, 2)
void gemm_qkv(const __half* __restrict__ Ahi, const __half* __restrict__ Alo,
              const __half* __restrict__ Wq, const __half* __restrict__ Wk,
              const __half* __restrict__ Wv,
              const float* __restrict__ bq, const float* __restrict__ bk,
              const float* __restrict__ bv, const float* __restrict__ pos,
              __half* __restrict__ qh,
              __half* __restrict__ kh, __half* __restrict__ vh) {
    extern __shared__ char smem[];
    int z = blockIdx.z;
    const __half* Bt = (z == 0) ? Wq : (z == 1) ? Wk : Wv;
    const float* bias = (z == 0) ? bq : (z == 1) ? bk : bv;
    const float* pp = (z == 1) ? pos : nullptr;
    __half* cs = (z == 0) ? qh : (z == 1) ? kh : vh;
    gemm_core(Ahi, Alo, Bt, bias, pp, nullptr, nullptr, nullptr, nullptr, cs,
              smem, blockIdx.y * 128, blockIdx.x * 128);
}

// single GEMM (output projection)
__global__ __launch_bounds__(256, 2)
void gemm_single(const __half* __restrict__ Ahi, const __half* __restrict__ Alo,
                 const __half* __restrict__ Bt, const float* __restrict__ bias,
                 const float* __restrict__ res, float* __restrict__ C) {
    extern __shared__ char smem[];
    gemm_core(Ahi, Alo, Bt, bias, nullptr, res, C, nullptr, nullptr, nullptr,
              smem, blockIdx.y * 128, blockIdx.x * 128);
}

// ---------------- Flash pass 1: rowsums + ctx (NO attn writes) -----------
#define FKP 72
#define KV_STAGE (2 * 64 * FKP)   // halfs per stage (K + V)
#define FLASH_SMEM_BYTES ((128*FKP + 2*KV_STAGE) * 2)

__global__ __launch_bounds__(256, 2)
void flash_mma(const __half* __restrict__ qh_g,
               const __half* __restrict__ kh_g,
               const __half* __restrict__ vh_g,
               __half* __restrict__ ctxh, __half* __restrict__ ctxl,
               float* __restrict__ rs_g) {
    extern __shared__ __half fsm[];
    __half* sQh = fsm;                    // [128][FKP]
    __half* sKV = fsm + 128 * FKP;        // stage st: K, then V (64 rows each)

    int tid = threadIdx.x;
    int warp = tid >> 5, lane = tid & 31;
    int gid = lane >> 2, tig = lane & 3;
    int bh = blockIdx.y;
    int b = bh >> 4, h = bh & 15;
    int q0 = (gridDim.x - 1 - blockIdx.x) * 128;   // heavy tiles first

    #pragma unroll
    for (int i = 0; i < 4; i++) {
        int f = tid + 256 * i;
        int r = f >> 3, g = f & 7;
        size_t src = (size_t)(b * S_ + q0 + r) * F_ + h * D_ + g * 8;
        *(uint4*)&sQh[r * FKP + g * 8] = *(const uint4*)(qh_g + src);
    }
    __syncthreads();

    int a_row = lane & 15, a_col = (lane & 16) >> 1;
    int b_row = (lane & 7) + ((lane & 16) >> 1), b_col = lane & 8;
    uint32_t qfh[4][4];
    #pragma unroll
    for (int ks = 0; ks < 4; ks++)
        ldsm4(qfh[ks], smem_u32(&sQh[(16 * warp + a_row) * FKP + 16 * ks + a_col]));

    uint32_t kvb = smem_u32(sKV);
    auto load_kv = [&](int st, int jb) {
        uint32_t base = kvb + st * (KV_STAGE * 2);
        #pragma unroll
        for (int i = 0; i < 2; i++) {
            int f = tid + 256 * i;
            int r = f >> 3, g = f & 7;
            size_t src = (size_t)(b * S_ + jb + r) * F_ + h * D_ + g * 8;
            uint32_t off = (r * FKP + g * 8) * 2;
            CP_ASYNC16(base + off, kh_g + src);
            CP_ASYNC16(base + 64 * FKP * 2 + off, vh_g + src);
        }
    };

    float O[8][4];
    #pragma unroll
    for (int i = 0; i < 8; i++)
        #pragma unroll
        for (int c = 0; c < 4; c++) O[i][c] = 0.f;
    float ls0 = 0.f, ls1 = 0.f;

    int r0 = q0 + 16 * warp + gid;
    int r1 = r0 + 8;
    int niter = (q0 + 128) / 64;

    load_kv(0, 0);
    CP_COMMIT();

    for (int it = 0; it < niter; it++) {
        int jb = it * 64;
        if (it < niter - 1) {
            load_kv((it + 1) & 1, jb + 64);
            CP_COMMIT();
            CP_WAIT1();
        } else {
            CP_WAIT0();
        }
        __syncthreads();

        const __half* sKh = sKV + (it & 1) * KV_STAGE;
        const __half* sVh = sKh + 64 * FKP;

        float Sv[8][4];
        #pragma unroll
        for (int i = 0; i < 8; i++)
            Sv[i][0] = Sv[i][1] = Sv[i][2] = Sv[i][3] = 0.f;
        #pragma unroll
        for (int ks = 0; ks < 4; ks++) {
            #pragma unroll
            for (int ni = 0; ni < 4; ni++) {
                uint32_t kb[4];
                ldsm4(kb, smem_u32(&sKh[(16 * ni + b_row) * FKP + 16 * ks + b_col]));
                mma_f16(Sv[2 * ni + 0], qfh[ks], kb[0], kb[1]);
                mma_f16(Sv[2 * ni + 1], qfh[ks], kb[2], kb[3]);
            }
        }

        bool needmask = (jb + 63 > q0 + 16 * warp);
        #pragma unroll
        for (int nt = 0; nt < 8; nt++) {
            int c0 = jb + 8 * nt + 2 * tig;
            float e0 = fexp_dot(Sv[nt][0]);
            float e1 = fexp_dot(Sv[nt][1]);
            float e2 = fexp_dot(Sv[nt][2]);
            float e3 = fexp_dot(Sv[nt][3]);
            if (needmask) {
                if (c0 + 0 > r0) e0 = 0.f;
                if (c0 + 1 > r0) e1 = 0.f;
                if (c0 + 0 > r1) e2 = 0.f;
                if (c0 + 1 > r1) e3 = 0.f;
            }
            Sv[nt][0] = e0; Sv[nt][1] = e1; Sv[nt][2] = e2; Sv[nt][3] = e3;
            ls0 += e0 + e1;
            ls1 += e2 + e3;
        }

        // P @ V; single fp16 P
        #pragma unroll
        for (int kt = 0; kt < 4; kt++) {
            uint32_t pah[4];
            pah[0] = packh(Sv[2 * kt][0], Sv[2 * kt][1]);
            pah[1] = packh(Sv[2 * kt][2], Sv[2 * kt][3]);
            pah[2] = packh(Sv[2 * kt + 1][0], Sv[2 * kt + 1][1]);
            pah[3] = packh(Sv[2 * kt + 1][2], Sv[2 * kt + 1][3]);
            #pragma unroll
            for (int ni = 0; ni < 4; ni++) {
                uint32_t vb[4];
                ldsm4t(vb, smem_u32(&sVh[(16 * kt + (lane & 15)) * FKP
                                         + 16 * ni + ((lane & 16) >> 1)]));
                mma_f16(O[2 * ni + 0], pah, vb[0], vb[1]);
                mma_f16(O[2 * ni + 1], pah, vb[2], vb[3]);
            }
        }
        __syncthreads();
    }

    ls0 += __shfl_xor_sync(0xffffffffu, ls0, 1);
    ls0 += __shfl_xor_sync(0xffffffffu, ls0, 2);
    ls1 += __shfl_xor_sync(0xffffffffu, ls1, 1);
    ls1 += __shfl_xor_sync(0xffffffffu, ls1, 2);
    float rs0 = 1.0f / ls0, rs1 = 1.0f / ls1;
    if (tig == 0) {
        rs_g[bh * S_ + r0] = rs0;
        rs_g[bh * S_ + r1] = rs1;
    }

    #pragma unroll
    for (int nt = 0; nt < 8; nt++) {
        int col = h * D_ + 8 * nt + 2 * tig;
        float o0 = O[nt][0] * rs0, o1 = O[nt][1] * rs0;
        float o2 = O[nt][2] * rs1, o3 = O[nt][3] * rs1;
        __half h0, l0, h1, l1;
        split_f32h(o0, h0, l0); split_f32h(o1, h1, l1);
        *(__half2*)&ctxh[(size_t)(b * S_ + r0) * F_ + col] = __half2(h0, h1);
        *(__half2*)&ctxl[(size_t)(b * S_ + r0) * F_ + col] = __half2(l0, l1);
        split_f32h(o2, h0, l0); split_f32h(o3, h1, l1);
        *(__half2*)&ctxh[(size_t)(b * S_ + r1) * F_ + col] = __half2(h0, h1);
        *(__half2*)&ctxl[(size_t)(b * S_ + r1) * F_ + col] = __half2(l0, l1);
    }
}

// ---------------- Pass 2: recompute QK, write normalized attn (causal) ---
// Zero triangle handled by attn_zero_kernel.
#define AW_SMEM_BYTES ((128*FKP + 2*64*FKP) * 2)

__global__ __launch_bounds__(256, 2)
void attn_write_mma(const __half* __restrict__ qh_g,
                    const __half* __restrict__ kh_g,
                    const float* __restrict__ rs_g,
                    float* __restrict__ attn) {
    extern __shared__ __half asm_[];
    __half* sQh = asm_;
    __half* sKst = asm_ + 128 * FKP;      // 2 stages of [64][FKP]

    int tid = threadIdx.x;
    int warp = tid >> 5, lane = tid & 31;
    int gid = lane >> 2, tig = lane & 3;
    int bh = blockIdx.y;
    int b = bh >> 4, h = bh & 15;
    int q0 = (gridDim.x - 1 - blockIdx.x) * 128;   // heavy tiles first

    #pragma unroll
    for (int i = 0; i < 4; i++) {
        int f = tid + 256 * i;
        int r = f >> 3, g = f & 7;
        size_t src = (size_t)(b * S_ + q0 + r) * F_ + h * D_ + g * 8;
        *(uint4*)&sQh[r * FKP + g * 8] = *(const uint4*)(qh_g + src);
    }
    __syncthreads();

    int a_row = lane & 15, a_col = (lane & 16) >> 1;
    int b_row = (lane & 7) + ((lane & 16) >> 1), b_col = lane & 8;
    uint32_t qfh[4][4];
    #pragma unroll
    for (int ks = 0; ks < 4; ks++)
        ldsm4(qfh[ks], smem_u32(&sQh[(16 * warp + a_row) * FKP + 16 * ks + a_col]));

    uint32_t kb0 = smem_u32(sKst);
    auto load_k = [&](int st, int jb) {
        uint32_t base = kb0 + st * (64 * FKP * 2);
        #pragma unroll
        for (int i = 0; i < 2; i++) {
            int f = tid + 256 * i;
            int r = f >> 3, g = f & 7;
            size_t src = (size_t)(b * S_ + jb + r) * F_ + h * D_ + g * 8;
            CP_ASYNC16(base + (r * FKP + g * 8) * 2, kh_g + src);
        }
    };

    int r0 = q0 + 16 * warp + gid;
    int r1 = r0 + 8;
    float rs0 = __ldg(&rs_g[bh * S_ + r0]);
    float rs1 = __ldg(&rs_g[bh * S_ + r1]);
    size_t arow0 = (size_t)(bh * S_ + r0) * S_;
    size_t arow1 = (size_t)(bh * S_ + r1) * S_;

    int ncaus = (q0 + 128) / 64;

    load_k(0, 0);
    CP_COMMIT();

    for (int it = 0; it < ncaus; it++) {
        int jb = it * 64;
        if (it < ncaus - 1) {
            load_k((it + 1) & 1, jb + 64);
            CP_COMMIT();
            CP_WAIT1();
        } else {
            CP_WAIT0();
        }
        __syncthreads();

        const __half* sKh = sKst + (it & 1) * 64 * FKP;

        float Sv[8][4];
        #pragma unroll
        for (int i = 0; i < 8; i++)
            Sv[i][0] = Sv[i][1] = Sv[i][2] = Sv[i][3] = 0.f;
        #pragma unroll
        for (int ks = 0; ks < 4; ks++) {
            #pragma unroll
            for (int ni = 0; ni < 4; ni++) {
                uint32_t kb[4];
                ldsm4(kb, smem_u32(&sKh[(16 * ni + b_row) * FKP + 16 * ks + b_col]));
                mma_f16(Sv[2 * ni + 0], qfh[ks], kb[0], kb[1]);
                mma_f16(Sv[2 * ni + 1], qfh[ks], kb[2], kb[3]);
            }
        }

        bool needmask = (jb + 63 > q0 + 16 * warp);
        #pragma unroll
        for (int nt = 0; nt < 8; nt++) {
            int c0 = jb + 8 * nt + 2 * tig;
            float e0 = fexp_dot(Sv[nt][0]) * rs0;
            float e1 = fexp_dot(Sv[nt][1]) * rs0;
            float e2 = fexp_dot(Sv[nt][2]) * rs1;
            float e3 = fexp_dot(Sv[nt][3]) * rs1;
            if (needmask) {
                if (c0 + 0 > r0) e0 = 0.f;
                if (c0 + 1 > r0) e1 = 0.f;
                if (c0 + 0 > r1) e2 = 0.f;
                if (c0 + 1 > r1) e3 = 0.f;
            }
            __stcs((float2*)&attn[arow0 + c0], make_float2(e0, e1));
            __stcs((float2*)&attn[arow1 + c0], make_float2(e2, e3));
        }
        __syncthreads();
    }
}

// ---------------- launch ----------------
extern "C" void kernel_launch(void* const* d_in, const int* in_sizes, int n_in,
                              void* d_out, int out_size) {
    const float* x      = (const float*)d_in[0];
    const float* Wq     = (const float*)d_in[1];
    const float* bq     = (const float*)d_in[2];
    const float* Wk     = (const float*)d_in[3];
    const float* bk     = (const float*)d_in[4];
    const float* Wv     = (const float*)d_in[5];
    const float* bv     = (const float*)d_in[6];
    const float* Wo     = (const float*)d_in[7];
    const float* bo     = (const float*)d_in[8];
    const float* gamma1 = (const float*)d_in[9];
    const float* beta1  = (const float*)d_in[10];
    const float* gamma2 = (const float*)d_in[11];
    const float* beta2  = (const float*)d_in[12];
    const float* pos    = (const float*)d_in[13];

    float* out = (float*)d_out;

    float *xn, *tmp, *rs, *attn_fb;
    cudaGetSymbolAddress((void**)&xn, g_xn);
    cudaGetSymbolAddress((void**)&tmp, g_tmp);
    cudaGetSymbolAddress((void**)&rs, g_rs);
    cudaGetSymbolAddress((void**)&attn_fb, g_attn_fallback);

    __half *xnh, *xnl, *qh, *kh, *vh, *ctxh, *ctxl;
    __half *wqt, *wkt, *wvt, *wot;
    cudaGetSymbolAddress((void**)&xnh, g_xn_hi);
    cudaGetSymbolAddress((void**)&xnl, g_xn_lo);
    cudaGetSymbolAddress((void**)&qh, g_qh);
    cudaGetSymbolAddress((void**)&kh, g_kh);
    cudaGetSymbolAddress((void**)&vh, g_vh);
    cudaGetSymbolAddress((void**)&ctxh, g_ctx_hi);
    cudaGetSymbolAddress((void**)&ctxl, g_ctx_lo);
    cudaGetSymbolAddress((void**)&wqt, g_WqT);
    cudaGetSymbolAddress((void**)&wkt, g_WkT);
    cudaGetSymbolAddress((void**)&wvt, g_WvT);
    cudaGetSymbolAddress((void**)&wot, g_WoT);

    float* attn = (out_size > OUT_ELEMS) ? (out + OUT_ELEMS) : attn_fb;

    // one-time side stream + events
    static cudaStream_t s2 = nullptr;
    static cudaEvent_t e_fork = nullptr, e_join = nullptr;
    static cudaEvent_t e_t0 = nullptr, e_t1 = nullptr;
    if (!s2) {
        cudaStreamCreateWithFlags(&s2, cudaStreamNonBlocking);
        cudaEventCreateWithFlags(&e_fork, cudaEventDisableTiming);
        cudaEventCreateWithFlags(&e_join, cudaEventDisableTiming);
        cudaEventCreateWithFlags(&e_t0, cudaEventDisableTiming);
        cudaEventCreateWithFlags(&e_t1, cudaEventDisableTiming);
    }

    cudaFuncSetAttribute(flash_mma, cudaFuncAttributeMaxDynamicSharedMemorySize,
                         FLASH_SMEM_BYTES);
    cudaFuncSetAttribute(attn_write_mma, cudaFuncAttributeMaxDynamicSharedMemorySize,
                         AW_SMEM_BYTES);
    cudaFuncSetAttribute(gemm_qkv, cudaFuncAttributeMaxDynamicSharedMemorySize,
                         GEMM_SMEM_BYTES);
    cudaFuncSetAttribute(gemm_single, cudaFuncAttributeMaxDynamicSharedMemorySize,
                         GEMM_SMEM_BYTES);

    // 1) side stream: transposes, then zero-fill of masked attn triangle
    //    (independent of all inputs); main: LN1. Join transposes before QKV.
    cudaEventRecord(e_t0, 0);
    cudaStreamWaitEvent(s2, e_t0, 0);
    dim3 tb(32, 8), tg(F_ / 32, F_ / 32, 4);
    transpose_all_kernel<<<tg, tb, 0, s2>>>(Wq, wqt, Wk, wkt, Wv, wvt, Wo, wot);
    cudaEventRecord(e_t1, s2);
    attn_zero_kernel<<<dim3(15, BH_), 256, 0, s2>>>(attn);
    ln_kernel<<<M_, 256>>>(x, gamma1, beta1, xn, xnh, xnl);
    cudaStreamWaitEvent(0, e_t1, 0);

    // 2) fused Q/K/V projections (BK=64 pipeline)
    dim3 qkvgrid(F_ / 128, M_ / 128, 3);
    gemm_qkv<<<qkvgrid, 256, GEMM_SMEM_BYTES>>>(xnh, xnl, wqt, wkt, wvt,
                                                bq, bk, bv, pos,
                                                qh, kh, vh);

    // 3) flash pass 1: rowsums + ctx
    dim3 fgrid(S_ / 128, BH_);
    flash_mma<<<fgrid, 256, FLASH_SMEM_BYTES>>>(qh, kh, vh, ctxh, ctxl, rs);

    // 4) fork: causal attn_write on side stream (after its zero-fill),
    //    overlapping gemm_single + LN2
    cudaEventRecord(e_fork, 0);
    cudaStreamWaitEvent(s2, e_fork, 0);
    attn_write_mma<<<fgrid, 256, AW_SMEM_BYTES, s2>>>(qh, kh, rs, attn);
    cudaEventRecord(e_join, s2);

    // 5) output projection + residual -> fp32 tmp (main stream)
    dim3 ggrid(F_ / 128, M_ / 128);
    gemm_single<<<ggrid, 256, GEMM_SMEM_BYTES>>>(ctxh, ctxl, wot, bo, xn, tmp);

    // 6) LN2 (main stream), then join side stream
    ln_kernel<<<M_, 256>>>(tmp, gamma2, beta2, out, nullptr, nullptr);
    cudaStreamWaitEvent(0, e_join, 0);
}